// round 1
// baseline (speedup 1.0000x reference)
#include <cuda_runtime.h>

#define B_ 8
#define C_ 512
#define T_ 1024
#define H_ 8
#define D_ 64
#define REL_ 129

// ---------------- scratch (no cudaMalloc allowed) ----------------
__device__ float g_q[B_*H_*T_*D_];   // (B,H,T,D)
__device__ float g_k[B_*H_*T_*D_];
__device__ float g_v[B_*H_*T_*D_];
__device__ float g_y[B_*C_*T_];      // (B,C,T) attention output pre-proj

// ---------------- shared-memory layout for attention ----------------
#define SC_OFF   0            // 32*1024 scores
#define SQ_OFF   32768        // 32*64 q tile
#define SKV_OFF  34816        // 64*65 k/v tile (padded)
#define SQR_OFF  38976        // 32*132 qrel, later bins
#define SREL_OFF 43200        // 129*65 emb_rel (padded)
#define SMK_OFF  51585        // 1024 mask
#define SMEM_FLOATS 52609
#define SMEM_BYTES (SMEM_FLOATS*4)

// =====================================================================
// QKV projection GEMM: out[b,h,t,d] = sum_c W[o,c]*x[b,c,t] + bias[o]
// M=C (o), N=B*T (n=b*T+t), K=C. Block tile 64x64, BK=32, 4x4 micro.
// tx -> o (so stores along contiguous d are float4), ty -> n.
// =====================================================================
__global__ __launch_bounds__(256) void qkv_gemm(
    const float* __restrict__ W, const float* __restrict__ X,
    const float* __restrict__ bias, float* __restrict__ out)
{
    __shared__ float As[32*64];
    __shared__ float Bs[32*64];
    const int tid = threadIdx.x;
    const int tx = tid & 15, ty = tid >> 4;
    const int n0 = blockIdx.x * 64;
    const int o0 = blockIdx.y * 64;
    const int b  = n0 / T_;
    const int t0 = n0 % T_;

    float acc[4][4] = {};

    for (int k0 = 0; k0 < C_; k0 += 32) {
        // As[kk][oo] <- W[o0+oo][k0+kk]   (coalesced global reads)
        #pragma unroll
        for (int r = 0; r < 2; r++) {
            int li = tid + r*256;           // 0..511
            int oo = li >> 3;
            int kc = (li & 7) << 2;
            float4 w4 = *(const float4*)&W[(size_t)(o0+oo)*C_ + k0 + kc];
            As[(kc+0)*64+oo] = w4.x;
            As[(kc+1)*64+oo] = w4.y;
            As[(kc+2)*64+oo] = w4.z;
            As[(kc+3)*64+oo] = w4.w;
        }
        // Bs[kk][nn] <- x[b][k0+kk][t0+nn]
        #pragma unroll
        for (int r = 0; r < 2; r++) {
            int li = tid + r*256;
            int kk = li >> 4;
            int nn = (li & 15) << 2;
            *(float4*)&Bs[kk*64+nn] =
                *(const float4*)&X[(size_t)b*C_*T_ + (size_t)(k0+kk)*T_ + t0 + nn];
        }
        __syncthreads();
        #pragma unroll
        for (int kk = 0; kk < 32; kk++) {
            float4 a4 = *(float4*)&As[kk*64 + tx*4];
            float4 b4 = *(float4*)&Bs[kk*64 + ty*4];
            float a[4] = {a4.x,a4.y,a4.z,a4.w};
            float c[4] = {b4.x,b4.y,b4.z,b4.w};
            #pragma unroll
            for (int i = 0; i < 4; i++)
                #pragma unroll
                for (int j = 0; j < 4; j++)
                    acc[i][j] += a[i]*c[j];
        }
        __syncthreads();
    }

    const int ob = o0 + tx*4;
    const int h = ob >> 6, d = ob & 63;
    float bi[4];
    #pragma unroll
    for (int i = 0; i < 4; i++) bi[i] = bias[ob+i];
    #pragma unroll
    for (int j = 0; j < 4; j++) {
        int t = t0 + ty*4 + j;
        float4 v = make_float4(acc[0][j]+bi[0], acc[1][j]+bi[1],
                               acc[2][j]+bi[2], acc[3][j]+bi[3]);
        *(float4*)&out[(((size_t)(b*H_+h))*T_ + t)*D_ + d] = v;
    }
}

// =====================================================================
// Output projection: out[b,o,t] = (sum_c Wo[o,c]*y[b,c,t] + bo[o]) * mask[b,t]
// Same tiling; ty -> o, tx -> n so stores along contiguous t are float4.
// =====================================================================
__global__ __launch_bounds__(256) void out_gemm(
    const float* __restrict__ W, const float* __restrict__ X,
    const float* __restrict__ bias, const float* __restrict__ mask,
    float* __restrict__ out)
{
    __shared__ float As[32*64];
    __shared__ float Bs[32*64];
    const int tid = threadIdx.x;
    const int tx = tid & 15, ty = tid >> 4;
    const int n0 = blockIdx.x * 64;
    const int o0 = blockIdx.y * 64;
    const int b  = n0 / T_;
    const int t0 = n0 % T_;

    float acc[4][4] = {};

    for (int k0 = 0; k0 < C_; k0 += 32) {
        #pragma unroll
        for (int r = 0; r < 2; r++) {
            int li = tid + r*256;
            int oo = li >> 3;
            int kc = (li & 7) << 2;
            float4 w4 = *(const float4*)&W[(size_t)(o0+oo)*C_ + k0 + kc];
            As[(kc+0)*64+oo] = w4.x;
            As[(kc+1)*64+oo] = w4.y;
            As[(kc+2)*64+oo] = w4.z;
            As[(kc+3)*64+oo] = w4.w;
        }
        #pragma unroll
        for (int r = 0; r < 2; r++) {
            int li = tid + r*256;
            int kk = li >> 4;
            int nn = (li & 15) << 2;
            *(float4*)&Bs[kk*64+nn] =
                *(const float4*)&X[(size_t)b*C_*T_ + (size_t)(k0+kk)*T_ + t0 + nn];
        }
        __syncthreads();
        #pragma unroll
        for (int kk = 0; kk < 32; kk++) {
            float4 a4 = *(float4*)&As[kk*64 + ty*4];   // o
            float4 b4 = *(float4*)&Bs[kk*64 + tx*4];   // n
            float a[4] = {a4.x,a4.y,a4.z,a4.w};
            float c[4] = {b4.x,b4.y,b4.z,b4.w};
            #pragma unroll
            for (int i = 0; i < 4; i++)
                #pragma unroll
                for (int j = 0; j < 4; j++)
                    acc[i][j] += a[i]*c[j];
        }
        __syncthreads();
    }

    float4 m4 = *(const float4*)&mask[(size_t)b*T_ + t0 + tx*4];
    #pragma unroll
    for (int i = 0; i < 4; i++) {
        int o = o0 + ty*4 + i;
        float bo = bias[o];
        float4 v = make_float4((acc[i][0]+bo)*m4.x, (acc[i][1]+bo)*m4.y,
                               (acc[i][2]+bo)*m4.z, (acc[i][3]+bo)*m4.w);
        *(float4*)&out[(size_t)b*C_*T_ + (size_t)o*T_ + t0 + tx*4] = v;
    }
}

// =====================================================================
// Fused attention per (b, h, 32-query tile):
//   scores = QK^T/8 + qrel gather, mask, softmax,
//   bins -> y = P@V + bins@emb_rel_v, written to g_y (B,C,T).
// =====================================================================
__global__ __launch_bounds__(256, 1) void attn_kernel(
    const float* __restrict__ mask,
    const float* __restrict__ erel_k,
    const float* __restrict__ erel_v)
{
    extern __shared__ float smf[];
    float* sc   = smf + SC_OFF;    // [32][1024]
    float* sq   = smf + SQ_OFF;    // [32][64]
    float* skv  = smf + SKV_OFF;   // [64][65] (K transposed / V natural)
    float* sqr  = smf + SQR_OFF;   // [32][132] qrel then bins
    float* srel = smf + SREL_OFF;  // [129][65]
    float* smk  = smf + SMK_OFF;   // [1024]

    const int tid = threadIdx.x;
    const int i0 = blockIdx.x * 32;
    const int h  = blockIdx.y;
    const int b  = blockIdx.z;
    const size_t headbase = (size_t)(b*H_+h)*T_*D_;

    // ---- Phase A: loads ----
    for (int e = tid; e < 32*64; e += 256)
        sq[e] = g_q[headbase + (size_t)i0*D_ + e];
    for (int e = tid; e < REL_*64; e += 256) {
        int r = e >> 6, d = e & 63;
        srel[r*65+d] = erel_k[e];
    }
    for (int e = tid; e < T_; e += 256) smk[e] = mask[(size_t)b*T_ + e];
    __syncthreads();

    // ---- Phase B: qrel[m][r] = q[m] . emb_rel_k[r] ----
    for (int idx = tid; idx < 32*REL_; idx += 256) {
        int m = idx / REL_, r = idx % REL_;
        float s = 0.f;
        #pragma unroll 16
        for (int d = 0; d < 64; d++) s += sq[m*64+d]*srel[r*65+d];
        sqr[m*132+r] = s;
    }
    __syncthreads();

    const int tx = tid & 15, ty = tid >> 4;
    const int m0 = ty*2, c4 = tx*4;
    const float scale = 0.125f;  // 1/sqrt(64)

    // ---- Phase C: scores ----
    for (int kt = 0; kt < 16; kt++) {
        const int j0 = kt*64;
        #pragma unroll
        for (int r = 0; r < 16; r++) {
            int e = tid + r*256;
            int jj = e >> 6, dd = e & 63;
            skv[dd*65+jj] = g_k[headbase + (size_t)j0*D_ + e];  // transposed
        }
        __syncthreads();
        float acc[2][4] = {};
        #pragma unroll 8
        for (int d = 0; d < 64; d++) {
            float a0 = sq[m0*64+d];
            float a1 = sq[m0*64+64+d];
            #pragma unroll
            for (int jj = 0; jj < 4; jj++) {
                float kk = skv[d*65 + c4 + jj];
                acc[0][jj] += a0*kk;
                acc[1][jj] += a1*kk;
            }
        }
        #pragma unroll
        for (int i = 0; i < 2; i++) {
            int gi = i0 + m0 + i;
            #pragma unroll
            for (int jj = 0; jj < 4; jj++) {
                int gj = j0 + c4 + jj;
                int rel = gj - gi;
                rel = rel < -64 ? -64 : (rel > 64 ? 64 : rel);
                float val = acc[i][jj]*scale + sqr[(m0+i)*132 + rel + 64];
                if (smk[gj] <= 0.f) val = -1e9f;
                sc[(m0+i)*1024 + gj] = val;
            }
        }
        __syncthreads();
    }

    // ---- Phase D: softmax (warp per row) ----
    {
        int w = tid >> 5, l = tid & 31;
        for (int m = w; m < 32; m += 8) {
            float* row = sc + m*1024;
            float mx = -1e30f;
            for (int j = l; j < 1024; j += 32) mx = fmaxf(mx, row[j]);
            #pragma unroll
            for (int o = 16; o; o >>= 1) mx = fmaxf(mx, __shfl_xor_sync(~0u, mx, o));
            float s = 0.f;
            for (int j = l; j < 1024; j += 32) {
                float e = __expf(row[j]-mx);
                row[j] = e;
                s += e;
            }
            #pragma unroll
            for (int o = 16; o; o >>= 1) s += __shfl_xor_sync(~0u, s, o);
            float inv = 1.f/s;
            for (int j = l; j < 1024; j += 32) row[j] *= inv;
        }
    }
    __syncthreads();

    // ---- Phase E: bins (reuse sqr) + load emb_rel_v ----
    {
        int w = tid >> 5, l = tid & 31;
        for (int m = w; m < 32; m += 8) {
            int gi = i0 + m;
            float* row = sc + m*1024;
            float* bins = sqr + m*132;
            for (int r = l+1; r < 128; r += 32) {
                int j = gi + r - 64;
                bins[r] = (j >= 0 && j < T_) ? row[j] : 0.f;
            }
            float s0 = 0.f;
            int hi = gi - 64;
            for (int j = l; j <= hi; j += 32) s0 += row[j];
            #pragma unroll
            for (int o = 16; o; o >>= 1) s0 += __shfl_xor_sync(~0u, s0, o);
            if (l == 0) bins[0] = s0;
            float s1 = 0.f;
            for (int j = gi + 64 + l; j < T_; j += 32) s1 += row[j];
            #pragma unroll
            for (int o = 16; o; o >>= 1) s1 += __shfl_xor_sync(~0u, s1, o);
            if (l == 0) bins[128] = s1;
        }
    }
    for (int e = tid; e < REL_*64; e += 256) {
        int r = e >> 6, d = e & 63;
        srel[r*65+d] = erel_v[e];
    }
    __syncthreads();

    // ---- Phase F: y = P@V + bins@emb_rel_v ----
    float acc[2][4] = {};
    for (int kt = 0; kt < 16; kt++) {
        const int j0 = kt*64;
        __syncthreads();
        #pragma unroll
        for (int r = 0; r < 16; r++) {
            int e = tid + r*256;
            int jj = e >> 6, dd = e & 63;
            skv[jj*65+dd] = g_v[headbase + (size_t)j0*D_ + e];  // natural layout
        }
        __syncthreads();
        #pragma unroll 4
        for (int j = 0; j < 64; j++) {
            float p0 = sc[m0*1024 + j0 + j];
            float p1 = sc[(m0+1)*1024 + j0 + j];
            #pragma unroll
            for (int c = 0; c < 4; c++) {
                float vv = skv[j*65 + c4 + c];
                acc[0][c] += p0*vv;
                acc[1][c] += p1*vv;
            }
        }
    }
    #pragma unroll 4
    for (int r = 0; r < REL_; r++) {
        float w0 = sqr[m0*132+r];
        float w1 = sqr[(m0+1)*132+r];
        #pragma unroll
        for (int c = 0; c < 4; c++) {
            float vv = srel[r*65 + c4 + c];
            acc[0][c] += w0*vv;
            acc[1][c] += w1*vv;
        }
    }
    #pragma unroll
    for (int i = 0; i < 2; i++) {
        #pragma unroll
        for (int c = 0; c < 4; c++) {
            int d = c4 + c;
            g_y[((size_t)b*C_ + h*D_ + d)*T_ + i0 + m0 + i] = acc[i][c];
        }
    }
}

// =====================================================================
extern "C" void kernel_launch(void* const* d_in, const int* in_sizes, int n_in,
                              void* d_out, int out_size)
{
    const float* x     = (const float*)d_in[0];
    const float* xmask = (const float*)d_in[1];
    const float* Wq    = (const float*)d_in[2];
    const float* bq    = (const float*)d_in[3];
    const float* Wk    = (const float*)d_in[4];
    const float* bk    = (const float*)d_in[5];
    const float* Wv    = (const float*)d_in[6];
    const float* bv    = (const float*)d_in[7];
    const float* Wo    = (const float*)d_in[8];
    const float* bo    = (const float*)d_in[9];
    const float* erelk = (const float*)d_in[10];
    const float* erelv = (const float*)d_in[11];
    float* out = (float*)d_out;

    float *pq, *pk, *pv, *py;
    cudaGetSymbolAddress((void**)&pq, g_q);
    cudaGetSymbolAddress((void**)&pk, g_k);
    cudaGetSymbolAddress((void**)&pv, g_v);
    cudaGetSymbolAddress((void**)&py, g_y);

    cudaFuncSetAttribute(attn_kernel,
                         cudaFuncAttributeMaxDynamicSharedMemorySize, SMEM_BYTES);

    dim3 gg(128, 8), bb(256);
    qkv_gemm<<<gg, bb>>>(Wq, x, bq, pq);
    qkv_gemm<<<gg, bb>>>(Wk, x, bk, pk);
    qkv_gemm<<<gg, bb>>>(Wv, x, bv, pv);

    attn_kernel<<<dim3(32, H_, B_), 256, SMEM_BYTES>>>(xmask, erelk, erelv);

    out_gemm<<<gg, bb>>>(Wo, py, bo, xmask, out);
}

// round 2
// speedup vs baseline: 1.1982x; 1.1982x over previous
#include <cuda_runtime.h>

#define B_ 8
#define C_ 512
#define T_ 1024
#define H_ 8
#define D_ 64
#define REL_ 129

// ---------------- scratch (no cudaMalloc allowed) ----------------
__device__ float g_q[B_*H_*T_*D_];   // (B,H,T,D)
__device__ float g_k[B_*H_*T_*D_];
__device__ float g_v[B_*H_*T_*D_];
__device__ float g_y[B_*C_*T_];      // (B,C,T) attention output pre-proj

// ---------------- shared-memory layout for attention (floats) ----------------
#define SC_OFF   0                 // 32*1024 scores / later PV partials
#define SQ_OFF   32768             // 32*64 q tile
#define SKV_OFF  34816             // 64*129 K^T tile  /  128*64 V tile
#define SQR_OFF  43072             // 32*132 qrel, later bins
#define SREL_OFF 47296             // 129*68 emb_rel (float4-aligned pad)
#define SMK_OFF  56068             // 1024 mask
#define SMEM_FLOATS 57092
#define SMEM_BYTES (SMEM_FLOATS*4)

// =====================================================================
// QKV projection GEMM (unchanged — already at fp32 FFMA roofline)
// =====================================================================
__global__ __launch_bounds__(256) void qkv_gemm(
    const float* __restrict__ W, const float* __restrict__ X,
    const float* __restrict__ bias, float* __restrict__ out)
{
    __shared__ float As[32*64];
    __shared__ float Bs[32*64];
    const int tid = threadIdx.x;
    const int tx = tid & 15, ty = tid >> 4;
    const int n0 = blockIdx.x * 64;
    const int o0 = blockIdx.y * 64;
    const int b  = n0 / T_;
    const int t0 = n0 % T_;

    float acc[4][4] = {};

    for (int k0 = 0; k0 < C_; k0 += 32) {
        #pragma unroll
        for (int r = 0; r < 2; r++) {
            int li = tid + r*256;
            int oo = li >> 3;
            int kc = (li & 7) << 2;
            float4 w4 = *(const float4*)&W[(size_t)(o0+oo)*C_ + k0 + kc];
            As[(kc+0)*64+oo] = w4.x;
            As[(kc+1)*64+oo] = w4.y;
            As[(kc+2)*64+oo] = w4.z;
            As[(kc+3)*64+oo] = w4.w;
        }
        #pragma unroll
        for (int r = 0; r < 2; r++) {
            int li = tid + r*256;
            int kk = li >> 4;
            int nn = (li & 15) << 2;
            *(float4*)&Bs[kk*64+nn] =
                *(const float4*)&X[(size_t)b*C_*T_ + (size_t)(k0+kk)*T_ + t0 + nn];
        }
        __syncthreads();
        #pragma unroll
        for (int kk = 0; kk < 32; kk++) {
            float4 a4 = *(float4*)&As[kk*64 + tx*4];
            float4 b4 = *(float4*)&Bs[kk*64 + ty*4];
            float a[4] = {a4.x,a4.y,a4.z,a4.w};
            float c[4] = {b4.x,b4.y,b4.z,b4.w};
            #pragma unroll
            for (int i = 0; i < 4; i++)
                #pragma unroll
                for (int j = 0; j < 4; j++)
                    acc[i][j] += a[i]*c[j];
        }
        __syncthreads();
    }

    const int ob = o0 + tx*4;
    const int h = ob >> 6, d = ob & 63;
    float bi[4];
    #pragma unroll
    for (int i = 0; i < 4; i++) bi[i] = bias[ob+i];
    #pragma unroll
    for (int j = 0; j < 4; j++) {
        int t = t0 + ty*4 + j;
        float4 v = make_float4(acc[0][j]+bi[0], acc[1][j]+bi[1],
                               acc[2][j]+bi[2], acc[3][j]+bi[3]);
        *(float4*)&out[(((size_t)(b*H_+h))*T_ + t)*D_ + d] = v;
    }
}

// =====================================================================
// Output projection (unchanged)
// =====================================================================
__global__ __launch_bounds__(256) void out_gemm(
    const float* __restrict__ W, const float* __restrict__ X,
    const float* __restrict__ bias, const float* __restrict__ mask,
    float* __restrict__ out)
{
    __shared__ float As[32*64];
    __shared__ float Bs[32*64];
    const int tid = threadIdx.x;
    const int tx = tid & 15, ty = tid >> 4;
    const int n0 = blockIdx.x * 64;
    const int o0 = blockIdx.y * 64;
    const int b  = n0 / T_;
    const int t0 = n0 % T_;

    float acc[4][4] = {};

    for (int k0 = 0; k0 < C_; k0 += 32) {
        #pragma unroll
        for (int r = 0; r < 2; r++) {
            int li = tid + r*256;
            int oo = li >> 3;
            int kc = (li & 7) << 2;
            float4 w4 = *(const float4*)&W[(size_t)(o0+oo)*C_ + k0 + kc];
            As[(kc+0)*64+oo] = w4.x;
            As[(kc+1)*64+oo] = w4.y;
            As[(kc+2)*64+oo] = w4.z;
            As[(kc+3)*64+oo] = w4.w;
        }
        #pragma unroll
        for (int r = 0; r < 2; r++) {
            int li = tid + r*256;
            int kk = li >> 4;
            int nn = (li & 15) << 2;
            *(float4*)&Bs[kk*64+nn] =
                *(const float4*)&X[(size_t)b*C_*T_ + (size_t)(k0+kk)*T_ + t0 + nn];
        }
        __syncthreads();
        #pragma unroll
        for (int kk = 0; kk < 32; kk++) {
            float4 a4 = *(float4*)&As[kk*64 + ty*4];
            float4 b4 = *(float4*)&Bs[kk*64 + tx*4];
            float a[4] = {a4.x,a4.y,a4.z,a4.w};
            float c[4] = {b4.x,b4.y,b4.z,b4.w};
            #pragma unroll
            for (int i = 0; i < 4; i++)
                #pragma unroll
                for (int j = 0; j < 4; j++)
                    acc[i][j] += a[i]*c[j];
        }
        __syncthreads();
    }

    float4 m4 = *(const float4*)&mask[(size_t)b*T_ + t0 + tx*4];
    #pragma unroll
    for (int i = 0; i < 4; i++) {
        int o = o0 + ty*4 + i;
        float bo = bias[o];
        float4 v = make_float4((acc[i][0]+bo)*m4.x, (acc[i][1]+bo)*m4.y,
                               (acc[i][2]+bo)*m4.z, (acc[i][3]+bo)*m4.w);
        *(float4*)&out[(size_t)b*C_*T_ + (size_t)o*T_ + t0 + tx*4] = v;
    }
}

// =====================================================================
// Fused attention per (b, h, 32-query tile). Register-blocked, LDS-lean.
// =====================================================================
__global__ __launch_bounds__(256, 1) void attn_kernel(
    const float* __restrict__ mask,
    const float* __restrict__ erel_k,
    const float* __restrict__ erel_v)
{
    extern __shared__ float smf[];
    float* sc   = smf + SC_OFF;    // [32][1024]
    float* sq   = smf + SQ_OFF;    // [32][64]
    float* skv  = smf + SKV_OFF;   // K^T [64][129]  or  V [128][64]
    float* sqr  = smf + SQR_OFF;   // [32][132] qrel then bins
    float* srel = smf + SREL_OFF;  // [129][68]
    float* smk  = smf + SMK_OFF;   // [1024]

    const int tid = threadIdx.x;
    const int i0 = blockIdx.x * 32;
    const int h  = blockIdx.y;
    const int b  = blockIdx.z;
    const size_t headbase = (size_t)(b*H_+h)*T_*D_;

    // ---- Phase A: loads ----
    for (int e = tid; e < 32*64/4; e += 256)
        ((float4*)sq)[e] = ((const float4*)(g_q + headbase + (size_t)i0*D_))[e];
    for (int e = tid; e < REL_*16; e += 256) {
        int r = e >> 4, d4 = (e & 15);
        *(float4*)&srel[r*68 + d4*4] = ((const float4*)erel_k)[e];
    }
    for (int e = tid; e < T_/4; e += 256)
        ((float4*)smk)[e] = ((const float4*)(mask + (size_t)b*T_))[e];
    __syncthreads();

    // ---- Phase B: qrel[m][r] = q[m] . emb_rel_k[r] ----
    for (int idx = tid; idx < 32*REL_; idx += 256) {
        int m = idx / REL_, r = idx - m*REL_;
        const float4* q4 = (const float4*)(sq + m*64);
        const float4* e4 = (const float4*)(srel + r*68);
        float s = 0.f;
        #pragma unroll
        for (int d = 0; d < 16; d++) {
            float4 a = q4[d], bb = e4[d];
            s += a.x*bb.x + a.y*bb.y + a.z*bb.z + a.w*bb.w;
        }
        sqr[m*132 + r] = s;
    }
    __syncthreads();

    // ---- Phase C: scores = QK^T/8 + qrel gather + mask ----
    {
        const int tx = tid & 31;          // j lanes (strided by 32)
        const int ty = tid >> 5;          // row group
        const int m0 = ty * 4;
        const float scale = 0.125f;

        for (int kt = 0; kt < 8; kt++) {
            const int j0g = kt * 128;
            __syncthreads();
            // load K tile [128 j][64 d] -> transposed skv[d*129 + j]
            #pragma unroll
            for (int r = 0; r < 8; r++) {
                int e = tid + r*256;
                int j = e >> 4, d4 = (e & 15) << 2;
                float4 kv = *(const float4*)&g_k[headbase + (size_t)(j0g + j)*D_ + d4];
                skv[(d4+0)*129 + j] = kv.x;
                skv[(d4+1)*129 + j] = kv.y;
                skv[(d4+2)*129 + j] = kv.z;
                skv[(d4+3)*129 + j] = kv.w;
            }
            __syncthreads();

            float acc[4][4] = {};
            #pragma unroll 2
            for (int d4 = 0; d4 < 64; d4 += 4) {
                float qv[4][4];
                #pragma unroll
                for (int i = 0; i < 4; i++) {
                    float4 t = *(const float4*)&sq[(m0+i)*64 + d4];  // broadcast
                    qv[i][0]=t.x; qv[i][1]=t.y; qv[i][2]=t.z; qv[i][3]=t.w;
                }
                #pragma unroll
                for (int dd = 0; dd < 4; dd++) {
                    const float* kr = &skv[(d4+dd)*129 + tx];
                    float kc[4] = {kr[0], kr[32], kr[64], kr[96]};  // conflict-free
                    #pragma unroll
                    for (int i = 0; i < 4; i++)
                        #pragma unroll
                        for (int c = 0; c < 4; c++)
                            acc[i][c] += qv[i][dd]*kc[c];
                }
            }
            #pragma unroll
            for (int i = 0; i < 4; i++) {
                int gi = i0 + m0 + i;
                #pragma unroll
                for (int c = 0; c < 4; c++) {
                    int gj = j0g + tx + 32*c;
                    int rel = gj - gi;
                    rel = rel < -64 ? -64 : (rel > 64 ? 64 : rel);
                    float val = acc[i][c]*scale + sqr[(m0+i)*132 + rel + 64];
                    if (smk[gj] <= 0.f) val = -1e9f;
                    sc[(m0+i)*1024 + gj] = val;
                }
            }
        }
    }
    __syncthreads();

    // ---- Phase D: softmax (warp per row, float4) ----
    {
        int w = tid >> 5, l = tid & 31;
        for (int m = w; m < 32; m += 8) {
            float4* row4 = (float4*)(sc + m*1024);
            float mx = -1e30f;
            #pragma unroll
            for (int q = 0; q < 8; q++) {
                float4 v = row4[l + q*32];
                mx = fmaxf(mx, fmaxf(fmaxf(v.x,v.y), fmaxf(v.z,v.w)));
            }
            #pragma unroll
            for (int o = 16; o; o >>= 1) mx = fmaxf(mx, __shfl_xor_sync(~0u, mx, o));
            float s = 0.f;
            #pragma unroll
            for (int q = 0; q < 8; q++) {
                float4 v = row4[l + q*32];
                v.x = __expf(v.x - mx); v.y = __expf(v.y - mx);
                v.z = __expf(v.z - mx); v.w = __expf(v.w - mx);
                row4[l + q*32] = v;
                s += v.x + v.y + v.z + v.w;
            }
            #pragma unroll
            for (int o = 16; o; o >>= 1) s += __shfl_xor_sync(~0u, s, o);
            float inv = 1.f / s;
            #pragma unroll
            for (int q = 0; q < 8; q++) {
                float4 v = row4[l + q*32];
                v.x *= inv; v.y *= inv; v.z *= inv; v.w *= inv;
                row4[l + q*32] = v;
            }
        }
    }
    __syncthreads();

    // ---- Phase E: bins (reuse sqr) + load emb_rel_v ----
    {
        int w = tid >> 5, l = tid & 31;
        for (int m = w; m < 32; m += 8) {
            int gi = i0 + m;
            float* row = sc + m*1024;
            float* bins = sqr + m*132;
            for (int r = l+1; r < 128; r += 32) {
                int j = gi + r - 64;
                bins[r] = (j >= 0 && j < T_) ? row[j] : 0.f;
            }
            float s0 = 0.f;
            int hi = gi - 64;
            for (int j = l; j <= hi; j += 32) s0 += row[j];
            #pragma unroll
            for (int o = 16; o; o >>= 1) s0 += __shfl_xor_sync(~0u, s0, o);
            if (l == 0) bins[0] = s0;
            float s1 = 0.f;
            for (int j = gi + 64 + l; j < T_; j += 32) s1 += row[j];
            #pragma unroll
            for (int o = 16; o; o >>= 1) s1 += __shfl_xor_sync(~0u, s1, o);
            if (l == 0) bins[128] = s1;
        }
    }
    for (int e = tid; e < REL_*16; e += 256) {
        int r = e >> 4, d4 = (e & 15);
        *(float4*)&srel[r*68 + d4*4] = ((const float4*)erel_v)[e];
    }

    // ---- Phase F: y = P@V (4-way K-split, 4x8 micro) ----
    {
        const int fx = tid & 7;            // col group: c8 = fx*8
        const int fy = (tid >> 3) & 7;     // row group: mf = fy*4
        const int kp = tid >> 6;           // K partition 0..3
        const int c8 = fx * 8, mf = fy * 4;
        const int jb = kp * 32;

        float fac[4][8] = {};
        for (int jt = 0; jt < 8; jt++) {
            __syncthreads();
            // load V tile [128 j][64 d] natural layout
            #pragma unroll
            for (int r = 0; r < 8; r++) {
                int e = tid + r*256;
                int j = e >> 4, d4 = (e & 15) << 2;
                *(float4*)&skv[j*64 + d4] =
                    *(const float4*)&g_v[headbase + (size_t)(jt*128 + j)*D_ + d4];
            }
            __syncthreads();

            const float* prow0 = sc + (mf+0)*1024 + jt*128 + jb;
            const float* prow1 = sc + (mf+1)*1024 + jt*128 + jb;
            const float* prow2 = sc + (mf+2)*1024 + jt*128 + jb;
            const float* prow3 = sc + (mf+3)*1024 + jt*128 + jb;
            #pragma unroll 2
            for (int j4 = 0; j4 < 32; j4 += 4) {
                float pv[4][4];
                {
                    float4 t0 = *(const float4*)(prow0 + j4);
                    float4 t1 = *(const float4*)(prow1 + j4);
                    float4 t2 = *(const float4*)(prow2 + j4);
                    float4 t3 = *(const float4*)(prow3 + j4);
                    pv[0][0]=t0.x; pv[0][1]=t0.y; pv[0][2]=t0.z; pv[0][3]=t0.w;
                    pv[1][0]=t1.x; pv[1][1]=t1.y; pv[1][2]=t1.z; pv[1][3]=t1.w;
                    pv[2][0]=t2.x; pv[2][1]=t2.y; pv[2][2]=t2.z; pv[2][3]=t2.w;
                    pv[3][0]=t3.x; pv[3][1]=t3.y; pv[3][2]=t3.z; pv[3][3]=t3.w;
                }
                #pragma unroll
                for (int jj = 0; jj < 4; jj++) {
                    const float* vr = &skv[(jb + j4 + jj)*64 + c8];
                    float4 a = *(const float4*)(vr);
                    float4 bb = *(const float4*)(vr + 4);
                    float vv[8] = {a.x,a.y,a.z,a.w, bb.x,bb.y,bb.z,bb.w};
                    #pragma unroll
                    for (int i = 0; i < 4; i++)
                        #pragma unroll
                        for (int c = 0; c < 8; c++)
                            fac[i][c] += pv[i][jj]*vv[c];
                }
            }
        }
        __syncthreads();   // all P reads done; sc becomes scratch
        #pragma unroll
        for (int i = 0; i < 4; i++) {
            *(float4*)&sc[kp*2048 + (mf+i)*64 + c8] =
                make_float4(fac[i][0], fac[i][1], fac[i][2], fac[i][3]);
            *(float4*)&sc[kp*2048 + (mf+i)*64 + c8 + 4] =
                make_float4(fac[i][4], fac[i][5], fac[i][6], fac[i][7]);
        }
    }
    __syncthreads();

    // ---- Phase G: reduce partials + rel-V term + store ----
    {
        const int gx = tid & 15, gy = tid >> 4;
        const int c4 = gx * 4;
        const int ma = gy*2, mb = gy*2 + 1;

        float4 sa = make_float4(0,0,0,0), sb = sa;
        #pragma unroll
        for (int kp = 0; kp < 4; kp++) {
            float4 ta = *(const float4*)&sc[kp*2048 + ma*64 + c4];
            float4 tb = *(const float4*)&sc[kp*2048 + mb*64 + c4];
            sa.x += ta.x; sa.y += ta.y; sa.z += ta.z; sa.w += ta.w;
            sb.x += tb.x; sb.y += tb.y; sb.z += tb.z; sb.w += tb.w;
        }
        #pragma unroll 4
        for (int r = 0; r < REL_; r++) {
            float wa = sqr[ma*132 + r];
            float wb = sqr[mb*132 + r];
            float4 rv = *(const float4*)&srel[r*68 + c4];
            sa.x += wa*rv.x; sa.y += wa*rv.y; sa.z += wa*rv.z; sa.w += wa*rv.w;
            sb.x += wb*rv.x; sb.y += wb*rv.y; sb.z += wb*rv.z; sb.w += wb*rv.w;
        }
        float va[4] = {sa.x, sa.y, sa.z, sa.w};
        float vb[4] = {sb.x, sb.y, sb.z, sb.w};
        #pragma unroll
        for (int c = 0; c < 4; c++) {
            int d = c4 + c;
            size_t base = ((size_t)b*C_ + h*D_ + d)*T_ + i0;
            g_y[base + ma] = va[c];
            g_y[base + mb] = vb[c];
        }
    }
}

// =====================================================================
extern "C" void kernel_launch(void* const* d_in, const int* in_sizes, int n_in,
                              void* d_out, int out_size)
{
    const float* x     = (const float*)d_in[0];
    const float* xmask = (const float*)d_in[1];
    const float* Wq    = (const float*)d_in[2];
    const float* bq    = (const float*)d_in[3];
    const float* Wk    = (const float*)d_in[4];
    const float* bk    = (const float*)d_in[5];
    const float* Wv    = (const float*)d_in[6];
    const float* bv    = (const float*)d_in[7];
    const float* Wo    = (const float*)d_in[8];
    const float* bo    = (const float*)d_in[9];
    const float* erelk = (const float*)d_in[10];
    const float* erelv = (const float*)d_in[11];
    float* out = (float*)d_out;

    float *pq, *pk, *pv, *py;
    cudaGetSymbolAddress((void**)&pq, g_q);
    cudaGetSymbolAddress((void**)&pk, g_k);
    cudaGetSymbolAddress((void**)&pv, g_v);
    cudaGetSymbolAddress((void**)&py, g_y);

    cudaFuncSetAttribute(attn_kernel,
                         cudaFuncAttributeMaxDynamicSharedMemorySize, SMEM_BYTES);

    dim3 gg(128, 8), bb(256);
    qkv_gemm<<<gg, bb>>>(Wq, x, bq, pq);
    qkv_gemm<<<gg, bb>>>(Wk, x, bk, pk);
    qkv_gemm<<<gg, bb>>>(Wv, x, bv, pv);

    attn_kernel<<<dim3(32, H_, B_), 256, SMEM_BYTES>>>(xmask, erelk, erelv);

    out_gemm<<<gg, bb>>>(Wo, py, bo, xmask, out);
}

// round 3
// speedup vs baseline: 1.4340x; 1.1968x over previous
#include <cuda_runtime.h>

#define B_ 8
#define C_ 512
#define T_ 1024
#define H_ 8
#define D_ 64
#define REL_ 129

// ---------------- scratch (no cudaMalloc allowed) ----------------
__device__ float g_q[B_*H_*T_*D_];   // (B,H,T,D)
__device__ float g_k[B_*H_*T_*D_];
__device__ float g_v[B_*H_*T_*D_];
__device__ float g_y[B_*C_*T_];      // (B,C,T) attention output pre-proj

// ---------------- attn shared memory layout (floats) ----------------
#define SQ_OFF   0                      // 32*64      = 2048
#define SKV_OFF  2048                   // max(64*129, 128*64, 129*68) = 8772
#define SP_OFF   (2048+8772)            // 32*132     = 4224
#define SBIN_OFF (SP_OFF+4224)          // 32*132     = 4224
#define SQR_OFF  (SBIN_OFF+4224)        // 32*132     = 4224
#define SMK_OFF  (SQR_OFF+4224)         // 1024
#define SST_OFF  (SMK_OFF+1024)         // 128 : l[32], e0[32], e1[32]
#define SMEM_FLOATS (SST_OFF+128)       // 24644
#define SMEM_BYTES (SMEM_FLOATS*4)      // 98576 -> 2 CTAs/SM

// =====================================================================
// QKV projection GEMM (unchanged — at scalar fp32 roofline)
// =====================================================================
__global__ __launch_bounds__(256) void qkv_gemm(
    const float* __restrict__ W, const float* __restrict__ X,
    const float* __restrict__ bias, float* __restrict__ out)
{
    __shared__ float As[32*64];
    __shared__ float Bs[32*64];
    const int tid = threadIdx.x;
    const int tx = tid & 15, ty = tid >> 4;
    const int n0 = blockIdx.x * 64;
    const int o0 = blockIdx.y * 64;
    const int b  = n0 / T_;
    const int t0 = n0 % T_;

    float acc[4][4] = {};

    for (int k0 = 0; k0 < C_; k0 += 32) {
        #pragma unroll
        for (int r = 0; r < 2; r++) {
            int li = tid + r*256;
            int oo = li >> 3;
            int kc = (li & 7) << 2;
            float4 w4 = *(const float4*)&W[(size_t)(o0+oo)*C_ + k0 + kc];
            As[(kc+0)*64+oo] = w4.x;
            As[(kc+1)*64+oo] = w4.y;
            As[(kc+2)*64+oo] = w4.z;
            As[(kc+3)*64+oo] = w4.w;
        }
        #pragma unroll
        for (int r = 0; r < 2; r++) {
            int li = tid + r*256;
            int kk = li >> 4;
            int nn = (li & 15) << 2;
            *(float4*)&Bs[kk*64+nn] =
                *(const float4*)&X[(size_t)b*C_*T_ + (size_t)(k0+kk)*T_ + t0 + nn];
        }
        __syncthreads();
        #pragma unroll
        for (int kk = 0; kk < 32; kk++) {
            float4 a4 = *(float4*)&As[kk*64 + tx*4];
            float4 b4 = *(float4*)&Bs[kk*64 + ty*4];
            float a[4] = {a4.x,a4.y,a4.z,a4.w};
            float c[4] = {b4.x,b4.y,b4.z,b4.w};
            #pragma unroll
            for (int i = 0; i < 4; i++)
                #pragma unroll
                for (int j = 0; j < 4; j++)
                    acc[i][j] += a[i]*c[j];
        }
        __syncthreads();
    }

    const int ob = o0 + tx*4;
    const int h = ob >> 6, d = ob & 63;
    float bi[4];
    #pragma unroll
    for (int i = 0; i < 4; i++) bi[i] = bias[ob+i];
    #pragma unroll
    for (int j = 0; j < 4; j++) {
        int t = t0 + ty*4 + j;
        float4 v = make_float4(acc[0][j]+bi[0], acc[1][j]+bi[1],
                               acc[2][j]+bi[2], acc[3][j]+bi[3]);
        *(float4*)&out[(((size_t)(b*H_+h))*T_ + t)*D_ + d] = v;
    }
}

// =====================================================================
// Output projection (unchanged)
// =====================================================================
__global__ __launch_bounds__(256) void out_gemm(
    const float* __restrict__ W, const float* __restrict__ X,
    const float* __restrict__ bias, const float* __restrict__ mask,
    float* __restrict__ out)
{
    __shared__ float As[32*64];
    __shared__ float Bs[32*64];
    const int tid = threadIdx.x;
    const int tx = tid & 15, ty = tid >> 4;
    const int n0 = blockIdx.x * 64;
    const int o0 = blockIdx.y * 64;
    const int b  = n0 / T_;
    const int t0 = n0 % T_;

    float acc[4][4] = {};

    for (int k0 = 0; k0 < C_; k0 += 32) {
        #pragma unroll
        for (int r = 0; r < 2; r++) {
            int li = tid + r*256;
            int oo = li >> 3;
            int kc = (li & 7) << 2;
            float4 w4 = *(const float4*)&W[(size_t)(o0+oo)*C_ + k0 + kc];
            As[(kc+0)*64+oo] = w4.x;
            As[(kc+1)*64+oo] = w4.y;
            As[(kc+2)*64+oo] = w4.z;
            As[(kc+3)*64+oo] = w4.w;
        }
        #pragma unroll
        for (int r = 0; r < 2; r++) {
            int li = tid + r*256;
            int kk = li >> 4;
            int nn = (li & 15) << 2;
            *(float4*)&Bs[kk*64+nn] =
                *(const float4*)&X[(size_t)b*C_*T_ + (size_t)(k0+kk)*T_ + t0 + nn];
        }
        __syncthreads();
        #pragma unroll
        for (int kk = 0; kk < 32; kk++) {
            float4 a4 = *(float4*)&As[kk*64 + ty*4];
            float4 b4 = *(float4*)&Bs[kk*64 + tx*4];
            float a[4] = {a4.x,a4.y,a4.z,a4.w};
            float c[4] = {b4.x,b4.y,b4.z,b4.w};
            #pragma unroll
            for (int i = 0; i < 4; i++)
                #pragma unroll
                for (int j = 0; j < 4; j++)
                    acc[i][j] += a[i]*c[j];
        }
        __syncthreads();
    }

    float4 m4 = *(const float4*)&mask[(size_t)b*T_ + t0 + tx*4];
    #pragma unroll
    for (int i = 0; i < 4; i++) {
        int o = o0 + ty*4 + i;
        float bo = bias[o];
        float4 v = make_float4((acc[i][0]+bo)*m4.x, (acc[i][1]+bo)*m4.y,
                               (acc[i][2]+bo)*m4.z, (acc[i][3]+bo)*m4.w);
        *(float4*)&out[(size_t)b*C_*T_ + (size_t)o*T_ + t0 + tx*4] = v;
    }
}

// =====================================================================
// Fused single-pass attention per (b, h, 32-query tile).
// No resident score strip -> 98.6KB smem -> 2 CTAs/SM.
// exp without max-subtraction (scores are O(1) for this problem; softmax
// is shift-invariant; masked entries give exp(-1e9)=0 exactly).
// =====================================================================
__global__ __launch_bounds__(256, 2) void attn_kernel(
    const float* __restrict__ mask,
    const float* __restrict__ erel_k,
    const float* __restrict__ erel_v)
{
    extern __shared__ float smf[];
    float* sq   = smf + SQ_OFF;    // [32][64] q tile
    float* skv  = smf + SKV_OFF;   // K^T [64][129] / V [128][64] / erel [129][68]
    float* sp   = smf + SP_OFF;    // [32][132] P chunk (e values)
    float* sbin = smf + SBIN_OFF;  // [32][132] raw middle-bin scores -> bins
    float* sqr  = smf + SQR_OFF;   // [32][132] qrel
    float* smk  = smf + SMK_OFF;   // [1024] mask
    float* sst  = smf + SST_OFF;   // l[32], e0[32], e1[32]

    const int tid = threadIdx.x;
    const int i0 = blockIdx.x * 32;
    const int h  = blockIdx.y;
    const int b  = blockIdx.z;
    const size_t headbase = (size_t)(b*H_+h)*T_*D_;

    // ---- Phase A: loads + init ----
    for (int e = tid; e < 32*64/4; e += 256)
        ((float4*)sq)[e] = ((const float4*)(g_q + headbase + (size_t)i0*D_))[e];
    for (int e = tid; e < REL_*16; e += 256) {
        int r = e >> 4, d4 = (e & 15) << 2;
        *(float4*)&skv[r*68 + d4] = ((const float4*)erel_k)[e];
    }
    for (int e = tid; e < T_/4; e += 256)
        ((float4*)smk)[e] = ((const float4*)(mask + (size_t)b*T_))[e];
    for (int e = tid; e < 32*132; e += 256)
        sbin[e] = -1e9f;
    __syncthreads();

    // ---- Phase B: qrel[m][r] = q[m] . emb_rel_k[r] ----
    for (int idx = tid; idx < 32*REL_; idx += 256) {
        int m = idx / REL_, r = idx - m*REL_;
        const float4* q4 = (const float4*)(sq + m*64);
        const float4* e4 = (const float4*)(skv + r*68);
        float s = 0.f;
        #pragma unroll
        for (int d = 0; d < 16; d++) {
            float4 a = q4[d], bb = e4[d];
            s += a.x*bb.x + a.y*bb.y + a.z*bb.z + a.w*bb.w;
        }
        sqr[m*132 + r] = s;
    }

    // S-phase mapping
    const int tx = tid & 31;          // j lanes
    const int ty = tid >> 5;          // warp -> 4 rows
    const int m0 = ty * 4;
    // PV-phase mapping
    const int px = tid & 15, py = tid >> 4;
    const int c4 = px * 4;
    const int mA = py*2, mB = py*2 + 1;

    const float scale = 0.125f;       // 1/sqrt(64)

    float lsum[4] = {0.f,0.f,0.f,0.f};
    float e0s[4]  = {0.f,0.f,0.f,0.f};
    float e1s[4]  = {0.f,0.f,0.f,0.f};
    float yA[4] = {0.f,0.f,0.f,0.f};
    float yB[4] = {0.f,0.f,0.f,0.f};

    // ---- Main loop over 8 j-chunks of 128 ----
    for (int kt = 0; kt < 8; kt++) {
        const int j0g = kt * 128;
        __syncthreads();   // prior PV reads of skv/sp done (and phase B reads)
        // load K chunk [128 j][64 d] -> transposed skv[d*129 + j]
        #pragma unroll
        for (int r = 0; r < 8; r++) {
            int e = tid + r*256;
            int j = e >> 4, d4 = (e & 15) << 2;
            float4 kv = *(const float4*)&g_k[headbase + (size_t)(j0g + j)*D_ + d4];
            skv[(d4+0)*129 + j] = kv.x;
            skv[(d4+1)*129 + j] = kv.y;
            skv[(d4+2)*129 + j] = kv.z;
            skv[(d4+3)*129 + j] = kv.w;
        }
        __syncthreads();

        // S = Q K^T (4 rows x 4 strided cols per thread)
        float acc[4][4] = {};
        #pragma unroll 2
        for (int d4 = 0; d4 < 64; d4 += 4) {
            float qv[4][4];
            #pragma unroll
            for (int i = 0; i < 4; i++) {
                float4 t = *(const float4*)&sq[(m0+i)*64 + d4];  // broadcast
                qv[i][0]=t.x; qv[i][1]=t.y; qv[i][2]=t.z; qv[i][3]=t.w;
            }
            #pragma unroll
            for (int dd = 0; dd < 4; dd++) {
                const float* kr = &skv[(d4+dd)*129 + tx];
                float kc[4] = {kr[0], kr[32], kr[64], kr[96]};  // conflict-free
                #pragma unroll
                for (int i = 0; i < 4; i++)
                    #pragma unroll
                    for (int c = 0; c < 4; c++)
                        acc[i][c] += qv[i][dd]*kc[c];
            }
        }
        // epilogue: rel gather, mask, exp, running sums, P/bin writes
        #pragma unroll
        for (int i = 0; i < 4; i++) {
            const int gi = i0 + m0 + i;
            #pragma unroll
            for (int c = 0; c < 4; c++) {
                int jl = tx + 32*c;
                int gj = j0g + jl;
                int rel = gj - gi;
                int relc = rel < -64 ? -64 : (rel > 64 ? 64 : rel);
                float s = acc[i][c]*scale + sqr[(m0+i)*132 + relc + 64];
                if (smk[gj] <= 0.f) s = -1e9f;
                float e = __expf(s);
                lsum[i] += e;
                if (rel <= -64)      e0s[i] += e;
                else if (rel >= 64)  e1s[i] += e;
                else                 sbin[(m0+i)*132 + rel + 64] = s;
                sp[(m0+i)*132 + jl] = e;
            }
        }
        __syncthreads();   // S reads of skv done; sp writes visible
        // load V chunk [128 j][64 d] natural layout
        #pragma unroll
        for (int r = 0; r < 8; r++) {
            int e = tid + r*256;
            int j = e >> 4, d4 = (e & 15) << 2;
            *(float4*)&skv[j*64 + d4] =
                *(const float4*)&g_v[headbase + (size_t)(j0g + j)*D_ + d4];
        }
        __syncthreads();

        // PV: y(2 rows x 4 cols) += P_chunk @ V_chunk
        const float* prowA = sp + mA*132;
        const float* prowB = sp + mB*132;
        #pragma unroll 4
        for (int j = 0; j < 128; j += 4) {
            float4 pa = *(const float4*)(prowA + j);
            float4 pb = *(const float4*)(prowB + j);
            float pav[4] = {pa.x, pa.y, pa.z, pa.w};
            float pbv[4] = {pb.x, pb.y, pb.z, pb.w};
            #pragma unroll
            for (int jj = 0; jj < 4; jj++) {
                float4 vv = *(const float4*)&skv[(j+jj)*64 + c4];
                yA[0] += pav[jj]*vv.x; yA[1] += pav[jj]*vv.y;
                yA[2] += pav[jj]*vv.z; yA[3] += pav[jj]*vv.w;
                yB[0] += pbv[jj]*vv.x; yB[1] += pbv[jj]*vv.y;
                yB[2] += pbv[jj]*vv.z; yB[3] += pbv[jj]*vv.w;
            }
        }
    }

    __syncthreads();   // last PV reads of skv done

    // ---- load erel_v (overwrites skv) + per-row stat reduction ----
    for (int e = tid; e < REL_*16; e += 256) {
        int r = e >> 4, d4 = (e & 15) << 2;
        *(float4*)&skv[r*68 + d4] = ((const float4*)erel_v)[e];
    }
    #pragma unroll
    for (int i = 0; i < 4; i++) {
        float l = lsum[i], a = e0s[i], c = e1s[i];
        #pragma unroll
        for (int o = 16; o; o >>= 1) {
            l += __shfl_xor_sync(~0u, l, o);
            a += __shfl_xor_sync(~0u, a, o);
            c += __shfl_xor_sync(~0u, c, o);
        }
        if (tx == 0) {
            sst[m0+i]      = l;
            sst[32 + m0+i] = a;
            sst[64 + m0+i] = c;
        }
    }
    __syncthreads();

    // ---- finalize bins: p = exp(s)/l ; edges = e/l ----
    for (int e = tid; e < 32*REL_; e += 256) {
        int m = e / REL_, r = e - m*REL_;
        float invl = 1.f / sst[m];
        float v;
        if (r == 0)         v = sst[32+m]*invl;
        else if (r == 128)  v = sst[64+m]*invl;
        else                v = __expf(sbin[m*132+r])*invl;
        sbin[m*132+r] = v;
    }
    __syncthreads();

    // ---- y = y_pv/l + bins @ erel_v ; store ----
    {
        float invA = 1.f / sst[mA];
        float invB = 1.f / sst[mB];
        #pragma unroll
        for (int c = 0; c < 4; c++) { yA[c] *= invA; yB[c] *= invB; }
        #pragma unroll 4
        for (int r = 0; r < REL_; r++) {
            float ba = sbin[mA*132 + r];
            float bb = sbin[mB*132 + r];
            float4 rv = *(const float4*)&skv[r*68 + c4];
            yA[0] += ba*rv.x; yA[1] += ba*rv.y; yA[2] += ba*rv.z; yA[3] += ba*rv.w;
            yB[0] += bb*rv.x; yB[1] += bb*rv.y; yB[2] += bb*rv.z; yB[3] += bb*rv.w;
        }
        #pragma unroll
        for (int c = 0; c < 4; c++) {
            int d = c4 + c;
            size_t base = ((size_t)b*C_ + h*D_ + d)*T_ + i0;
            g_y[base + mA] = yA[c];
            g_y[base + mB] = yB[c];
        }
    }
}

// =====================================================================
extern "C" void kernel_launch(void* const* d_in, const int* in_sizes, int n_in,
                              void* d_out, int out_size)
{
    const float* x     = (const float*)d_in[0];
    const float* xmask = (const float*)d_in[1];
    const float* Wq    = (const float*)d_in[2];
    const float* bq    = (const float*)d_in[3];
    const float* Wk    = (const float*)d_in[4];
    const float* bk    = (const float*)d_in[5];
    const float* Wv    = (const float*)d_in[6];
    const float* bv    = (const float*)d_in[7];
    const float* Wo    = (const float*)d_in[8];
    const float* bo    = (const float*)d_in[9];
    const float* erelk = (const float*)d_in[10];
    const float* erelv = (const float*)d_in[11];
    float* out = (float*)d_out;

    float *pq, *pk, *pv, *py;
    cudaGetSymbolAddress((void**)&pq, g_q);
    cudaGetSymbolAddress((void**)&pk, g_k);
    cudaGetSymbolAddress((void**)&pv, g_v);
    cudaGetSymbolAddress((void**)&py, g_y);

    cudaFuncSetAttribute(attn_kernel,
                         cudaFuncAttributeMaxDynamicSharedMemorySize, SMEM_BYTES);

    dim3 gg(128, 8), bb(256);
    qkv_gemm<<<gg, bb>>>(Wq, x, bq, pq);
    qkv_gemm<<<gg, bb>>>(Wk, x, bk, pk);
    qkv_gemm<<<gg, bb>>>(Wv, x, bv, pv);

    attn_kernel<<<dim3(32, H_, B_), 256, SMEM_BYTES>>>(xmask, erelk, erelv);

    out_gemm<<<gg, bb>>>(Wo, py, bo, xmask, out);
}

// round 4
// speedup vs baseline: 1.5888x; 1.1080x over previous
#include <cuda_runtime.h>
#include <cuda_bf16.h>

#define B_ 8
#define C_ 512
#define T_ 1024
#define H_ 8
#define D_ 64
#define REL_ 129

// ---------------- scratch (no cudaMalloc allowed) ----------------
__device__ float g_q[B_*H_*T_*D_];   // (B,H,T,D)
__device__ float g_k[B_*H_*T_*D_];
__device__ float g_v[B_*H_*T_*D_];
__device__ float g_y[B_*C_*T_];      // (B,C,T) attention output pre-proj

// ---------------- attn shared memory (byte offsets) ----------------
// strides: q/k bf16 rows stride 72 ; p/v bf16 rows stride 136 ; erel fp32 stride 68
#define OFF_SQ    0          // fp32 [32][64]          8192B
#define OFF_QHI   8192       // bf16 [32][72]          4608B
#define OFF_QLO   12800      // bf16 [32][72]          4608B
#define OFF_KV    17408      // bf16 khi[128][72](18432) + klo(18432)  OR vhi[64][136]+vlo  OR fp32 erel[129][68](35088)
#define OFF_PHI   54272      // bf16 [32][136]         8704B
#define OFF_PLO   62976      // bf16 [32][136]         8704B
#define OFF_SBIN  71680      // fp32 [32][132]        16896B
#define OFF_SQR   88576      // fp32 [32][132]        16896B
#define OFF_SMK   105472     // fp32 [1024]            4096B
#define OFF_SSTP  109568     // fp32 [3][4][32]        1536B
#define OFF_SST   111104     // fp32 [96]               384B
#define SMEM_BYTES 111488

__device__ __forceinline__ unsigned pk2(__nv_bfloat16 a, __nv_bfloat16 b) {
    __nv_bfloat162 t = __halves2bfloat162(a, b);
    return *reinterpret_cast<unsigned*>(&t);
}
__device__ __forceinline__ void cv(float x, __nv_bfloat16& h, __nv_bfloat16& l) {
    h = __float2bfloat16(x);
    l = __float2bfloat16(x - __bfloat162float(h));
}
__device__ __forceinline__ unsigned ld32(const __nv_bfloat16* p) {
    return *reinterpret_cast<const unsigned*>(p);
}
__device__ __forceinline__ void mma16816(float* c, unsigned a0, unsigned a1,
                                         unsigned a2, unsigned a3,
                                         unsigned b0, unsigned b1) {
    asm volatile(
        "mma.sync.aligned.m16n8k16.row.col.f32.bf16.bf16.f32 "
        "{%0,%1,%2,%3}, {%4,%5,%6,%7}, {%8,%9}, {%0,%1,%2,%3};"
        : "+f"(c[0]), "+f"(c[1]), "+f"(c[2]), "+f"(c[3])
        : "r"(a0), "r"(a1), "r"(a2), "r"(a3), "r"(b0), "r"(b1));
}

// =====================================================================
// QKV projection GEMM (unchanged)
// =====================================================================
__global__ __launch_bounds__(256) void qkv_gemm(
    const float* __restrict__ W, const float* __restrict__ X,
    const float* __restrict__ bias, float* __restrict__ out)
{
    __shared__ float As[32*64];
    __shared__ float Bs[32*64];
    const int tid = threadIdx.x;
    const int tx = tid & 15, ty = tid >> 4;
    const int n0 = blockIdx.x * 64;
    const int o0 = blockIdx.y * 64;
    const int b  = n0 / T_;
    const int t0 = n0 % T_;

    float acc[4][4] = {};

    for (int k0 = 0; k0 < C_; k0 += 32) {
        #pragma unroll
        for (int r = 0; r < 2; r++) {
            int li = tid + r*256;
            int oo = li >> 3;
            int kc = (li & 7) << 2;
            float4 w4 = *(const float4*)&W[(size_t)(o0+oo)*C_ + k0 + kc];
            As[(kc+0)*64+oo] = w4.x;
            As[(kc+1)*64+oo] = w4.y;
            As[(kc+2)*64+oo] = w4.z;
            As[(kc+3)*64+oo] = w4.w;
        }
        #pragma unroll
        for (int r = 0; r < 2; r++) {
            int li = tid + r*256;
            int kk = li >> 4;
            int nn = (li & 15) << 2;
            *(float4*)&Bs[kk*64+nn] =
                *(const float4*)&X[(size_t)b*C_*T_ + (size_t)(k0+kk)*T_ + t0 + nn];
        }
        __syncthreads();
        #pragma unroll
        for (int kk = 0; kk < 32; kk++) {
            float4 a4 = *(float4*)&As[kk*64 + tx*4];
            float4 b4 = *(float4*)&Bs[kk*64 + ty*4];
            float a[4] = {a4.x,a4.y,a4.z,a4.w};
            float c[4] = {b4.x,b4.y,b4.z,b4.w};
            #pragma unroll
            for (int i = 0; i < 4; i++)
                #pragma unroll
                for (int j = 0; j < 4; j++)
                    acc[i][j] += a[i]*c[j];
        }
        __syncthreads();
    }

    const int ob = o0 + tx*4;
    const int h = ob >> 6, d = ob & 63;
    float bi[4];
    #pragma unroll
    for (int i = 0; i < 4; i++) bi[i] = bias[ob+i];
    #pragma unroll
    for (int j = 0; j < 4; j++) {
        int t = t0 + ty*4 + j;
        float4 v = make_float4(acc[0][j]+bi[0], acc[1][j]+bi[1],
                               acc[2][j]+bi[2], acc[3][j]+bi[3]);
        *(float4*)&out[(((size_t)(b*H_+h))*T_ + t)*D_ + d] = v;
    }
}

// =====================================================================
// Output projection (unchanged)
// =====================================================================
__global__ __launch_bounds__(256) void out_gemm(
    const float* __restrict__ W, const float* __restrict__ X,
    const float* __restrict__ bias, const float* __restrict__ mask,
    float* __restrict__ out)
{
    __shared__ float As[32*64];
    __shared__ float Bs[32*64];
    const int tid = threadIdx.x;
    const int tx = tid & 15, ty = tid >> 4;
    const int n0 = blockIdx.x * 64;
    const int o0 = blockIdx.y * 64;
    const int b  = n0 / T_;
    const int t0 = n0 % T_;

    float acc[4][4] = {};

    for (int k0 = 0; k0 < C_; k0 += 32) {
        #pragma unroll
        for (int r = 0; r < 2; r++) {
            int li = tid + r*256;
            int oo = li >> 3;
            int kc = (li & 7) << 2;
            float4 w4 = *(const float4*)&W[(size_t)(o0+oo)*C_ + k0 + kc];
            As[(kc+0)*64+oo] = w4.x;
            As[(kc+1)*64+oo] = w4.y;
            As[(kc+2)*64+oo] = w4.z;
            As[(kc+3)*64+oo] = w4.w;
        }
        #pragma unroll
        for (int r = 0; r < 2; r++) {
            int li = tid + r*256;
            int kk = li >> 4;
            int nn = (li & 15) << 2;
            *(float4*)&Bs[kk*64+nn] =
                *(const float4*)&X[(size_t)b*C_*T_ + (size_t)(k0+kk)*T_ + t0 + nn];
        }
        __syncthreads();
        #pragma unroll
        for (int kk = 0; kk < 32; kk++) {
            float4 a4 = *(float4*)&As[kk*64 + ty*4];
            float4 b4 = *(float4*)&Bs[kk*64 + tx*4];
            float a[4] = {a4.x,a4.y,a4.z,a4.w};
            float c[4] = {b4.x,b4.y,b4.z,b4.w};
            #pragma unroll
            for (int i = 0; i < 4; i++)
                #pragma unroll
                for (int j = 0; j < 4; j++)
                    acc[i][j] += a[i]*c[j];
        }
        __syncthreads();
    }

    float4 m4 = *(const float4*)&mask[(size_t)b*T_ + t0 + tx*4];
    #pragma unroll
    for (int i = 0; i < 4; i++) {
        int o = o0 + ty*4 + i;
        float bo = bias[o];
        float4 v = make_float4((acc[i][0]+bo)*m4.x, (acc[i][1]+bo)*m4.y,
                               (acc[i][2]+bo)*m4.z, (acc[i][3]+bo)*m4.w);
        *(float4*)&out[(size_t)b*C_*T_ + (size_t)o*T_ + t0 + tx*4] = v;
    }
}

// =====================================================================
// Fused attention, tensor-core (bf16x3 mma.sync) version.
// Per CTA: 32 queries x full T keys, 8 chunks of 128.
// =====================================================================
__global__ __launch_bounds__(256, 2) void attn_kernel(
    const float* __restrict__ mask,
    const float* __restrict__ erel_k,
    const float* __restrict__ erel_v)
{
    extern __shared__ unsigned char smem[];
    float*          sq   = (float*)(smem + OFF_SQ);
    __nv_bfloat16*  qhi  = (__nv_bfloat16*)(smem + OFF_QHI);
    __nv_bfloat16*  qlo  = (__nv_bfloat16*)(smem + OFF_QLO);
    __nv_bfloat16*  khi  = (__nv_bfloat16*)(smem + OFF_KV);
    __nv_bfloat16*  klo  = (__nv_bfloat16*)(smem + OFF_KV + 18432);
    __nv_bfloat16*  vhi  = khi;
    __nv_bfloat16*  vlo  = klo;
    float*          serel= (float*)(smem + OFF_KV);       // fp32 [129][68]
    __nv_bfloat16*  phi  = (__nv_bfloat16*)(smem + OFF_PHI);
    __nv_bfloat16*  plo  = (__nv_bfloat16*)(smem + OFF_PLO);
    float*          sbin = (float*)(smem + OFF_SBIN);
    float*          sqr  = (float*)(smem + OFF_SQR);
    float*          smk  = (float*)(smem + OFF_SMK);
    float*          sstp = (float*)(smem + OFF_SSTP);
    float*          sst  = (float*)(smem + OFF_SST);

    const int tid  = threadIdx.x;
    const int lane = tid & 31;
    const int w    = tid >> 5;
    const int mt   = w & 1;            // m16 tile (rows mt*16..+16)
    const int wg   = w >> 1;           // col group
    const int lg   = lane >> 2;        // fragment groupID
    const int tg   = lane & 3;         // fragment threadID-in-group
    const int r0   = mt*16 + lg;
    const int r1   = r0 + 8;

    const int i0 = blockIdx.x * 32;
    const int h  = blockIdx.y;
    const int b  = blockIdx.z;
    const size_t headbase = (size_t)(b*H_+h)*T_*D_;

    // ---- Phase A: loads + init ----
    for (int e = tid; e < 512; e += 256)
        ((float4*)sq)[e] = ((const float4*)(g_q + headbase + (size_t)i0*D_))[e];
    for (int e = tid; e < REL_*16; e += 256) {
        int r = e >> 4, d4 = (e & 15) << 2;
        *(float4*)&serel[r*68 + d4] = ((const float4*)erel_k)[e];
    }
    for (int e = tid; e < T_/4; e += 256)
        ((float4*)smk)[e] = ((const float4*)(mask + (size_t)b*T_))[e];
    for (int e = tid; e < 32*132; e += 256)
        sbin[e] = -1e9f;
    __syncthreads();

    // ---- Phase B: qrel + q hi/lo conversion ----
    for (int idx = tid; idx < 32*REL_; idx += 256) {
        int m = idx / REL_, r = idx - m*REL_;
        const float4* q4 = (const float4*)(sq + m*64);
        const float4* e4 = (const float4*)(serel + r*68);
        float s = 0.f;
        #pragma unroll
        for (int d = 0; d < 16; d++) {
            float4 a = q4[d], bb = e4[d];
            s += a.x*bb.x + a.y*bb.y + a.z*bb.z + a.w*bb.w;
        }
        sqr[m*132 + r] = s;
    }
    for (int e = tid; e < 512; e += 256) {
        int m = e >> 4, d4 = (e & 15) << 2;
        float4 qv = *(const float4*)&sq[m*64 + d4];
        __nv_bfloat16 h0,l0,h1,l1,h2,l2,h3,l3;
        cv(qv.x,h0,l0); cv(qv.y,h1,l1); cv(qv.z,h2,l2); cv(qv.w,h3,l3);
        *(uint2*)&qhi[m*72 + d4] = make_uint2(pk2(h0,h1), pk2(h2,h3));
        *(uint2*)&qlo[m*72 + d4] = make_uint2(pk2(l0,l1), pk2(l2,l3));
    }

    const float scale = 0.125f;   // 1/sqrt(64)
    float yacc[2][4] = {};        // PV accumulators (persist across chunks)
    float ls0=0.f, ls1=0.f, ea0=0.f, ea1=0.f, eb0=0.f, eb1=0.f;

    // ---- Main loop over 8 key chunks of 128 ----
    for (int kt = 0; kt < 8; kt++) {
        const int j0g = kt * 128;
        __syncthreads();   // prev PV reads of vhi / phase-B reads done
        // convert K chunk -> khi/klo [j][72]
        #pragma unroll
        for (int r = 0; r < 8; r++) {
            int e = tid + r*256;
            int j = e >> 4, d4 = (e & 15) << 2;
            float4 kv = *(const float4*)&g_k[headbase + (size_t)(j0g + j)*D_ + d4];
            __nv_bfloat16 h0,l0,h1,l1,h2,l2,h3,l3;
            cv(kv.x,h0,l0); cv(kv.y,h1,l1); cv(kv.z,h2,l2); cv(kv.w,h3,l3);
            *(uint2*)&khi[j*72 + d4] = make_uint2(pk2(h0,h1), pk2(h2,h3));
            *(uint2*)&klo[j*72 + d4] = make_uint2(pk2(l0,l1), pk2(l2,l3));
        }
        __syncthreads();

        // ---- S = Q K^T via mma (warp: m16 tile mt, cols wg*32..+32) ----
        float sacc[4][4] = {};
        #pragma unroll
        for (int ks = 0; ks < 4; ks++) {
            const int kk = ks*16 + tg*2;
            unsigned a0h = ld32(&qhi[(mt*16+lg)*72 + kk]);
            unsigned a1h = ld32(&qhi[(mt*16+lg+8)*72 + kk]);
            unsigned a2h = ld32(&qhi[(mt*16+lg)*72 + kk + 8]);
            unsigned a3h = ld32(&qhi[(mt*16+lg+8)*72 + kk + 8]);
            unsigned a0l = ld32(&qlo[(mt*16+lg)*72 + kk]);
            unsigned a1l = ld32(&qlo[(mt*16+lg+8)*72 + kk]);
            unsigned a2l = ld32(&qlo[(mt*16+lg)*72 + kk + 8]);
            unsigned a3l = ld32(&qlo[(mt*16+lg+8)*72 + kk + 8]);
            #pragma unroll
            for (int t = 0; t < 4; t++) {
                const int nb = wg*32 + t*8;
                unsigned b0h = ld32(&khi[(nb+lg)*72 + kk]);
                unsigned b1h = ld32(&khi[(nb+lg)*72 + kk + 8]);
                unsigned b0l = ld32(&klo[(nb+lg)*72 + kk]);
                unsigned b1l = ld32(&klo[(nb+lg)*72 + kk + 8]);
                mma16816(sacc[t], a0h,a1h,a2h,a3h, b0h,b1h);
                mma16816(sacc[t], a0h,a1h,a2h,a3h, b0l,b1l);
                mma16816(sacc[t], a0l,a1l,a2l,a3l, b0h,b1h);
            }
        }

        // ---- epilogue: rel gather, mask, exp, bins, P hi/lo stores ----
        #pragma unroll
        for (int t = 0; t < 4; t++) {
            const int cb = wg*32 + t*8 + tg*2;
            #pragma unroll
            for (int ii = 0; ii < 2; ii++) {
                const int rr = ii ? r1 : r0;
                const int gi = i0 + rr;
                float ev[2];
                #pragma unroll
                for (int jj = 0; jj < 2; jj++) {
                    int gj = j0g + cb + jj;
                    int rel = gj - gi;
                    int relc = rel < -64 ? -64 : (rel > 64 ? 64 : rel);
                    float s = sacc[t][ii*2+jj]*scale + sqr[rr*132 + relc + 64];
                    if (smk[gj] <= 0.f) s = -1e9f;
                    float e = __expf(s);
                    if (ii == 0) ls0 += e; else ls1 += e;
                    if (rel <= -64)      { if (ii == 0) ea0 += e; else ea1 += e; }
                    else if (rel >= 64)  { if (ii == 0) eb0 += e; else eb1 += e; }
                    else                 sbin[rr*132 + rel + 64] = s;
                    ev[jj] = e;
                }
                __nv_bfloat16 eh0,el0,eh1,el1;
                cv(ev[0],eh0,el0); cv(ev[1],eh1,el1);
                *(unsigned*)&phi[rr*136 + cb] = pk2(eh0,eh1);
                *(unsigned*)&plo[rr*136 + cb] = pk2(el0,el1);
            }
        }
        __syncthreads();   // S reads of khi done; phi/plo visible

        // convert V chunk -> transposed vhi/vlo [d][136]
        #pragma unroll
        for (int r = 0; r < 8; r++) {
            int e = tid + r*256;
            int j = e >> 4, d4 = (e & 15) << 2;
            float4 vv = *(const float4*)&g_v[headbase + (size_t)(j0g + j)*D_ + d4];
            __nv_bfloat16 h0,l0,h1,l1,h2,l2,h3,l3;
            cv(vv.x,h0,l0); cv(vv.y,h1,l1); cv(vv.z,h2,l2); cv(vv.w,h3,l3);
            vhi[(d4+0)*136 + j] = h0; vlo[(d4+0)*136 + j] = l0;
            vhi[(d4+1)*136 + j] = h1; vlo[(d4+1)*136 + j] = l1;
            vhi[(d4+2)*136 + j] = h2; vlo[(d4+2)*136 + j] = l2;
            vhi[(d4+3)*136 + j] = h3; vlo[(d4+3)*136 + j] = l3;
        }
        __syncthreads();

        // ---- PV: y += P_chunk @ V_chunk (warp: m16 tile mt, d tiles wg, wg+4) ----
        #pragma unroll
        for (int ks = 0; ks < 8; ks++) {
            const int kk = ks*16 + tg*2;
            unsigned a0h = ld32(&phi[(mt*16+lg)*136 + kk]);
            unsigned a1h = ld32(&phi[(mt*16+lg+8)*136 + kk]);
            unsigned a2h = ld32(&phi[(mt*16+lg)*136 + kk + 8]);
            unsigned a3h = ld32(&phi[(mt*16+lg+8)*136 + kk + 8]);
            unsigned a0l = ld32(&plo[(mt*16+lg)*136 + kk]);
            unsigned a1l = ld32(&plo[(mt*16+lg+8)*136 + kk]);
            unsigned a2l = ld32(&plo[(mt*16+lg)*136 + kk + 8]);
            unsigned a3l = ld32(&plo[(mt*16+lg+8)*136 + kk + 8]);
            #pragma unroll
            for (int ti = 0; ti < 2; ti++) {
                const int nb = (wg + ti*4)*8;
                unsigned b0h = ld32(&vhi[(nb+lg)*136 + kk]);
                unsigned b1h = ld32(&vhi[(nb+lg)*136 + kk + 8]);
                unsigned b0l = ld32(&vlo[(nb+lg)*136 + kk]);
                unsigned b1l = ld32(&vlo[(nb+lg)*136 + kk + 8]);
                mma16816(yacc[ti], a0h,a1h,a2h,a3h, b0h,b1h);
                mma16816(yacc[ti], a0h,a1h,a2h,a3h, b0l,b1l);
                mma16816(yacc[ti], a0l,a1l,a2l,a3l, b0h,b1h);
            }
        }
    }
    __syncthreads();   // last PV reads done

    // ---- load erel_v (fp32, overwrites kv buffer) + stat reduction ----
    for (int e = tid; e < REL_*16; e += 256) {
        int r = e >> 4, d4 = (e & 15) << 2;
        *(float4*)&serel[r*68 + d4] = ((const float4*)erel_v)[e];
    }
    {
        float v;
        #define RED_(x) v = x; v += __shfl_xor_sync(~0u, v, 1); v += __shfl_xor_sync(~0u, v, 2); x = v;
        RED_(ls0) RED_(ls1) RED_(ea0) RED_(ea1) RED_(eb0) RED_(eb1)
        #undef RED_
        if (tg == 0) {
            sstp[0*128 + wg*32 + r0] = ls0;  sstp[0*128 + wg*32 + r1] = ls1;
            sstp[1*128 + wg*32 + r0] = ea0;  sstp[1*128 + wg*32 + r1] = ea1;
            sstp[2*128 + wg*32 + r0] = eb0;  sstp[2*128 + wg*32 + r1] = eb1;
        }
    }
    __syncthreads();
    if (tid < 32) {
        float l = 0.f, a = 0.f, c = 0.f;
        #pragma unroll
        for (int g = 0; g < 4; g++) {
            l += sstp[0*128 + g*32 + tid];
            a += sstp[1*128 + g*32 + tid];
            c += sstp[2*128 + g*32 + tid];
        }
        sst[tid] = l; sst[32+tid] = a; sst[64+tid] = c;
    }
    __syncthreads();

    // ---- finalize bins ----
    for (int e = tid; e < 32*REL_; e += 256) {
        int m = e / REL_, r = e - m*REL_;
        float invl = 1.f / sst[m];
        float v;
        if (r == 0)         v = sst[32+m]*invl;
        else if (r == 128)  v = sst[64+m]*invl;
        else                v = __expf(sbin[m*132+r])*invl;
        sbin[m*132+r] = v;
    }
    __syncthreads();

    // ---- final: y = yacc/l + bins @ erel_v ; store ----
    {
        const float inv0 = 1.f / sst[r0];
        const float inv1 = 1.f / sst[r1];
        const int dA = wg*8 + tg*2;
        const int dB = dA + 32;
        float o00 = yacc[0][0]*inv0, o01 = yacc[0][1]*inv0;
        float o02 = yacc[0][2]*inv1, o03 = yacc[0][3]*inv1;
        float o10 = yacc[1][0]*inv0, o11 = yacc[1][1]*inv0;
        float o12 = yacc[1][2]*inv1, o13 = yacc[1][3]*inv1;
        #pragma unroll 4
        for (int r = 0; r < REL_; r++) {
            float b0 = sbin[r0*132 + r];
            float b1 = sbin[r1*132 + r];
            float2 eA = *(const float2*)&serel[r*68 + dA];
            float2 eB = *(const float2*)&serel[r*68 + dB];
            o00 += b0*eA.x; o01 += b0*eA.y;
            o02 += b1*eA.x; o03 += b1*eA.y;
            o10 += b0*eB.x; o11 += b0*eB.y;
            o12 += b1*eB.x; o13 += b1*eB.y;
        }
        const size_t cb0 = (size_t)b*C_ + h*64;
        g_y[(cb0 + dA  )*T_ + i0 + r0] = o00;
        g_y[(cb0 + dA+1)*T_ + i0 + r0] = o01;
        g_y[(cb0 + dA  )*T_ + i0 + r1] = o02;
        g_y[(cb0 + dA+1)*T_ + i0 + r1] = o03;
        g_y[(cb0 + dB  )*T_ + i0 + r0] = o10;
        g_y[(cb0 + dB+1)*T_ + i0 + r0] = o11;
        g_y[(cb0 + dB  )*T_ + i0 + r1] = o12;
        g_y[(cb0 + dB+1)*T_ + i0 + r1] = o13;
    }
}

// =====================================================================
extern "C" void kernel_launch(void* const* d_in, const int* in_sizes, int n_in,
                              void* d_out, int out_size)
{
    const float* x     = (const float*)d_in[0];
    const float* xmask = (const float*)d_in[1];
    const float* Wq    = (const float*)d_in[2];
    const float* bq    = (const float*)d_in[3];
    const float* Wk    = (const float*)d_in[4];
    const float* bk    = (const float*)d_in[5];
    const float* Wv    = (const float*)d_in[6];
    const float* bv    = (const float*)d_in[7];
    const float* Wo    = (const float*)d_in[8];
    const float* bo    = (const float*)d_in[9];
    const float* erelk = (const float*)d_in[10];
    const float* erelv = (const float*)d_in[11];
    float* out = (float*)d_out;

    float *pq, *pk, *pv, *py;
    cudaGetSymbolAddress((void**)&pq, g_q);
    cudaGetSymbolAddress((void**)&pk, g_k);
    cudaGetSymbolAddress((void**)&pv, g_v);
    cudaGetSymbolAddress((void**)&py, g_y);

    cudaFuncSetAttribute(attn_kernel,
                         cudaFuncAttributeMaxDynamicSharedMemorySize, SMEM_BYTES);

    dim3 gg(128, 8), bb(256);
    qkv_gemm<<<gg, bb>>>(Wq, x, bq, pq);
    qkv_gemm<<<gg, bb>>>(Wk, x, bk, pk);
    qkv_gemm<<<gg, bb>>>(Wv, x, bv, pv);

    attn_kernel<<<dim3(32, H_, B_), 256, SMEM_BYTES>>>(xmask, erelk, erelv);

    out_gemm<<<gg, bb>>>(Wo, py, bo, xmask, out);
}

// round 5
// speedup vs baseline: 1.9209x; 1.2090x over previous
#include <cuda_runtime.h>
#include <cuda_bf16.h>

#define B_ 8
#define C_ 512
#define T_ 1024
#define H_ 8
#define D_ 64
#define REL_ 129

// ---------------- scratch (no cudaMalloc allowed) ----------------
__device__ __nv_bfloat16 g_qhi[B_*H_*T_*D_];  // (B,H,T,D)
__device__ __nv_bfloat16 g_qlo[B_*H_*T_*D_];
__device__ __nv_bfloat16 g_khi[B_*H_*T_*D_];  // (B,H,T,D)
__device__ __nv_bfloat16 g_klo[B_*H_*T_*D_];
__device__ __nv_bfloat16 g_vhi[B_*H_*T_*D_];  // (B,H,D,T)  pre-transposed
__device__ __nv_bfloat16 g_vlo[B_*H_*T_*D_];
__device__ float g_y[B_*C_*T_];               // (B,C,T)

// ---------------- attn shared memory (byte offsets) ----------------
#define OFF_QHI   0        // bf16 [32][72]   4608
#define OFF_QLO   4608     // bf16 [32][72]   4608
#define OFF_KV    9216     // khi[128][72]+klo | vhi[64][136]+vlo | fp32 erel[129][68]
#define OFF_PHI   46080    // bf16 [32][136]  8704
#define OFF_PLO   54784    // bf16 [32][136]  8704
#define OFF_SBIN  63488    // fp32 [32][132] 16896
#define OFF_SQR   80384    // fp32 [32][132] 16896
#define OFF_SMK   97280    // fp32 [1024]     4096
#define OFF_SSTP  101376   // fp32 [3][128]   1536
#define OFF_SST   102912   // fp32 [96]        384
#define SMEM_BYTES 103296

__device__ __forceinline__ unsigned pk2(__nv_bfloat16 a, __nv_bfloat16 b) {
    __nv_bfloat162 t = __halves2bfloat162(a, b);
    return *reinterpret_cast<unsigned*>(&t);
}
__device__ __forceinline__ void cv(float x, __nv_bfloat16& h, __nv_bfloat16& l) {
    h = __float2bfloat16(x);
    l = __float2bfloat16(x - __bfloat162float(h));
}
__device__ __forceinline__ unsigned su32(const void* p) {
    return (unsigned)__cvta_generic_to_shared(p);
}
__device__ __forceinline__ void cpasync16(unsigned s, const void* g) {
    asm volatile("cp.async.cg.shared.global [%0], [%1], 16;" :: "r"(s), "l"(g));
}
__device__ __forceinline__ void cp_commit_wait() {
    asm volatile("cp.async.commit_group;\n\tcp.async.wait_group 0;" ::: "memory");
}
__device__ __forceinline__ void ldsm4(unsigned& r0, unsigned& r1, unsigned& r2,
                                      unsigned& r3, unsigned addr) {
    asm volatile("ldmatrix.sync.aligned.m8n8.x4.shared.b16 {%0,%1,%2,%3}, [%4];"
                 : "=r"(r0), "=r"(r1), "=r"(r2), "=r"(r3) : "r"(addr));
}
__device__ __forceinline__ void mma16816(float* c, unsigned a0, unsigned a1,
                                         unsigned a2, unsigned a3,
                                         unsigned b0, unsigned b1) {
    asm volatile(
        "mma.sync.aligned.m16n8k16.row.col.f32.bf16.bf16.f32 "
        "{%0,%1,%2,%3}, {%4,%5,%6,%7}, {%8,%9}, {%0,%1,%2,%3};"
        : "+f"(c[0]), "+f"(c[1]), "+f"(c[2]), "+f"(c[3])
        : "r"(a0), "r"(a1), "r"(a2), "r"(a3), "r"(b0), "r"(b1));
}

// =====================================================================
// Projection GEMM core (64x64 tile, 4x4 micro) — shared by Q/K/V variants
// =====================================================================
#define PROJ_BODY \
    __shared__ float As[32*64]; \
    __shared__ float Bs[32*64]; \
    const int tid = threadIdx.x; \
    const int tx = tid & 15, ty = tid >> 4; \
    const int n0 = blockIdx.x * 64; \
    const int o0 = blockIdx.y * 64; \
    const int b  = n0 / T_; \
    const int t0 = n0 % T_; \
    float acc[4][4] = {}; \
    for (int k0 = 0; k0 < C_; k0 += 32) { \
        _Pragma("unroll") \
        for (int r = 0; r < 2; r++) { \
            int li = tid + r*256; \
            int oo = li >> 3; \
            int kc = (li & 7) << 2; \
            float4 w4 = *(const float4*)&W[(size_t)(o0+oo)*C_ + k0 + kc]; \
            As[(kc+0)*64+oo] = w4.x; \
            As[(kc+1)*64+oo] = w4.y; \
            As[(kc+2)*64+oo] = w4.z; \
            As[(kc+3)*64+oo] = w4.w; \
        } \
        _Pragma("unroll") \
        for (int r = 0; r < 2; r++) { \
            int li = tid + r*256; \
            int kk = li >> 4; \
            int nn = (li & 15) << 2; \
            *(float4*)&Bs[kk*64+nn] = \
                *(const float4*)&X[(size_t)b*C_*T_ + (size_t)(k0+kk)*T_ + t0 + nn]; \
        } \
        __syncthreads(); \
        _Pragma("unroll") \
        for (int kk = 0; kk < 32; kk++) { \
            float4 a4 = *(float4*)&As[kk*64 + tx*4]; \
            float4 b4 = *(float4*)&Bs[kk*64 + ty*4]; \
            float a[4] = {a4.x,a4.y,a4.z,a4.w}; \
            float c[4] = {b4.x,b4.y,b4.z,b4.w}; \
            _Pragma("unroll") \
            for (int i = 0; i < 4; i++) \
                _Pragma("unroll") \
                for (int j = 0; j < 4; j++) \
                    acc[i][j] += a[i]*c[j]; \
        } \
        __syncthreads(); \
    }

// Q/K variant: out (B,H,T,D) bf16 hi/lo
__global__ __launch_bounds__(256) void proj_qk(
    const float* __restrict__ W, const float* __restrict__ X,
    const float* __restrict__ bias,
    __nv_bfloat16* __restrict__ outhi, __nv_bfloat16* __restrict__ outlo)
{
    PROJ_BODY
    const int ob = o0 + tx*4;
    const int h = ob >> 6, d = ob & 63;
    float bi[4];
    #pragma unroll
    for (int i = 0; i < 4; i++) bi[i] = bias[ob+i];
    #pragma unroll
    for (int j = 0; j < 4; j++) {
        int t = t0 + ty*4 + j;
        __nv_bfloat16 h0,l0,h1,l1,h2,l2,h3,l3;
        cv(acc[0][j]+bi[0],h0,l0); cv(acc[1][j]+bi[1],h1,l1);
        cv(acc[2][j]+bi[2],h2,l2); cv(acc[3][j]+bi[3],h3,l3);
        size_t idx = (((size_t)(b*H_+h))*T_ + t)*D_ + d;
        *(uint2*)&outhi[idx] = make_uint2(pk2(h0,h1), pk2(h2,h3));
        *(uint2*)&outlo[idx] = make_uint2(pk2(l0,l1), pk2(l2,l3));
    }
}

// V variant: out (B,H,D,T) bf16 hi/lo (transposed store)
__global__ __launch_bounds__(256) void proj_v(
    const float* __restrict__ W, const float* __restrict__ X,
    const float* __restrict__ bias,
    __nv_bfloat16* __restrict__ outhi, __nv_bfloat16* __restrict__ outlo)
{
    PROJ_BODY
    #pragma unroll
    for (int i = 0; i < 4; i++) {
        int o = o0 + tx*4 + i;
        int h = o >> 6, d = o & 63;
        float bo = bias[o];
        __nv_bfloat16 h0,l0,h1,l1,h2,l2,h3,l3;
        cv(acc[i][0]+bo,h0,l0); cv(acc[i][1]+bo,h1,l1);
        cv(acc[i][2]+bo,h2,l2); cv(acc[i][3]+bo,h3,l3);
        size_t idx = (((size_t)(b*H_+h))*D_ + d)*T_ + t0 + ty*4;
        *(uint2*)&outhi[idx] = make_uint2(pk2(h0,h1), pk2(h2,h3));
        *(uint2*)&outlo[idx] = make_uint2(pk2(l0,l1), pk2(l2,l3));
    }
}

// =====================================================================
// Output projection (unchanged)
// =====================================================================
__global__ __launch_bounds__(256) void out_gemm(
    const float* __restrict__ W, const float* __restrict__ X,
    const float* __restrict__ bias, const float* __restrict__ mask,
    float* __restrict__ out)
{
    PROJ_BODY
    float4 m4 = *(const float4*)&mask[(size_t)b*T_ + t0 + tx*4];
    #pragma unroll
    for (int i = 0; i < 4; i++) {
        int o = o0 + ty*4 + i;
        // NOTE: this variant multiplies along ty->o, tx->n mapping of original
        (void)o;
    }
    // re-do epilogue with ty->o, tx->n mapping (acc computed with tx/ty as in body:
    // body maps tx->o for As reads; we need the out layout (o rows, t cols))
    // --- use same mapping as body: tx->o, ty->t; store transposed ---
    const int ob = o0 + tx*4;
    #pragma unroll
    for (int i = 0; i < 4; i++) {
        float bo = bias[ob+i];
        #pragma unroll
        for (int j = 0; j < 4; j++) {
            int t = t0 + ty*4 + j;
            float mval = (j==0)?m4.x:(j==1)?m4.y:(j==2)?m4.z:m4.w;
            // m4 was loaded with tx mapping; reload correct scalar:
            mval = mask[(size_t)b*T_ + t];
            out[(size_t)b*C_*T_ + (size_t)(ob+i)*T_ + t] = (acc[i][j]+bo)*mval;
        }
    }
}

// =====================================================================
// Fused attention: tensor-core bf16x3, cp.async staging, ldmatrix frags.
// =====================================================================
__global__ __launch_bounds__(256, 2) void attn_kernel(
    const float* __restrict__ mask,
    const float* __restrict__ erel_k,
    const float* __restrict__ erel_v)
{
    extern __shared__ unsigned char smem[];
    __nv_bfloat16* qhi = (__nv_bfloat16*)(smem + OFF_QHI);
    __nv_bfloat16* qlo = (__nv_bfloat16*)(smem + OFF_QLO);
    __nv_bfloat16* khi = (__nv_bfloat16*)(smem + OFF_KV);
    __nv_bfloat16* klo = (__nv_bfloat16*)(smem + OFF_KV + 18432);
    __nv_bfloat16* vhi = (__nv_bfloat16*)(smem + OFF_KV);
    __nv_bfloat16* vlo = (__nv_bfloat16*)(smem + OFF_KV + 17408);
    float*         serel = (float*)(smem + OFF_KV);      // fp32 [129][68]
    __nv_bfloat16* phi = (__nv_bfloat16*)(smem + OFF_PHI);
    __nv_bfloat16* plo = (__nv_bfloat16*)(smem + OFF_PLO);
    float* sbin = (float*)(smem + OFF_SBIN);
    float* sqr  = (float*)(smem + OFF_SQR);
    float* smk  = (float*)(smem + OFF_SMK);
    float* sstp = (float*)(smem + OFF_SSTP);
    float* sst  = (float*)(smem + OFF_SST);

    const int tid  = threadIdx.x;
    const int lane = tid & 31;
    const int w    = tid >> 5;
    const int mt   = w & 1;
    const int wg   = w >> 1;
    const int lg   = lane >> 2;
    const int tg   = lane & 3;
    const int r0   = mt*16 + lg;
    const int r1   = r0 + 8;
    const int l7   = lane & 7;
    const int lh   = (lane >> 3) & 1;
    const int lq   = lane >> 4;

    const int i0 = blockIdx.x * 32;
    const int h  = blockIdx.y;
    const int b  = blockIdx.z;
    const size_t headbase = (size_t)(b*H_+h)*T_*D_;

    // ---- Phase A: stage q (cp.async), erel_k, mask, init sbin ----
    #pragma unroll
    for (int r = 0; r < 2; r++) {
        int e = tid + r*256;
        int bufi = e >> 8;
        int rc = e & 255;
        int m = rc >> 3, c = rc & 7;
        unsigned dst = su32(bufi ? qlo : qhi) + m*144 + c*16;
        const unsigned char* src =
            (const unsigned char*)(bufi ? g_qlo : g_qhi)
            + (headbase + (size_t)(i0+m)*D_)*2 + c*16;
        cpasync16(dst, src);
    }
    for (int e = tid; e < REL_*16; e += 256) {
        int r = e >> 4, d4 = (e & 15) << 2;
        *(float4*)&serel[r*68 + d4] = ((const float4*)erel_k)[e];
    }
    for (int e = tid; e < T_/4; e += 256)
        ((float4*)smk)[e] = ((const float4*)(mask + (size_t)b*T_))[e];
    for (int e = tid; e < 32*132; e += 256)
        sbin[e] = -1e9f;
    cp_commit_wait();
    __syncthreads();

    // ---- Phase B: qrel[m][r] = (qhi+qlo)[m] . erel_k[r] ----
    for (int idx = tid; idx < 32*REL_; idx += 256) {
        int m = idx / REL_, r = idx - m*REL_;
        const __nv_bfloat162* qh = (const __nv_bfloat162*)&qhi[m*72];
        const __nv_bfloat162* ql = (const __nv_bfloat162*)&qlo[m*72];
        const float2* e2 = (const float2*)&serel[r*68];
        float s = 0.f;
        #pragma unroll
        for (int i = 0; i < 32; i++) {
            __nv_bfloat162 hh = qh[i], ll = ql[i];
            float2 ee = e2[i];
            s += (__bfloat162float(hh.x)+__bfloat162float(ll.x))*ee.x
               + (__bfloat162float(hh.y)+__bfloat162float(ll.y))*ee.y;
        }
        sqr[m*132 + r] = s;
    }

    const float scale = 0.125f;
    float yacc[2][4] = {};
    float ls0=0.f, ls1=0.f, ea0=0.f, ea1=0.f, eb0=0.f, eb1=0.f;

    // precomputed ldmatrix lane addresses (k-base added per step)
    const unsigned qhiA = su32(qhi) + (unsigned)((mt*16 + lh*8 + l7)*144 + lq*16);
    const unsigned qloA = su32(qlo) + (unsigned)((mt*16 + lh*8 + l7)*144 + lq*16);
    const unsigned khiB0 = su32(khi) + (unsigned)((wg*32 + lq*8 + l7)*144 + lh*16);
    const unsigned kloB0 = su32(klo) + (unsigned)((wg*32 + lq*8 + l7)*144 + lh*16);
    const unsigned phiA = su32(phi) + (unsigned)((mt*16 + lh*8 + l7)*272 + lq*16);
    const unsigned ploA = su32(plo) + (unsigned)((mt*16 + lh*8 + l7)*272 + lq*16);
    const unsigned vhiB = su32(vhi) + (unsigned)((wg*8 + lq*32 + l7)*272 + lh*16);
    const unsigned vloB = su32(vlo) + (unsigned)((wg*8 + lq*32 + l7)*272 + lh*16);

    // ---- Main loop over 8 key chunks of 128 ----
    for (int kt = 0; kt < 8; kt++) {
        const int j0g = kt * 128;
        __syncthreads();   // prev reads of KV region done
        // stage khi/klo [128][72]
        #pragma unroll
        for (int r = 0; r < 8; r++) {
            int e = tid + r*256;
            int bufi = e >> 10;
            int rc = e & 1023;
            int j = rc >> 3, c = rc & 7;
            unsigned dst = su32(bufi ? klo : khi) + j*144 + c*16;
            const unsigned char* src =
                (const unsigned char*)(bufi ? g_klo : g_khi)
                + (headbase + (size_t)(j0g+j)*D_)*2 + c*16;
            cpasync16(dst, src);
        }
        cp_commit_wait();
        __syncthreads();

        // ---- S = Q K^T ----
        float sacc[4][4] = {};
        #pragma unroll
        for (int ks = 0; ks < 4; ks++) {
            const unsigned ko = ks*32;   // k offset bytes (16 elems * 2B)
            unsigned aH0,aH1,aH2,aH3, aL0,aL1,aL2,aL3;
            ldsm4(aH0,aH1,aH2,aH3, qhiA + ko);
            ldsm4(aL0,aL1,aL2,aL3, qloA + ko);
            unsigned bH[8], bL[8];
            ldsm4(bH[0],bH[1],bH[2],bH[3], khiB0 + ko);
            ldsm4(bH[4],bH[5],bH[6],bH[7], khiB0 + 16*144 + ko);
            ldsm4(bL[0],bL[1],bL[2],bL[3], kloB0 + ko);
            ldsm4(bL[4],bL[5],bL[6],bL[7], kloB0 + 16*144 + ko);
            #pragma unroll
            for (int t = 0; t < 4; t++) {
                unsigned b0h = bH[t*2], b1h = bH[t*2+1];
                unsigned b0l = bL[t*2], b1l = bL[t*2+1];
                mma16816(sacc[t], aH0,aH1,aH2,aH3, b0h,b1h);
                mma16816(sacc[t], aH0,aH1,aH2,aH3, b0l,b1l);
                mma16816(sacc[t], aL0,aL1,aL2,aL3, b0h,b1h);
            }
        }

        // ---- epilogue: rel gather, mask, exp, bins, P hi/lo ----
        #pragma unroll
        for (int t = 0; t < 4; t++) {
            const int cb = wg*32 + t*8 + tg*2;
            #pragma unroll
            for (int ii = 0; ii < 2; ii++) {
                const int rr = ii ? r1 : r0;
                const int gi = i0 + rr;
                float ev[2];
                #pragma unroll
                for (int jj = 0; jj < 2; jj++) {
                    int gj = j0g + cb + jj;
                    int rel = gj - gi;
                    int relc = rel < -64 ? -64 : (rel > 64 ? 64 : rel);
                    float s = sacc[t][ii*2+jj]*scale + sqr[rr*132 + relc + 64];
                    if (smk[gj] <= 0.f) s = -1e9f;
                    float e = __expf(s);
                    if (ii == 0) ls0 += e; else ls1 += e;
                    if (rel <= -64)      { if (ii == 0) ea0 += e; else ea1 += e; }
                    else if (rel >= 64)  { if (ii == 0) eb0 += e; else eb1 += e; }
                    else                 sbin[rr*132 + rel + 64] = s;
                    ev[jj] = e;
                }
                __nv_bfloat16 eh0,el0,eh1,el1;
                cv(ev[0],eh0,el0); cv(ev[1],eh1,el1);
                *(unsigned*)&phi[rr*136 + cb] = pk2(eh0,eh1);
                *(unsigned*)&plo[rr*136 + cb] = pk2(el0,el1);
            }
        }
        __syncthreads();   // K reads done, phi/plo visible

        // stage vhi/vlo [64][136] (global (B,H,D,T): row d, cols j0g..+128)
        #pragma unroll
        for (int r = 0; r < 8; r++) {
            int e = tid + r*256;
            int bufi = e >> 10;
            int rc = e & 1023;
            int d = rc >> 4, c = rc & 15;
            unsigned dst = su32(bufi ? vlo : vhi) + d*272 + c*16;
            const unsigned char* src =
                (const unsigned char*)(bufi ? g_vlo : g_vhi)
                + (headbase + (size_t)d*T_ + j0g)*2 + c*16;
            cpasync16(dst, src);
        }
        cp_commit_wait();
        __syncthreads();

        // ---- PV: y += P @ V ----
        #pragma unroll
        for (int ks = 0; ks < 8; ks++) {
            const unsigned ko = ks*32;
            unsigned aH0,aH1,aH2,aH3, aL0,aL1,aL2,aL3;
            ldsm4(aH0,aH1,aH2,aH3, phiA + ko);
            ldsm4(aL0,aL1,aL2,aL3, ploA + ko);
            unsigned bH[4], bL[4];
            ldsm4(bH[0],bH[1],bH[2],bH[3], vhiB + ko);
            ldsm4(bL[0],bL[1],bL[2],bL[3], vloB + ko);
            #pragma unroll
            for (int ti = 0; ti < 2; ti++) {
                unsigned b0h = bH[ti*2], b1h = bH[ti*2+1];
                unsigned b0l = bL[ti*2], b1l = bL[ti*2+1];
                mma16816(yacc[ti], aH0,aH1,aH2,aH3, b0h,b1h);
                mma16816(yacc[ti], aH0,aH1,aH2,aH3, b0l,b1l);
                mma16816(yacc[ti], aL0,aL1,aL2,aL3, b0h,b1h);
            }
        }
    }
    __syncthreads();   // last PV reads done

    // ---- load erel_v + stat reduction ----
    for (int e = tid; e < REL_*16; e += 256) {
        int r = e >> 4, d4 = (e & 15) << 2;
        *(float4*)&serel[r*68 + d4] = ((const float4*)erel_v)[e];
    }
    {
        float v;
        #define RED_(x) v = x; v += __shfl_xor_sync(~0u, v, 1); v += __shfl_xor_sync(~0u, v, 2); x = v;
        RED_(ls0) RED_(ls1) RED_(ea0) RED_(ea1) RED_(eb0) RED_(eb1)
        #undef RED_
        if (tg == 0) {
            sstp[0*128 + wg*32 + r0] = ls0;  sstp[0*128 + wg*32 + r1] = ls1;
            sstp[1*128 + wg*32 + r0] = ea0;  sstp[1*128 + wg*32 + r1] = ea1;
            sstp[2*128 + wg*32 + r0] = eb0;  sstp[2*128 + wg*32 + r1] = eb1;
        }
    }
    __syncthreads();
    if (tid < 32) {
        float l = 0.f, a = 0.f, c = 0.f;
        #pragma unroll
        for (int g = 0; g < 4; g++) {
            l += sstp[0*128 + g*32 + tid];
            a += sstp[1*128 + g*32 + tid];
            c += sstp[2*128 + g*32 + tid];
        }
        sst[tid] = l; sst[32+tid] = a; sst[64+tid] = c;
    }
    __syncthreads();

    // ---- finalize bins ----
    for (int e = tid; e < 32*REL_; e += 256) {
        int m = e / REL_, r = e - m*REL_;
        float invl = 1.f / sst[m];
        float v;
        if (r == 0)         v = sst[32+m]*invl;
        else if (r == 128)  v = sst[64+m]*invl;
        else                v = __expf(sbin[m*132+r])*invl;
        sbin[m*132+r] = v;
    }
    __syncthreads();

    // ---- final: y = yacc/l + bins @ erel_v ; store ----
    {
        const float inv0 = 1.f / sst[r0];
        const float inv1 = 1.f / sst[r1];
        const int dA = wg*8 + tg*2;
        const int dB = dA + 32;
        float o00 = yacc[0][0]*inv0, o01 = yacc[0][1]*inv0;
        float o02 = yacc[0][2]*inv1, o03 = yacc[0][3]*inv1;
        float o10 = yacc[1][0]*inv0, o11 = yacc[1][1]*inv0;
        float o12 = yacc[1][2]*inv1, o13 = yacc[1][3]*inv1;
        #pragma unroll 4
        for (int r = 0; r < REL_; r++) {
            float b0 = sbin[r0*132 + r];
            float b1 = sbin[r1*132 + r];
            float2 eA = *(const float2*)&serel[r*68 + dA];
            float2 eB = *(const float2*)&serel[r*68 + dB];
            o00 += b0*eA.x; o01 += b0*eA.y;
            o02 += b1*eA.x; o03 += b1*eA.y;
            o10 += b0*eB.x; o11 += b0*eB.y;
            o12 += b1*eB.x; o13 += b1*eB.y;
        }
        const size_t cb0 = (size_t)b*C_ + h*64;
        g_y[(cb0 + dA  )*T_ + i0 + r0] = o00;
        g_y[(cb0 + dA+1)*T_ + i0 + r0] = o01;
        g_y[(cb0 + dA  )*T_ + i0 + r1] = o02;
        g_y[(cb0 + dA+1)*T_ + i0 + r1] = o03;
        g_y[(cb0 + dB  )*T_ + i0 + r0] = o10;
        g_y[(cb0 + dB+1)*T_ + i0 + r0] = o11;
        g_y[(cb0 + dB  )*T_ + i0 + r1] = o12;
        g_y[(cb0 + dB+1)*T_ + i0 + r1] = o13;
    }
}

// =====================================================================
extern "C" void kernel_launch(void* const* d_in, const int* in_sizes, int n_in,
                              void* d_out, int out_size)
{
    const float* x     = (const float*)d_in[0];
    const float* xmask = (const float*)d_in[1];
    const float* Wq    = (const float*)d_in[2];
    const float* bq    = (const float*)d_in[3];
    const float* Wk    = (const float*)d_in[4];
    const float* bk    = (const float*)d_in[5];
    const float* Wv    = (const float*)d_in[6];
    const float* bv    = (const float*)d_in[7];
    const float* Wo    = (const float*)d_in[8];
    const float* bo    = (const float*)d_in[9];
    const float* erelk = (const float*)d_in[10];
    const float* erelv = (const float*)d_in[11];
    float* out = (float*)d_out;

    __nv_bfloat16 *pqh, *pql, *pkh, *pkl, *pvh, *pvl;
    float *py;
    cudaGetSymbolAddress((void**)&pqh, g_qhi);
    cudaGetSymbolAddress((void**)&pql, g_qlo);
    cudaGetSymbolAddress((void**)&pkh, g_khi);
    cudaGetSymbolAddress((void**)&pkl, g_klo);
    cudaGetSymbolAddress((void**)&pvh, g_vhi);
    cudaGetSymbolAddress((void**)&pvl, g_vlo);
    cudaGetSymbolAddress((void**)&py, g_y);

    cudaFuncSetAttribute(attn_kernel,
                         cudaFuncAttributeMaxDynamicSharedMemorySize, SMEM_BYTES);

    dim3 gg(128, 8), bb(256);
    proj_qk<<<gg, bb>>>(Wq, x, bq, pqh, pql);
    proj_qk<<<gg, bb>>>(Wk, x, bk, pkh, pkl);
    proj_v <<<gg, bb>>>(Wv, x, bv, pvh, pvl);

    attn_kernel<<<dim3(32, H_, B_), 256, SMEM_BYTES>>>(xmask, erelk, erelv);

    out_gemm<<<gg, bb>>>(Wo, py, bo, xmask, out);
}

// round 6
// speedup vs baseline: 2.9460x; 1.5337x over previous
#include <cuda_runtime.h>
#include <cuda_bf16.h>

#define B_ 8
#define C_ 512
#define T_ 1024
#define H_ 8
#define D_ 64
#define REL_ 129

// ---------------- scratch (no cudaMalloc allowed) ----------------
__device__ __nv_bfloat16 g_xthi[B_*T_*C_];    // x^T (B,T,C) hi
__device__ __nv_bfloat16 g_xtlo[B_*T_*C_];
__device__ __nv_bfloat16 g_whi[4*C_*C_];      // Wq,Wk,Wv,Wo hi
__device__ __nv_bfloat16 g_wlo[4*C_*C_];
__device__ __nv_bfloat16 g_qhi[B_*H_*T_*D_];  // (B,H,T,D)
__device__ __nv_bfloat16 g_qlo[B_*H_*T_*D_];
__device__ __nv_bfloat16 g_khi[B_*H_*T_*D_];
__device__ __nv_bfloat16 g_klo[B_*H_*T_*D_];
__device__ __nv_bfloat16 g_vhi[B_*H_*T_*D_];  // (B,H,D,T)
__device__ __nv_bfloat16 g_vlo[B_*H_*T_*D_];
__device__ __nv_bfloat16 g_ythi[B_*T_*C_];    // y^T (B,T,C)
__device__ __nv_bfloat16 g_ytlo[B_*T_*C_];

// ---------------- attn shared memory (byte offsets) ----------------
#define OFF_QHI   0
#define OFF_QLO   4608
#define OFF_KV    9216
#define OFF_PHI   46080
#define OFF_PLO   54784
#define OFF_SBIN  63488
#define OFF_SQR   80384
#define OFF_SMK   97280
#define OFF_SSTP  101376
#define OFF_SST   102912
#define SMEM_BYTES 103296

__device__ __forceinline__ unsigned pk2(__nv_bfloat16 a, __nv_bfloat16 b) {
    __nv_bfloat162 t = __halves2bfloat162(a, b);
    return *reinterpret_cast<unsigned*>(&t);
}
__device__ __forceinline__ void cv(float x, __nv_bfloat16& h, __nv_bfloat16& l) {
    h = __float2bfloat16(x);
    l = __float2bfloat16(x - __bfloat162float(h));
}
__device__ __forceinline__ unsigned su32(const void* p) {
    return (unsigned)__cvta_generic_to_shared(p);
}
__device__ __forceinline__ void cpasync16(unsigned s, const void* g) {
    asm volatile("cp.async.cg.shared.global [%0], [%1], 16;" :: "r"(s), "l"(g));
}
__device__ __forceinline__ void cp_commit_wait() {
    asm volatile("cp.async.commit_group;\n\tcp.async.wait_group 0;" ::: "memory");
}
__device__ __forceinline__ void ldsm4(unsigned& r0, unsigned& r1, unsigned& r2,
                                      unsigned& r3, unsigned addr) {
    asm volatile("ldmatrix.sync.aligned.m8n8.x4.shared.b16 {%0,%1,%2,%3}, [%4];"
                 : "=r"(r0), "=r"(r1), "=r"(r2), "=r"(r3) : "r"(addr));
}
__device__ __forceinline__ void mma16816(float* c, unsigned a0, unsigned a1,
                                         unsigned a2, unsigned a3,
                                         unsigned b0, unsigned b1) {
    asm volatile(
        "mma.sync.aligned.m16n8k16.row.col.f32.bf16.bf16.f32 "
        "{%0,%1,%2,%3}, {%4,%5,%6,%7}, {%8,%9}, {%0,%1,%2,%3};"
        : "+f"(c[0]), "+f"(c[1]), "+f"(c[2]), "+f"(c[3])
        : "r"(a0), "r"(a1), "r"(a2), "r"(a3), "r"(b0), "r"(b1));
}

// =====================================================================
// prep: x (B,C,T) fp32 -> xt (B,T,C) bf16 hi/lo  (32x32 smem transpose)
// =====================================================================
__global__ __launch_bounds__(256) void conv_x(const float* __restrict__ x)
{
    __shared__ float s[32][33];
    const int b = blockIdx.z, c0 = blockIdx.y*32, t0 = blockIdx.x*32;
    const int tx = threadIdx.x & 31, ty = threadIdx.x >> 5;
    #pragma unroll
    for (int r = 0; r < 4; r++) {
        int c = ty + r*8;
        s[c][tx] = x[((size_t)b*C_ + c0 + c)*T_ + t0 + tx];
    }
    __syncthreads();
    #pragma unroll
    for (int r = 0; r < 4; r++) {
        int t = ty + r*8;
        float v = s[tx][t];
        __nv_bfloat16 h, l;
        cv(v, h, l);
        size_t idx = ((size_t)b*T_ + t0 + t)*C_ + c0 + tx;
        g_xthi[idx] = h;
        g_xtlo[idx] = l;
    }
}

// prep: 4 weight matrices fp32 -> bf16 hi/lo
__global__ __launch_bounds__(256) void conv_w(
    const float* __restrict__ w0, const float* __restrict__ w1,
    const float* __restrict__ w2, const float* __restrict__ w3)
{
    const int g = blockIdx.y;
    const float* W = g==0 ? w0 : g==1 ? w1 : g==2 ? w2 : w3;
    int idx = blockIdx.x*256 + threadIdx.x;
    float v = W[idx];
    __nv_bfloat16 h, l;
    cv(v, h, l);
    g_whi[(size_t)g*C_*C_ + idx] = h;
    g_wlo[(size_t)g*C_*C_ + idx] = l;
}

// =====================================================================
// Fused QKV tensor GEMM: M = B*T (rows of xt), N = o (512), K = C.
// grid (64, 12): y = wsel*4 + o-block. CTA 128x128, warps 4(m)x2(n).
// =====================================================================
__global__ __launch_bounds__(256, 2) void proj_fused(
    const float* __restrict__ bq, const float* __restrict__ bk,
    const float* __restrict__ bv)
{
    __shared__ __align__(16) __nv_bfloat16 sA[2][128*40];
    __shared__ __align__(16) __nv_bfloat16 sB[2][128*40];

    const int tid = threadIdx.x, lane = tid & 31, w = tid >> 5;
    const int wm = w & 3, wn = w >> 2;
    const int lg = lane >> 2, tg = lane & 3;
    const int l7 = lane & 7, lh = (lane >> 3) & 1, lq = lane >> 4;

    const int ny = blockIdx.y;
    const int wsel = ny >> 2;
    const int o0 = (ny & 3) * 128;
    const int m0g = blockIdx.x * 128;
    const int b = m0g >> 10, t0 = m0g & 1023;

    const __nv_bfloat16* Ah = g_xthi;
    const __nv_bfloat16* Al = g_xtlo;
    const __nv_bfloat16* Bh = g_whi + (size_t)wsel*C_*C_;
    const __nv_bfloat16* Bl = g_wlo + (size_t)wsel*C_*C_;

    float acc[2][8][4] = {};

    const unsigned aHB = su32(sA[0]) + (wm*32 + lh*8 + l7)*80 + lq*16;
    const unsigned aLB = su32(sA[1]) + (wm*32 + lh*8 + l7)*80 + lq*16;
    const unsigned bHB = su32(sB[0]) + (wn*64 + lq*8 + l7)*80 + lh*16;
    const unsigned bLB = su32(sB[1]) + (wn*64 + lq*8 + l7)*80 + lh*16;

    for (int k0 = 0; k0 < C_; k0 += 32) {
        __syncthreads();
        #pragma unroll
        for (int r = 0; r < 4; r++) {
            int s = tid + r*256;
            int buf = s >> 9, rc = s & 511;
            int row = rc >> 2, c = rc & 3;
            unsigned off = row*80 + c*16;
            const __nv_bfloat16* asrc = (buf ? Al : Ah) + (size_t)(m0g+row)*C_ + k0 + c*8;
            const __nv_bfloat16* bsrc = (buf ? Bl : Bh) + (size_t)(o0+row)*C_ + k0 + c*8;
            cpasync16(su32(sA[buf]) + off, asrc);
            cpasync16(su32(sB[buf]) + off, bsrc);
        }
        cp_commit_wait();
        __syncthreads();

        #pragma unroll
        for (int ks = 0; ks < 2; ks++) {
            const unsigned ko = ks*32;
            unsigned aH[2][4], aL[2][4];
            #pragma unroll
            for (int mi = 0; mi < 2; mi++) {
                ldsm4(aH[mi][0],aH[mi][1],aH[mi][2],aH[mi][3], aHB + mi*16*80 + ko);
                ldsm4(aL[mi][0],aL[mi][1],aL[mi][2],aL[mi][3], aLB + mi*16*80 + ko);
            }
            #pragma unroll
            for (int nb = 0; nb < 4; nb++) {
                unsigned bH[4], bL[4];
                ldsm4(bH[0],bH[1],bH[2],bH[3], bHB + nb*16*80 + ko);
                ldsm4(bL[0],bL[1],bL[2],bL[3], bLB + nb*16*80 + ko);
                #pragma unroll
                for (int mi = 0; mi < 2; mi++) {
                    #pragma unroll
                    for (int t = 0; t < 2; t++) {
                        float* c = acc[mi][nb*2+t];
                        mma16816(c, aH[mi][0],aH[mi][1],aH[mi][2],aH[mi][3], bH[t*2],bH[t*2+1]);
                        mma16816(c, aH[mi][0],aH[mi][1],aH[mi][2],aH[mi][3], bL[t*2],bL[t*2+1]);
                        mma16816(c, aL[mi][0],aL[mi][1],aL[mi][2],aL[mi][3], bH[t*2],bH[t*2+1]);
                    }
                }
            }
        }
    }

    const float* bias = wsel==0 ? bq : (wsel==1 ? bk : bv);
    if (wsel < 2) {
        __nv_bfloat16* oh = wsel==0 ? g_qhi : g_khi;
        __nv_bfloat16* ol = wsel==0 ? g_qlo : g_klo;
        #pragma unroll
        for (int mi = 0; mi < 2; mi++) {
            int tr0 = t0 + wm*32 + mi*16 + lg;
            #pragma unroll
            for (int nj = 0; nj < 8; nj++) {
                int o = o0 + wn*64 + nj*8 + tg*2;
                float bi0 = bias[o], bi1 = bias[o+1];
                int hh = o >> 6, d = o & 63;
                size_t base = ((size_t)(b*H_+hh)*T_ + tr0)*D_ + d;
                __nv_bfloat16 h0,l0,h1,l1;
                cv(acc[mi][nj][0]+bi0, h0,l0); cv(acc[mi][nj][1]+bi1, h1,l1);
                *(unsigned*)&oh[base] = pk2(h0,h1);
                *(unsigned*)&ol[base] = pk2(l0,l1);
                cv(acc[mi][nj][2]+bi0, h0,l0); cv(acc[mi][nj][3]+bi1, h1,l1);
                *(unsigned*)&oh[base + 8*D_] = pk2(h0,h1);
                *(unsigned*)&ol[base + 8*D_] = pk2(l0,l1);
            }
        }
    } else {
        #pragma unroll
        for (int mi = 0; mi < 2; mi++) {
            int tr0 = t0 + wm*32 + mi*16 + lg;
            #pragma unroll
            for (int nj = 0; nj < 8; nj++) {
                int o = o0 + wn*64 + nj*8 + tg*2;
                float bi0 = bias[o], bi1 = bias[o+1];
                int hh = o >> 6, d = o & 63;
                size_t base = ((size_t)(b*H_+hh)*D_ + d)*T_ + tr0;
                __nv_bfloat16 h0,l0;
                cv(acc[mi][nj][0]+bi0, h0,l0); g_vhi[base] = h0;      g_vlo[base] = l0;
                cv(acc[mi][nj][1]+bi1, h0,l0); g_vhi[base+T_] = h0;   g_vlo[base+T_] = l0;
                cv(acc[mi][nj][2]+bi0, h0,l0); g_vhi[base+8] = h0;    g_vlo[base+8] = l0;
                cv(acc[mi][nj][3]+bi1, h0,l0); g_vhi[base+T_+8] = h0; g_vlo[base+T_+8] = l0;
            }
        }
    }
}

// =====================================================================
// Output projection tensor GEMM: M = o (512, rows of Wo), N = B*T (yt rows).
// grid (4, 64). out fp32 (B,C,T) with bias + mask.
// =====================================================================
__global__ __launch_bounds__(256, 2) void outp_gemm(
    const float* __restrict__ bo, const float* __restrict__ mask,
    float* __restrict__ out)
{
    __shared__ __align__(16) __nv_bfloat16 sA[2][128*40];
    __shared__ __align__(16) __nv_bfloat16 sB[2][128*40];

    const int tid = threadIdx.x, lane = tid & 31, w = tid >> 5;
    const int wm = w & 3, wn = w >> 2;
    const int lg = lane >> 2, tg = lane & 3;
    const int l7 = lane & 7, lh = (lane >> 3) & 1, lq = lane >> 4;

    const int o0 = blockIdx.x * 128;
    const int n0g = blockIdx.y * 128;
    const int b = n0g >> 10, t0 = n0g & 1023;

    const __nv_bfloat16* Ah = g_whi + (size_t)3*C_*C_;
    const __nv_bfloat16* Al = g_wlo + (size_t)3*C_*C_;

    float acc[2][8][4] = {};

    const unsigned aHB = su32(sA[0]) + (wm*32 + lh*8 + l7)*80 + lq*16;
    const unsigned aLB = su32(sA[1]) + (wm*32 + lh*8 + l7)*80 + lq*16;
    const unsigned bHB = su32(sB[0]) + (wn*64 + lq*8 + l7)*80 + lh*16;
    const unsigned bLB = su32(sB[1]) + (wn*64 + lq*8 + l7)*80 + lh*16;

    for (int k0 = 0; k0 < C_; k0 += 32) {
        __syncthreads();
        #pragma unroll
        for (int r = 0; r < 4; r++) {
            int s = tid + r*256;
            int buf = s >> 9, rc = s & 511;
            int row = rc >> 2, c = rc & 3;
            unsigned off = row*80 + c*16;
            const __nv_bfloat16* asrc = (buf ? Al : Ah) + (size_t)(o0+row)*C_ + k0 + c*8;
            const __nv_bfloat16* bsrc = (buf ? g_ytlo : g_ythi) + (size_t)(n0g+row)*C_ + k0 + c*8;
            cpasync16(su32(sA[buf]) + off, asrc);
            cpasync16(su32(sB[buf]) + off, bsrc);
        }
        cp_commit_wait();
        __syncthreads();

        #pragma unroll
        for (int ks = 0; ks < 2; ks++) {
            const unsigned ko = ks*32;
            unsigned aH[2][4], aL[2][4];
            #pragma unroll
            for (int mi = 0; mi < 2; mi++) {
                ldsm4(aH[mi][0],aH[mi][1],aH[mi][2],aH[mi][3], aHB + mi*16*80 + ko);
                ldsm4(aL[mi][0],aL[mi][1],aL[mi][2],aL[mi][3], aLB + mi*16*80 + ko);
            }
            #pragma unroll
            for (int nb = 0; nb < 4; nb++) {
                unsigned bH[4], bL[4];
                ldsm4(bH[0],bH[1],bH[2],bH[3], bHB + nb*16*80 + ko);
                ldsm4(bL[0],bL[1],bL[2],bL[3], bLB + nb*16*80 + ko);
                #pragma unroll
                for (int mi = 0; mi < 2; mi++) {
                    #pragma unroll
                    for (int t = 0; t < 2; t++) {
                        float* c = acc[mi][nb*2+t];
                        mma16816(c, aH[mi][0],aH[mi][1],aH[mi][2],aH[mi][3], bH[t*2],bH[t*2+1]);
                        mma16816(c, aH[mi][0],aH[mi][1],aH[mi][2],aH[mi][3], bL[t*2],bL[t*2+1]);
                        mma16816(c, aL[mi][0],aL[mi][1],aL[mi][2],aL[mi][3], bH[t*2],bH[t*2+1]);
                    }
                }
            }
        }
    }

    #pragma unroll
    for (int mi = 0; mi < 2; mi++) {
        int o = o0 + wm*32 + mi*16 + lg;
        float bi0 = bo[o], bi1 = bo[o+8];
        #pragma unroll
        for (int nj = 0; nj < 8; nj++) {
            int t = t0 + wn*64 + nj*8 + tg*2;
            float m0v = mask[(size_t)b*T_ + t];
            float m1v = mask[(size_t)b*T_ + t + 1];
            float2 v0 = make_float2((acc[mi][nj][0]+bi0)*m0v, (acc[mi][nj][1]+bi0)*m1v);
            float2 v1 = make_float2((acc[mi][nj][2]+bi1)*m0v, (acc[mi][nj][3]+bi1)*m1v);
            *(float2*)&out[((size_t)b*C_ + o)*T_ + t]     = v0;
            *(float2*)&out[((size_t)b*C_ + o + 8)*T_ + t] = v1;
        }
    }
}

// =====================================================================
// Fused attention (unchanged core; final store now bf16 hi/lo -> yt)
// =====================================================================
__global__ __launch_bounds__(256, 2) void attn_kernel(
    const float* __restrict__ mask,
    const float* __restrict__ erel_k,
    const float* __restrict__ erel_v)
{
    extern __shared__ unsigned char smem[];
    __nv_bfloat16* qhi = (__nv_bfloat16*)(smem + OFF_QHI);
    __nv_bfloat16* qlo = (__nv_bfloat16*)(smem + OFF_QLO);
    __nv_bfloat16* khi = (__nv_bfloat16*)(smem + OFF_KV);
    __nv_bfloat16* klo = (__nv_bfloat16*)(smem + OFF_KV + 18432);
    __nv_bfloat16* vhi = (__nv_bfloat16*)(smem + OFF_KV);
    __nv_bfloat16* vlo = (__nv_bfloat16*)(smem + OFF_KV + 17408);
    float*         serel = (float*)(smem + OFF_KV);
    __nv_bfloat16* phi = (__nv_bfloat16*)(smem + OFF_PHI);
    __nv_bfloat16* plo = (__nv_bfloat16*)(smem + OFF_PLO);
    float* sbin = (float*)(smem + OFF_SBIN);
    float* sqr  = (float*)(smem + OFF_SQR);
    float* smk  = (float*)(smem + OFF_SMK);
    float* sstp = (float*)(smem + OFF_SSTP);
    float* sst  = (float*)(smem + OFF_SST);

    const int tid  = threadIdx.x;
    const int lane = tid & 31;
    const int w    = tid >> 5;
    const int mt   = w & 1;
    const int wg   = w >> 1;
    const int lg   = lane >> 2;
    const int tg   = lane & 3;
    const int r0   = mt*16 + lg;
    const int r1   = r0 + 8;
    const int l7   = lane & 7;
    const int lh   = (lane >> 3) & 1;
    const int lq   = lane >> 4;

    const int i0 = blockIdx.x * 32;
    const int h  = blockIdx.y;
    const int b  = blockIdx.z;
    const size_t headbase = (size_t)(b*H_+h)*T_*D_;

    #pragma unroll
    for (int r = 0; r < 2; r++) {
        int e = tid + r*256;
        int bufi = e >> 8;
        int rc = e & 255;
        int m = rc >> 3, c = rc & 7;
        unsigned dst = su32(bufi ? qlo : qhi) + m*144 + c*16;
        const unsigned char* src =
            (const unsigned char*)(bufi ? g_qlo : g_qhi)
            + (headbase + (size_t)(i0+m)*D_)*2 + c*16;
        cpasync16(dst, src);
    }
    for (int e = tid; e < REL_*16; e += 256) {
        int r = e >> 4, d4 = (e & 15) << 2;
        *(float4*)&serel[r*68 + d4] = ((const float4*)erel_k)[e];
    }
    for (int e = tid; e < T_/4; e += 256)
        ((float4*)smk)[e] = ((const float4*)(mask + (size_t)b*T_))[e];
    for (int e = tid; e < 32*132; e += 256)
        sbin[e] = -1e9f;
    cp_commit_wait();
    __syncthreads();

    for (int idx = tid; idx < 32*REL_; idx += 256) {
        int m = idx / REL_, r = idx - m*REL_;
        const __nv_bfloat162* qh = (const __nv_bfloat162*)&qhi[m*72];
        const __nv_bfloat162* ql = (const __nv_bfloat162*)&qlo[m*72];
        const float2* e2 = (const float2*)&serel[r*68];
        float s = 0.f;
        #pragma unroll
        for (int i = 0; i < 32; i++) {
            __nv_bfloat162 hh = qh[i], ll = ql[i];
            float2 ee = e2[i];
            s += (__bfloat162float(hh.x)+__bfloat162float(ll.x))*ee.x
               + (__bfloat162float(hh.y)+__bfloat162float(ll.y))*ee.y;
        }
        sqr[m*132 + r] = s;
    }

    const float scale = 0.125f;
    float yacc[2][4] = {};
    float ls0=0.f, ls1=0.f, ea0=0.f, ea1=0.f, eb0=0.f, eb1=0.f;

    const unsigned qhiA = su32(qhi) + (unsigned)((mt*16 + lh*8 + l7)*144 + lq*16);
    const unsigned qloA = su32(qlo) + (unsigned)((mt*16 + lh*8 + l7)*144 + lq*16);
    const unsigned khiB0 = su32(khi) + (unsigned)((wg*32 + lq*8 + l7)*144 + lh*16);
    const unsigned kloB0 = su32(klo) + (unsigned)((wg*32 + lq*8 + l7)*144 + lh*16);
    const unsigned phiA = su32(phi) + (unsigned)((mt*16 + lh*8 + l7)*272 + lq*16);
    const unsigned ploA = su32(plo) + (unsigned)((mt*16 + lh*8 + l7)*272 + lq*16);
    const unsigned vhiB = su32(vhi) + (unsigned)((wg*8 + lq*32 + l7)*272 + lh*16);
    const unsigned vloB = su32(vlo) + (unsigned)((wg*8 + lq*32 + l7)*272 + lh*16);

    for (int kt = 0; kt < 8; kt++) {
        const int j0g = kt * 128;
        __syncthreads();
        #pragma unroll
        for (int r = 0; r < 8; r++) {
            int e = tid + r*256;
            int bufi = e >> 10;
            int rc = e & 1023;
            int j = rc >> 3, c = rc & 7;
            unsigned dst = su32(bufi ? klo : khi) + j*144 + c*16;
            const unsigned char* src =
                (const unsigned char*)(bufi ? g_klo : g_khi)
                + (headbase + (size_t)(j0g+j)*D_)*2 + c*16;
            cpasync16(dst, src);
        }
        cp_commit_wait();
        __syncthreads();

        float sacc[4][4] = {};
        #pragma unroll
        for (int ks = 0; ks < 4; ks++) {
            const unsigned ko = ks*32;
            unsigned aH0,aH1,aH2,aH3, aL0,aL1,aL2,aL3;
            ldsm4(aH0,aH1,aH2,aH3, qhiA + ko);
            ldsm4(aL0,aL1,aL2,aL3, qloA + ko);
            unsigned bH[8], bL[8];
            ldsm4(bH[0],bH[1],bH[2],bH[3], khiB0 + ko);
            ldsm4(bH[4],bH[5],bH[6],bH[7], khiB0 + 16*144 + ko);
            ldsm4(bL[0],bL[1],bL[2],bL[3], kloB0 + ko);
            ldsm4(bL[4],bL[5],bL[6],bL[7], kloB0 + 16*144 + ko);
            #pragma unroll
            for (int t = 0; t < 4; t++) {
                unsigned b0h = bH[t*2], b1h = bH[t*2+1];
                unsigned b0l = bL[t*2], b1l = bL[t*2+1];
                mma16816(sacc[t], aH0,aH1,aH2,aH3, b0h,b1h);
                mma16816(sacc[t], aH0,aH1,aH2,aH3, b0l,b1l);
                mma16816(sacc[t], aL0,aL1,aL2,aL3, b0h,b1h);
            }
        }

        #pragma unroll
        for (int t = 0; t < 4; t++) {
            const int cb = wg*32 + t*8 + tg*2;
            #pragma unroll
            for (int ii = 0; ii < 2; ii++) {
                const int rr = ii ? r1 : r0;
                const int gi = i0 + rr;
                float ev[2];
                #pragma unroll
                for (int jj = 0; jj < 2; jj++) {
                    int gj = j0g + cb + jj;
                    int rel = gj - gi;
                    int relc = rel < -64 ? -64 : (rel > 64 ? 64 : rel);
                    float s = sacc[t][ii*2+jj]*scale + sqr[rr*132 + relc + 64];
                    if (smk[gj] <= 0.f) s = -1e9f;
                    float e = __expf(s);
                    if (ii == 0) ls0 += e; else ls1 += e;
                    if (rel <= -64)      { if (ii == 0) ea0 += e; else ea1 += e; }
                    else if (rel >= 64)  { if (ii == 0) eb0 += e; else eb1 += e; }
                    else                 sbin[rr*132 + rel + 64] = s;
                    ev[jj] = e;
                }
                __nv_bfloat16 eh0,el0,eh1,el1;
                cv(ev[0],eh0,el0); cv(ev[1],eh1,el1);
                *(unsigned*)&phi[rr*136 + cb] = pk2(eh0,eh1);
                *(unsigned*)&plo[rr*136 + cb] = pk2(el0,el1);
            }
        }
        __syncthreads();

        #pragma unroll
        for (int r = 0; r < 8; r++) {
            int e = tid + r*256;
            int bufi = e >> 10;
            int rc = e & 1023;
            int d = rc >> 4, c = rc & 15;
            unsigned dst = su32(bufi ? vlo : vhi) + d*272 + c*16;
            const unsigned char* src =
                (const unsigned char*)(bufi ? g_vlo : g_vhi)
                + (headbase + (size_t)d*T_ + j0g)*2 + c*16;
            cpasync16(dst, src);
        }
        cp_commit_wait();
        __syncthreads();

        #pragma unroll
        for (int ks = 0; ks < 8; ks++) {
            const unsigned ko = ks*32;
            unsigned aH0,aH1,aH2,aH3, aL0,aL1,aL2,aL3;
            ldsm4(aH0,aH1,aH2,aH3, phiA + ko);
            ldsm4(aL0,aL1,aL2,aL3, ploA + ko);
            unsigned bH[4], bL[4];
            ldsm4(bH[0],bH[1],bH[2],bH[3], vhiB + ko);
            ldsm4(bL[0],bL[1],bL[2],bL[3], vloB + ko);
            #pragma unroll
            for (int ti = 0; ti < 2; ti++) {
                unsigned b0h = bH[ti*2], b1h = bH[ti*2+1];
                unsigned b0l = bL[ti*2], b1l = bL[ti*2+1];
                mma16816(yacc[ti], aH0,aH1,aH2,aH3, b0h,b1h);
                mma16816(yacc[ti], aH0,aH1,aH2,aH3, b0l,b1l);
                mma16816(yacc[ti], aL0,aL1,aL2,aL3, b0h,b1h);
            }
        }
    }
    __syncthreads();

    for (int e = tid; e < REL_*16; e += 256) {
        int r = e >> 4, d4 = (e & 15) << 2;
        *(float4*)&serel[r*68 + d4] = ((const float4*)erel_v)[e];
    }
    {
        float v;
        #define RED_(x) v = x; v += __shfl_xor_sync(~0u, v, 1); v += __shfl_xor_sync(~0u, v, 2); x = v;
        RED_(ls0) RED_(ls1) RED_(ea0) RED_(ea1) RED_(eb0) RED_(eb1)
        #undef RED_
        if (tg == 0) {
            sstp[0*128 + wg*32 + r0] = ls0;  sstp[0*128 + wg*32 + r1] = ls1;
            sstp[1*128 + wg*32 + r0] = ea0;  sstp[1*128 + wg*32 + r1] = ea1;
            sstp[2*128 + wg*32 + r0] = eb0;  sstp[2*128 + wg*32 + r1] = eb1;
        }
    }
    __syncthreads();
    if (tid < 32) {
        float l = 0.f, a = 0.f, c = 0.f;
        #pragma unroll
        for (int g = 0; g < 4; g++) {
            l += sstp[0*128 + g*32 + tid];
            a += sstp[1*128 + g*32 + tid];
            c += sstp[2*128 + g*32 + tid];
        }
        sst[tid] = l; sst[32+tid] = a; sst[64+tid] = c;
    }
    __syncthreads();

    for (int e = tid; e < 32*REL_; e += 256) {
        int m = e / REL_, r = e - m*REL_;
        float invl = 1.f / sst[m];
        float v;
        if (r == 0)         v = sst[32+m]*invl;
        else if (r == 128)  v = sst[64+m]*invl;
        else                v = __expf(sbin[m*132+r])*invl;
        sbin[m*132+r] = v;
    }
    __syncthreads();

    {
        const float inv0 = 1.f / sst[r0];
        const float inv1 = 1.f / sst[r1];
        const int dA = wg*8 + tg*2;
        const int dB = dA + 32;
        float o00 = yacc[0][0]*inv0, o01 = yacc[0][1]*inv0;
        float o02 = yacc[0][2]*inv1, o03 = yacc[0][3]*inv1;
        float o10 = yacc[1][0]*inv0, o11 = yacc[1][1]*inv0;
        float o12 = yacc[1][2]*inv1, o13 = yacc[1][3]*inv1;
        #pragma unroll 4
        for (int r = 0; r < REL_; r++) {
            float b0 = sbin[r0*132 + r];
            float b1 = sbin[r1*132 + r];
            float2 eA = *(const float2*)&serel[r*68 + dA];
            float2 eB = *(const float2*)&serel[r*68 + dB];
            o00 += b0*eA.x; o01 += b0*eA.y;
            o02 += b1*eA.x; o03 += b1*eA.y;
            o10 += b0*eB.x; o11 += b0*eB.y;
            o12 += b1*eB.x; o13 += b1*eB.y;
        }
        // write yt (B,T,C) bf16 hi/lo
        const int cbase = h*64;
        size_t tb0 = ((size_t)b*T_ + i0 + r0)*C_;
        size_t tb1 = ((size_t)b*T_ + i0 + r1)*C_;
        __nv_bfloat16 h0,l0,h1,l1;
        cv(o00,h0,l0); cv(o01,h1,l1);
        *(unsigned*)&g_ythi[tb0 + cbase + dA] = pk2(h0,h1);
        *(unsigned*)&g_ytlo[tb0 + cbase + dA] = pk2(l0,l1);
        cv(o02,h0,l0); cv(o03,h1,l1);
        *(unsigned*)&g_ythi[tb1 + cbase + dA] = pk2(h0,h1);
        *(unsigned*)&g_ytlo[tb1 + cbase + dA] = pk2(l0,l1);
        cv(o10,h0,l0); cv(o11,h1,l1);
        *(unsigned*)&g_ythi[tb0 + cbase + dB] = pk2(h0,h1);
        *(unsigned*)&g_ytlo[tb0 + cbase + dB] = pk2(l0,l1);
        cv(o12,h0,l0); cv(o13,h1,l1);
        *(unsigned*)&g_ythi[tb1 + cbase + dB] = pk2(h0,h1);
        *(unsigned*)&g_ytlo[tb1 + cbase + dB] = pk2(l0,l1);
    }
}

// =====================================================================
extern "C" void kernel_launch(void* const* d_in, const int* in_sizes, int n_in,
                              void* d_out, int out_size)
{
    const float* x     = (const float*)d_in[0];
    const float* xmask = (const float*)d_in[1];
    const float* Wq    = (const float*)d_in[2];
    const float* bq    = (const float*)d_in[3];
    const float* Wk    = (const float*)d_in[4];
    const float* bk    = (const float*)d_in[5];
    const float* Wv    = (const float*)d_in[6];
    const float* bv    = (const float*)d_in[7];
    const float* Wo    = (const float*)d_in[8];
    const float* bo    = (const float*)d_in[9];
    const float* erelk = (const float*)d_in[10];
    const float* erelv = (const float*)d_in[11];
    float* out = (float*)d_out;

    cudaFuncSetAttribute(attn_kernel,
                         cudaFuncAttributeMaxDynamicSharedMemorySize, SMEM_BYTES);

    conv_x<<<dim3(T_/32, C_/32, B_), 256>>>(x);
    conv_w<<<dim3(C_*C_/256, 4), 256>>>(Wq, Wk, Wv, Wo);

    proj_fused<<<dim3(64, 12), 256>>>(bq, bk, bv);

    attn_kernel<<<dim3(32, H_, B_), 256, SMEM_BYTES>>>(xmask, erelk, erelv);

    outp_gemm<<<dim3(4, 64), 256>>>(bo, xmask, out);
}

// round 7
// speedup vs baseline: 2.9674x; 1.0073x over previous
#include <cuda_runtime.h>
#include <cuda_bf16.h>

#define B_ 8
#define C_ 512
#define T_ 1024
#define H_ 8
#define D_ 64
#define REL_ 129

// ---------------- scratch (no cudaMalloc allowed) ----------------
__device__ __nv_bfloat16 g_xthi[B_*T_*C_];    // x^T (B,T,C) hi
__device__ __nv_bfloat16 g_xtlo[B_*T_*C_];
__device__ __nv_bfloat16 g_whi[4*C_*C_];      // Wq,Wk,Wv,Wo hi
__device__ __nv_bfloat16 g_wlo[4*C_*C_];
__device__ __nv_bfloat16 g_qhi[B_*H_*T_*D_];  // (B,H,T,D)
__device__ __nv_bfloat16 g_qlo[B_*H_*T_*D_];
__device__ __nv_bfloat16 g_khi[B_*H_*T_*D_];
__device__ __nv_bfloat16 g_klo[B_*H_*T_*D_];
__device__ __nv_bfloat16 g_vhi[B_*H_*T_*D_];  // (B,H,D,T)
__device__ __nv_bfloat16 g_vlo[B_*H_*T_*D_];
__device__ __nv_bfloat16 g_ythi[B_*T_*C_];    // y^T (B,T,C)
__device__ __nv_bfloat16 g_ytlo[B_*T_*C_];

// ---------------- attn shared memory (byte offsets), 64-query CTA ----------------
#define OFF_QHI   0          // bf16 [64][72]  9216
#define OFF_QLO   9216       // 9216
#define OFF_K     18432      // khi[128][72] 18432 + klo 18432 = 36864
#define OFF_V     55296      // vhi[64][136] 17408 + vlo 17408 = 34816 | erel_v fp32 [129][66]
#define OFF_P     90112      // phi[64][136] 17408 + plo 17408 = 34816 | erel_k fp32 [129][66]
#define OFF_SBIN  124928     // fp32 [64][132] 33792
#define OFF_SQR   158720     // fp32 [64][132] 33792
#define OFF_SMK   192512     // fp32 [1024]     4096
#define OFF_SSTP  196608     // fp32 [3][4][64] 3072
#define OFF_SST   199680     // fp32 [3][64]     768
#define SMEM_BYTES 200448

__device__ __forceinline__ unsigned pk2(__nv_bfloat16 a, __nv_bfloat16 b) {
    __nv_bfloat162 t = __halves2bfloat162(a, b);
    return *reinterpret_cast<unsigned*>(&t);
}
__device__ __forceinline__ void cv(float x, __nv_bfloat16& h, __nv_bfloat16& l) {
    h = __float2bfloat16(x);
    l = __float2bfloat16(x - __bfloat162float(h));
}
__device__ __forceinline__ unsigned su32(const void* p) {
    return (unsigned)__cvta_generic_to_shared(p);
}
__device__ __forceinline__ void cpasync16(unsigned s, const void* g) {
    asm volatile("cp.async.cg.shared.global [%0], [%1], 16;" :: "r"(s), "l"(g));
}
__device__ __forceinline__ void cp_commit() {
    asm volatile("cp.async.commit_group;" ::: "memory");
}
__device__ __forceinline__ void cp_wait0() {
    asm volatile("cp.async.wait_group 0;" ::: "memory");
}
__device__ __forceinline__ void cp_wait1() {
    asm volatile("cp.async.wait_group 1;" ::: "memory");
}
__device__ __forceinline__ void ldsm4(unsigned& r0, unsigned& r1, unsigned& r2,
                                      unsigned& r3, unsigned addr) {
    asm volatile("ldmatrix.sync.aligned.m8n8.x4.shared.b16 {%0,%1,%2,%3}, [%4];"
                 : "=r"(r0), "=r"(r1), "=r"(r2), "=r"(r3) : "r"(addr));
}
__device__ __forceinline__ void mma16816(float* c, unsigned a0, unsigned a1,
                                         unsigned a2, unsigned a3,
                                         unsigned b0, unsigned b1) {
    asm volatile(
        "mma.sync.aligned.m16n8k16.row.col.f32.bf16.bf16.f32 "
        "{%0,%1,%2,%3}, {%4,%5,%6,%7}, {%8,%9}, {%0,%1,%2,%3};"
        : "+f"(c[0]), "+f"(c[1]), "+f"(c[2]), "+f"(c[3])
        : "r"(a0), "r"(a1), "r"(a2), "r"(a3), "r"(b0), "r"(b1));
}

// =====================================================================
// prep kernels (unchanged)
// =====================================================================
__global__ __launch_bounds__(256) void conv_x(const float* __restrict__ x)
{
    __shared__ float s[32][33];
    const int b = blockIdx.z, c0 = blockIdx.y*32, t0 = blockIdx.x*32;
    const int tx = threadIdx.x & 31, ty = threadIdx.x >> 5;
    #pragma unroll
    for (int r = 0; r < 4; r++) {
        int c = ty + r*8;
        s[c][tx] = x[((size_t)b*C_ + c0 + c)*T_ + t0 + tx];
    }
    __syncthreads();
    #pragma unroll
    for (int r = 0; r < 4; r++) {
        int t = ty + r*8;
        float v = s[tx][t];
        __nv_bfloat16 h, l;
        cv(v, h, l);
        size_t idx = ((size_t)b*T_ + t0 + t)*C_ + c0 + tx;
        g_xthi[idx] = h;
        g_xtlo[idx] = l;
    }
}

__global__ __launch_bounds__(256) void conv_w(
    const float* __restrict__ w0, const float* __restrict__ w1,
    const float* __restrict__ w2, const float* __restrict__ w3)
{
    const int g = blockIdx.y;
    const float* W = g==0 ? w0 : g==1 ? w1 : g==2 ? w2 : w3;
    int idx = blockIdx.x*256 + threadIdx.x;
    float v = W[idx];
    __nv_bfloat16 h, l;
    cv(v, h, l);
    g_whi[(size_t)g*C_*C_ + idx] = h;
    g_wlo[(size_t)g*C_*C_ + idx] = l;
}

// =====================================================================
// Fused QKV tensor GEMM (unchanged)
// =====================================================================
__global__ __launch_bounds__(256, 2) void proj_fused(
    const float* __restrict__ bq, const float* __restrict__ bk,
    const float* __restrict__ bv)
{
    __shared__ __align__(16) __nv_bfloat16 sA[2][128*40];
    __shared__ __align__(16) __nv_bfloat16 sB[2][128*40];

    const int tid = threadIdx.x, lane = tid & 31, w = tid >> 5;
    const int wm = w & 3, wn = w >> 2;
    const int lg = lane >> 2, tg = lane & 3;
    const int l7 = lane & 7, lh = (lane >> 3) & 1, lq = lane >> 4;

    const int ny = blockIdx.y;
    const int wsel = ny >> 2;
    const int o0 = (ny & 3) * 128;
    const int m0g = blockIdx.x * 128;
    const int b = m0g >> 10, t0 = m0g & 1023;

    const __nv_bfloat16* Ah = g_xthi;
    const __nv_bfloat16* Al = g_xtlo;
    const __nv_bfloat16* Bh = g_whi + (size_t)wsel*C_*C_;
    const __nv_bfloat16* Bl = g_wlo + (size_t)wsel*C_*C_;

    float acc[2][8][4] = {};

    const unsigned aHB = su32(sA[0]) + (wm*32 + lh*8 + l7)*80 + lq*16;
    const unsigned aLB = su32(sA[1]) + (wm*32 + lh*8 + l7)*80 + lq*16;
    const unsigned bHB = su32(sB[0]) + (wn*64 + lq*8 + l7)*80 + lh*16;
    const unsigned bLB = su32(sB[1]) + (wn*64 + lq*8 + l7)*80 + lh*16;

    for (int k0 = 0; k0 < C_; k0 += 32) {
        __syncthreads();
        #pragma unroll
        for (int r = 0; r < 4; r++) {
            int s = tid + r*256;
            int buf = s >> 9, rc = s & 511;
            int row = rc >> 2, c = rc & 3;
            unsigned off = row*80 + c*16;
            const __nv_bfloat16* asrc = (buf ? Al : Ah) + (size_t)(m0g+row)*C_ + k0 + c*8;
            const __nv_bfloat16* bsrc = (buf ? Bl : Bh) + (size_t)(o0+row)*C_ + k0 + c*8;
            cpasync16(su32(sA[buf]) + off, asrc);
            cpasync16(su32(sB[buf]) + off, bsrc);
        }
        cp_commit(); cp_wait0();
        __syncthreads();

        #pragma unroll
        for (int ks = 0; ks < 2; ks++) {
            const unsigned ko = ks*32;
            unsigned aH[2][4], aL[2][4];
            #pragma unroll
            for (int mi = 0; mi < 2; mi++) {
                ldsm4(aH[mi][0],aH[mi][1],aH[mi][2],aH[mi][3], aHB + mi*16*80 + ko);
                ldsm4(aL[mi][0],aL[mi][1],aL[mi][2],aL[mi][3], aLB + mi*16*80 + ko);
            }
            #pragma unroll
            for (int nb = 0; nb < 4; nb++) {
                unsigned bH[4], bL[4];
                ldsm4(bH[0],bH[1],bH[2],bH[3], bHB + nb*16*80 + ko);
                ldsm4(bL[0],bL[1],bL[2],bL[3], bLB + nb*16*80 + ko);
                #pragma unroll
                for (int mi = 0; mi < 2; mi++) {
                    #pragma unroll
                    for (int t = 0; t < 2; t++) {
                        float* c = acc[mi][nb*2+t];
                        mma16816(c, aH[mi][0],aH[mi][1],aH[mi][2],aH[mi][3], bH[t*2],bH[t*2+1]);
                        mma16816(c, aH[mi][0],aH[mi][1],aH[mi][2],aH[mi][3], bL[t*2],bL[t*2+1]);
                        mma16816(c, aL[mi][0],aL[mi][1],aL[mi][2],aL[mi][3], bH[t*2],bH[t*2+1]);
                    }
                }
            }
        }
    }

    const float* bias = wsel==0 ? bq : (wsel==1 ? bk : bv);
    if (wsel < 2) {
        __nv_bfloat16* oh = wsel==0 ? g_qhi : g_khi;
        __nv_bfloat16* ol = wsel==0 ? g_qlo : g_klo;
        #pragma unroll
        for (int mi = 0; mi < 2; mi++) {
            int tr0 = t0 + wm*32 + mi*16 + lg;
            #pragma unroll
            for (int nj = 0; nj < 8; nj++) {
                int o = o0 + wn*64 + nj*8 + tg*2;
                float bi0 = bias[o], bi1 = bias[o+1];
                int hh = o >> 6, d = o & 63;
                size_t base = ((size_t)(b*H_+hh)*T_ + tr0)*D_ + d;
                __nv_bfloat16 h0,l0,h1,l1;
                cv(acc[mi][nj][0]+bi0, h0,l0); cv(acc[mi][nj][1]+bi1, h1,l1);
                *(unsigned*)&oh[base] = pk2(h0,h1);
                *(unsigned*)&ol[base] = pk2(l0,l1);
                cv(acc[mi][nj][2]+bi0, h0,l0); cv(acc[mi][nj][3]+bi1, h1,l1);
                *(unsigned*)&oh[base + 8*D_] = pk2(h0,h1);
                *(unsigned*)&ol[base + 8*D_] = pk2(l0,l1);
            }
        }
    } else {
        #pragma unroll
        for (int mi = 0; mi < 2; mi++) {
            int tr0 = t0 + wm*32 + mi*16 + lg;
            #pragma unroll
            for (int nj = 0; nj < 8; nj++) {
                int o = o0 + wn*64 + nj*8 + tg*2;
                float bi0 = bias[o], bi1 = bias[o+1];
                int hh = o >> 6, d = o & 63;
                size_t base = ((size_t)(b*H_+hh)*D_ + d)*T_ + tr0;
                __nv_bfloat16 h0,l0;
                cv(acc[mi][nj][0]+bi0, h0,l0); g_vhi[base] = h0;      g_vlo[base] = l0;
                cv(acc[mi][nj][1]+bi1, h0,l0); g_vhi[base+T_] = h0;   g_vlo[base+T_] = l0;
                cv(acc[mi][nj][2]+bi0, h0,l0); g_vhi[base+8] = h0;    g_vlo[base+8] = l0;
                cv(acc[mi][nj][3]+bi1, h0,l0); g_vhi[base+T_+8] = h0; g_vlo[base+T_+8] = l0;
            }
        }
    }
}

// =====================================================================
// Output projection tensor GEMM (unchanged)
// =====================================================================
__global__ __launch_bounds__(256, 2) void outp_gemm(
    const float* __restrict__ bo, const float* __restrict__ mask,
    float* __restrict__ out)
{
    __shared__ __align__(16) __nv_bfloat16 sA[2][128*40];
    __shared__ __align__(16) __nv_bfloat16 sB[2][128*40];

    const int tid = threadIdx.x, lane = tid & 31, w = tid >> 5;
    const int wm = w & 3, wn = w >> 2;
    const int lg = lane >> 2, tg = lane & 3;
    const int l7 = lane & 7, lh = (lane >> 3) & 1, lq = lane >> 4;

    const int o0 = blockIdx.x * 128;
    const int n0g = blockIdx.y * 128;
    const int b = n0g >> 10, t0 = n0g & 1023;

    const __nv_bfloat16* Ah = g_whi + (size_t)3*C_*C_;
    const __nv_bfloat16* Al = g_wlo + (size_t)3*C_*C_;

    float acc[2][8][4] = {};

    const unsigned aHB = su32(sA[0]) + (wm*32 + lh*8 + l7)*80 + lq*16;
    const unsigned aLB = su32(sA[1]) + (wm*32 + lh*8 + l7)*80 + lq*16;
    const unsigned bHB = su32(sB[0]) + (wn*64 + lq*8 + l7)*80 + lh*16;
    const unsigned bLB = su32(sB[1]) + (wn*64 + lq*8 + l7)*80 + lh*16;

    for (int k0 = 0; k0 < C_; k0 += 32) {
        __syncthreads();
        #pragma unroll
        for (int r = 0; r < 4; r++) {
            int s = tid + r*256;
            int buf = s >> 9, rc = s & 511;
            int row = rc >> 2, c = rc & 3;
            unsigned off = row*80 + c*16;
            const __nv_bfloat16* asrc = (buf ? Al : Ah) + (size_t)(o0+row)*C_ + k0 + c*8;
            const __nv_bfloat16* bsrc = (buf ? g_ytlo : g_ythi) + (size_t)(n0g+row)*C_ + k0 + c*8;
            cpasync16(su32(sA[buf]) + off, asrc);
            cpasync16(su32(sB[buf]) + off, bsrc);
        }
        cp_commit(); cp_wait0();
        __syncthreads();

        #pragma unroll
        for (int ks = 0; ks < 2; ks++) {
            const unsigned ko = ks*32;
            unsigned aH[2][4], aL[2][4];
            #pragma unroll
            for (int mi = 0; mi < 2; mi++) {
                ldsm4(aH[mi][0],aH[mi][1],aH[mi][2],aH[mi][3], aHB + mi*16*80 + ko);
                ldsm4(aL[mi][0],aL[mi][1],aL[mi][2],aL[mi][3], aLB + mi*16*80 + ko);
            }
            #pragma unroll
            for (int nb = 0; nb < 4; nb++) {
                unsigned bH[4], bL[4];
                ldsm4(bH[0],bH[1],bH[2],bH[3], bHB + nb*16*80 + ko);
                ldsm4(bL[0],bL[1],bL[2],bL[3], bLB + nb*16*80 + ko);
                #pragma unroll
                for (int mi = 0; mi < 2; mi++) {
                    #pragma unroll
                    for (int t = 0; t < 2; t++) {
                        float* c = acc[mi][nb*2+t];
                        mma16816(c, aH[mi][0],aH[mi][1],aH[mi][2],aH[mi][3], bH[t*2],bH[t*2+1]);
                        mma16816(c, aH[mi][0],aH[mi][1],aH[mi][2],aH[mi][3], bL[t*2],bL[t*2+1]);
                        mma16816(c, aL[mi][0],aL[mi][1],aL[mi][2],aL[mi][3], bH[t*2],bH[t*2+1]);
                    }
                }
            }
        }
    }

    #pragma unroll
    for (int mi = 0; mi < 2; mi++) {
        int o = o0 + wm*32 + mi*16 + lg;
        float bi0 = bo[o], bi1 = bo[o+8];
        #pragma unroll
        for (int nj = 0; nj < 8; nj++) {
            int t = t0 + wn*64 + nj*8 + tg*2;
            float m0v = mask[(size_t)b*T_ + t];
            float m1v = mask[(size_t)b*T_ + t + 1];
            float2 v0 = make_float2((acc[mi][nj][0]+bi0)*m0v, (acc[mi][nj][1]+bi0)*m1v);
            float2 v1 = make_float2((acc[mi][nj][2]+bi1)*m0v, (acc[mi][nj][3]+bi1)*m1v);
            *(float2*)&out[((size_t)b*C_ + o)*T_ + t]     = v0;
            *(float2*)&out[((size_t)b*C_ + o + 8)*T_ + t] = v1;
        }
    }
}

// =====================================================================
// Fused attention: 64-query CTA, 512 threads, V-load overlapped with S.
// =====================================================================
__global__ __launch_bounds__(512, 1) void attn_kernel(
    const float* __restrict__ mask,
    const float* __restrict__ erel_k,
    const float* __restrict__ erel_v)
{
    extern __shared__ unsigned char smem[];
    __nv_bfloat16* qhi = (__nv_bfloat16*)(smem + OFF_QHI);
    __nv_bfloat16* qlo = (__nv_bfloat16*)(smem + OFF_QLO);
    __nv_bfloat16* khi = (__nv_bfloat16*)(smem + OFF_K);
    __nv_bfloat16* klo = (__nv_bfloat16*)(smem + OFF_K + 18432);
    __nv_bfloat16* vhi = (__nv_bfloat16*)(smem + OFF_V);
    __nv_bfloat16* vlo = (__nv_bfloat16*)(smem + OFF_V + 17408);
    float*  serelK = (float*)(smem + OFF_P);   // erel_k fp32 [129][66] pre-loop
    float*  serelV = (float*)(smem + OFF_V);   // erel_v fp32 [129][66] post-loop
    __nv_bfloat16* phi = (__nv_bfloat16*)(smem + OFF_P);
    __nv_bfloat16* plo = (__nv_bfloat16*)(smem + OFF_P + 17408);
    float* sbin = (float*)(smem + OFF_SBIN);
    float* sqr  = (float*)(smem + OFF_SQR);
    float* smk  = (float*)(smem + OFF_SMK);
    float* sstp = (float*)(smem + OFF_SSTP);   // [3][4][64]
    float* sst  = (float*)(smem + OFF_SST);    // [3][64]

    const int tid  = threadIdx.x;
    const int lane = tid & 31;
    const int w    = tid >> 5;          // 0..15
    const int wm   = w & 3;             // m16 tile (rows wm*16..+16)
    const int wg   = w >> 2;            // col group 0..3
    const int lg   = lane >> 2;
    const int tg   = lane & 3;
    const int r0   = wm*16 + lg;
    const int r1   = r0 + 8;
    const int l7   = lane & 7;
    const int lh   = (lane >> 3) & 1;
    const int lq   = lane >> 4;

    const int i0 = blockIdx.x * 64;
    const int h  = blockIdx.y;
    const int b  = blockIdx.z;
    const size_t headbase = (size_t)(b*H_+h)*T_*D_;

    // ---- Phase A: stage q (cp.async), erel_k (into P region), mask, init sbin ----
    #pragma unroll
    for (int r = 0; r < 2; r++) {
        int e = tid + r*512;
        int bufi = e >> 9;
        int rc = e & 511;
        int m = rc >> 3, c = rc & 7;
        unsigned dst = su32(bufi ? qlo : qhi) + m*144 + c*16;
        const unsigned char* src =
            (const unsigned char*)(bufi ? g_qlo : g_qhi)
            + (headbase + (size_t)(i0+m)*D_)*2 + c*16;
        cpasync16(dst, src);
    }
    cp_commit();
    for (int e = tid; e < REL_*32; e += 512) {
        int r = e >> 5, d2 = (e & 31) << 1;
        *(float2*)&serelK[r*66 + d2] = ((const float2*)erel_k)[e];
    }
    for (int e = tid; e < T_/4; e += 512)
        ((float4*)smk)[e] = ((const float4*)(mask + (size_t)b*T_))[e];
    for (int e = tid; e < 64*132; e += 512)
        sbin[e] = -1e9f;
    cp_wait0();
    __syncthreads();

    // ---- Phase B: qrel[m][r] = (qhi+qlo)[m] . erel_k[r] ----
    for (int idx = tid; idx < 64*REL_; idx += 512) {
        int m = idx / REL_, r = idx - m*REL_;
        const __nv_bfloat162* qh = (const __nv_bfloat162*)&qhi[m*72];
        const __nv_bfloat162* ql = (const __nv_bfloat162*)&qlo[m*72];
        const float2* e2 = (const float2*)&serelK[r*66];
        float s = 0.f;
        #pragma unroll
        for (int i = 0; i < 32; i++) {
            __nv_bfloat162 hh = qh[i], ll = ql[i];
            float2 ee = e2[i];
            s += (__bfloat162float(hh.x)+__bfloat162float(ll.x))*ee.x
               + (__bfloat162float(hh.y)+__bfloat162float(ll.y))*ee.y;
        }
        sqr[m*132 + r] = s;
    }

    const float scale = 0.125f;
    float yacc[2][4] = {};
    float ls0=0.f, ls1=0.f, ea0=0.f, ea1=0.f, eb0=0.f, eb1=0.f;

    const unsigned qhiA = su32(qhi) + (unsigned)((wm*16 + lh*8 + l7)*144 + lq*16);
    const unsigned qloA = su32(qlo) + (unsigned)((wm*16 + lh*8 + l7)*144 + lq*16);
    const unsigned khiB0 = su32(khi) + (unsigned)((wg*32 + lq*8 + l7)*144 + lh*16);
    const unsigned kloB0 = su32(klo) + (unsigned)((wg*32 + lq*8 + l7)*144 + lh*16);
    const unsigned phiA = su32(phi) + (unsigned)((wm*16 + lh*8 + l7)*272 + lq*16);
    const unsigned ploA = su32(plo) + (unsigned)((wm*16 + lh*8 + l7)*272 + lq*16);
    const unsigned vhiB = su32(vhi) + (unsigned)((wg*8 + lq*32 + l7)*272 + lh*16);
    const unsigned vloB = su32(vlo) + (unsigned)((wg*8 + lq*32 + l7)*272 + lh*16);

    // ---- Main loop over 8 key chunks of 128 ----
    for (int kt = 0; kt < 8; kt++) {
        const int j0g = kt * 128;
        __syncthreads();   // prior chunk PV reads of V + phase-B reads done
        // stage khi/klo [128][72]  (group 0)
        #pragma unroll
        for (int r = 0; r < 4; r++) {
            int e = tid + r*512;
            int bufi = e >> 10;
            int rc = e & 1023;
            int j = rc >> 3, c = rc & 7;
            unsigned dst = su32(bufi ? klo : khi) + j*144 + c*16;
            const unsigned char* src =
                (const unsigned char*)(bufi ? g_klo : g_khi)
                + (headbase + (size_t)(j0g+j)*D_)*2 + c*16;
            cpasync16(dst, src);
        }
        cp_commit();
        // stage vhi/vlo [64][136]  (group 1 — overlaps with S phase)
        #pragma unroll
        for (int r = 0; r < 4; r++) {
            int e = tid + r*512;
            int bufi = e >> 10;
            int rc = e & 1023;
            int d = rc >> 4, c = rc & 15;
            unsigned dst = su32(bufi ? vlo : vhi) + d*272 + c*16;
            const unsigned char* src =
                (const unsigned char*)(bufi ? g_vlo : g_vhi)
                + (headbase + (size_t)d*T_ + j0g)*2 + c*16;
            cpasync16(dst, src);
        }
        cp_commit();
        cp_wait1();        // K arrived; V still in flight
        __syncthreads();

        // ---- S = Q K^T ----
        float sacc[4][4] = {};
        #pragma unroll
        for (int ks = 0; ks < 4; ks++) {
            const unsigned ko = ks*32;
            unsigned aH0,aH1,aH2,aH3, aL0,aL1,aL2,aL3;
            ldsm4(aH0,aH1,aH2,aH3, qhiA + ko);
            ldsm4(aL0,aL1,aL2,aL3, qloA + ko);
            unsigned bH[8], bL[8];
            ldsm4(bH[0],bH[1],bH[2],bH[3], khiB0 + ko);
            ldsm4(bH[4],bH[5],bH[6],bH[7], khiB0 + 16*144 + ko);
            ldsm4(bL[0],bL[1],bL[2],bL[3], kloB0 + ko);
            ldsm4(bL[4],bL[5],bL[6],bL[7], kloB0 + 16*144 + ko);
            #pragma unroll
            for (int t = 0; t < 4; t++) {
                unsigned b0h = bH[t*2], b1h = bH[t*2+1];
                unsigned b0l = bL[t*2], b1l = bL[t*2+1];
                mma16816(sacc[t], aH0,aH1,aH2,aH3, b0h,b1h);
                mma16816(sacc[t], aH0,aH1,aH2,aH3, b0l,b1l);
                mma16816(sacc[t], aL0,aL1,aL2,aL3, b0h,b1h);
            }
        }

        // ---- epilogue: rel gather, mask, exp, bins, P hi/lo ----
        #pragma unroll
        for (int t = 0; t < 4; t++) {
            const int cb = wg*32 + t*8 + tg*2;
            #pragma unroll
            for (int ii = 0; ii < 2; ii++) {
                const int rr = ii ? r1 : r0;
                const int gi = i0 + rr;
                float ev[2];
                #pragma unroll
                for (int jj = 0; jj < 2; jj++) {
                    int gj = j0g + cb + jj;
                    int rel = gj - gi;
                    int relc = rel < -64 ? -64 : (rel > 64 ? 64 : rel);
                    float s = sacc[t][ii*2+jj]*scale + sqr[rr*132 + relc + 64];
                    if (smk[gj] <= 0.f) s = -1e9f;
                    float e = __expf(s);
                    if (ii == 0) ls0 += e; else ls1 += e;
                    if (rel <= -64)      { if (ii == 0) ea0 += e; else ea1 += e; }
                    else if (rel >= 64)  { if (ii == 0) eb0 += e; else eb1 += e; }
                    else                 sbin[rr*132 + rel + 64] = s;
                    ev[jj] = e;
                }
                __nv_bfloat16 eh0,el0,eh1,el1;
                cv(ev[0],eh0,el0); cv(ev[1],eh1,el1);
                *(unsigned*)&phi[rr*136 + cb] = pk2(eh0,eh1);
                *(unsigned*)&plo[rr*136 + cb] = pk2(el0,el1);
            }
        }
        cp_wait0();        // V arrived (long since, overlapped)
        __syncthreads();   // V + phi/plo visible

        // ---- PV: y += P @ V ----
        #pragma unroll
        for (int ks = 0; ks < 8; ks++) {
            const unsigned ko = ks*32;
            unsigned aH0,aH1,aH2,aH3, aL0,aL1,aL2,aL3;
            ldsm4(aH0,aH1,aH2,aH3, phiA + ko);
            ldsm4(aL0,aL1,aL2,aL3, ploA + ko);
            unsigned bH[4], bL[4];
            ldsm4(bH[0],bH[1],bH[2],bH[3], vhiB + ko);
            ldsm4(bL[0],bL[1],bL[2],bL[3], vloB + ko);
            #pragma unroll
            for (int ti = 0; ti < 2; ti++) {
                unsigned b0h = bH[ti*2], b1h = bH[ti*2+1];
                unsigned b0l = bL[ti*2], b1l = bL[ti*2+1];
                mma16816(yacc[ti], aH0,aH1,aH2,aH3, b0h,b1h);
                mma16816(yacc[ti], aH0,aH1,aH2,aH3, b0l,b1l);
                mma16816(yacc[ti], aL0,aL1,aL2,aL3, b0h,b1h);
            }
        }
    }
    __syncthreads();   // last PV reads done

    // ---- load erel_v into V region + stat reduction ----
    for (int e = tid; e < REL_*32; e += 512) {
        int r = e >> 5, d2 = (e & 31) << 1;
        *(float2*)&serelV[r*66 + d2] = ((const float2*)erel_v)[e];
    }
    {
        float v;
        #define RED_(x) v = x; v += __shfl_xor_sync(~0u, v, 1); v += __shfl_xor_sync(~0u, v, 2); x = v;
        RED_(ls0) RED_(ls1) RED_(ea0) RED_(ea1) RED_(eb0) RED_(eb1)
        #undef RED_
        if (tg == 0) {
            sstp[0*256 + wg*64 + r0] = ls0;  sstp[0*256 + wg*64 + r1] = ls1;
            sstp[1*256 + wg*64 + r0] = ea0;  sstp[1*256 + wg*64 + r1] = ea1;
            sstp[2*256 + wg*64 + r0] = eb0;  sstp[2*256 + wg*64 + r1] = eb1;
        }
    }
    __syncthreads();
    if (tid < 64) {
        float l = 0.f, a = 0.f, c = 0.f;
        #pragma unroll
        for (int g = 0; g < 4; g++) {
            l += sstp[0*256 + g*64 + tid];
            a += sstp[1*256 + g*64 + tid];
            c += sstp[2*256 + g*64 + tid];
        }
        sst[tid] = l; sst[64+tid] = a; sst[128+tid] = c;
    }
    __syncthreads();

    // ---- finalize bins ----
    for (int e = tid; e < 64*REL_; e += 512) {
        int m = e / REL_, r = e - m*REL_;
        float invl = 1.f / sst[m];
        float v;
        if (r == 0)         v = sst[64+m]*invl;
        else if (r == 128)  v = sst[128+m]*invl;
        else                v = __expf(sbin[m*132+r])*invl;
        sbin[m*132+r] = v;
    }
    __syncthreads();

    // ---- final: y = yacc/l + bins @ erel_v ; store yt bf16 hi/lo ----
    {
        const float inv0 = 1.f / sst[r0];
        const float inv1 = 1.f / sst[r1];
        const int dA = wg*8 + tg*2;
        const int dB = dA + 32;
        float o00 = yacc[0][0]*inv0, o01 = yacc[0][1]*inv0;
        float o02 = yacc[0][2]*inv1, o03 = yacc[0][3]*inv1;
        float o10 = yacc[1][0]*inv0, o11 = yacc[1][1]*inv0;
        float o12 = yacc[1][2]*inv1, o13 = yacc[1][3]*inv1;
        #pragma unroll 4
        for (int r = 0; r < REL_; r++) {
            float b0 = sbin[r0*132 + r];
            float b1 = sbin[r1*132 + r];
            float2 eA = *(const float2*)&serelV[r*66 + dA];
            float2 eB = *(const float2*)&serelV[r*66 + dB];
            o00 += b0*eA.x; o01 += b0*eA.y;
            o02 += b1*eA.x; o03 += b1*eA.y;
            o10 += b0*eB.x; o11 += b0*eB.y;
            o12 += b1*eB.x; o13 += b1*eB.y;
        }
        const int cbase = h*64;
        size_t tb0 = ((size_t)b*T_ + i0 + r0)*C_;
        size_t tb1 = ((size_t)b*T_ + i0 + r1)*C_;
        __nv_bfloat16 h0,l0,h1,l1;
        cv(o00,h0,l0); cv(o01,h1,l1);
        *(unsigned*)&g_ythi[tb0 + cbase + dA] = pk2(h0,h1);
        *(unsigned*)&g_ytlo[tb0 + cbase + dA] = pk2(l0,l1);
        cv(o02,h0,l0); cv(o03,h1,l1);
        *(unsigned*)&g_ythi[tb1 + cbase + dA] = pk2(h0,h1);
        *(unsigned*)&g_ytlo[tb1 + cbase + dA] = pk2(l0,l1);
        cv(o10,h0,l0); cv(o11,h1,l1);
        *(unsigned*)&g_ythi[tb0 + cbase + dB] = pk2(h0,h1);
        *(unsigned*)&g_ytlo[tb0 + cbase + dB] = pk2(l0,l1);
        cv(o12,h0,l0); cv(o13,h1,l1);
        *(unsigned*)&g_ythi[tb1 + cbase + dB] = pk2(h0,h1);
        *(unsigned*)&g_ytlo[tb1 + cbase + dB] = pk2(l0,l1);
    }
}

// =====================================================================
extern "C" void kernel_launch(void* const* d_in, const int* in_sizes, int n_in,
                              void* d_out, int out_size)
{
    const float* x     = (const float*)d_in[0];
    const float* xmask = (const float*)d_in[1];
    const float* Wq    = (const float*)d_in[2];
    const float* bq    = (const float*)d_in[3];
    const float* Wk    = (const float*)d_in[4];
    const float* bk    = (const float*)d_in[5];
    const float* Wv    = (const float*)d_in[6];
    const float* bv    = (const float*)d_in[7];
    const float* Wo    = (const float*)d_in[8];
    const float* bo    = (const float*)d_in[9];
    const float* erelk = (const float*)d_in[10];
    const float* erelv = (const float*)d_in[11];
    float* out = (float*)d_out;

    cudaFuncSetAttribute(attn_kernel,
                         cudaFuncAttributeMaxDynamicSharedMemorySize, SMEM_BYTES);

    conv_x<<<dim3(T_/32, C_/32, B_), 256>>>(x);
    conv_w<<<dim3(C_*C_/256, 4), 256>>>(Wq, Wk, Wv, Wo);

    proj_fused<<<dim3(64, 12), 256>>>(bq, bk, bv);

    attn_kernel<<<dim3(16, H_, B_), 512, SMEM_BYTES>>>(xmask, erelk, erelv);

    outp_gemm<<<dim3(4, 64), 256>>>(bo, xmask, out);
}

// round 8
// speedup vs baseline: 4.1928x; 1.4129x over previous
#include <cuda_runtime.h>
#include <cuda_bf16.h>

#define B_ 8
#define C_ 512
#define T_ 1024
#define H_ 8
#define D_ 64
#define REL_ 129

// ---------------- scratch (no cudaMalloc allowed) ----------------
__device__ __nv_bfloat16 g_xthi[B_*T_*C_];    // x^T (B,T,C) hi
__device__ __nv_bfloat16 g_xtlo[B_*T_*C_];
__device__ __nv_bfloat16 g_whi[4*C_*C_];      // Wq,Wk,Wv,Wo hi
__device__ __nv_bfloat16 g_wlo[4*C_*C_];
__device__ __nv_bfloat16 g_qhi[B_*H_*T_*D_];  // (B,H,T,D)
__device__ __nv_bfloat16 g_qlo[B_*H_*T_*D_];
__device__ __nv_bfloat16 g_khi[B_*H_*T_*D_];
__device__ __nv_bfloat16 g_klo[B_*H_*T_*D_];
__device__ __nv_bfloat16 g_vhi[B_*H_*T_*D_];  // (B,H,D,T)
__device__ __nv_bfloat16 g_vlo[B_*H_*T_*D_];
__device__ __nv_bfloat16 g_ythi[B_*T_*C_];    // y^T (B,T,C)
__device__ __nv_bfloat16 g_ytlo[B_*T_*C_];
__device__ __nv_bfloat16 g_ekhi[REL_*D_];     // erel_k [129][64]
__device__ __nv_bfloat16 g_eklo[REL_*D_];
__device__ __nv_bfloat16 g_evhi[D_*144];      // erel_v^T [64][144] (zero-padded)
__device__ __nv_bfloat16 g_evlo[D_*144];

// ---------------- attn shared memory (byte offsets), 64-query CTA ----------------
#define OFF_QHI   0          // bf16 [64][72]  9216
#define OFF_QLO   9216
#define OFF_K     18432      // khi 18432 + klo 18432
#define OFF_V     55296      // vhi 17408 + vlo 17408
#define OFF_P     90112      // phi 17408 + plo 17408
#define OFF_SBIN  124928     // fp32 [64][132] 33792
#define OFF_SQR   158720     // fp32 [64][136] 34816
#define OFF_SMK   193536     // fp32 [1024] 4096
#define OFF_SSTP  197632     // fp32 [3][4][64] 3072
#define OFF_SST   200704     // fp32 [64] (+pad) 768
#define SMEM_BYTES 201472
// overlays: phase B (pre-loop): ek over K/V region; post-loop: bins/ev over K/V/P
#define OFF_EKHI  18432      // bf16 [144][72] 20736 (rows 0..128 staged)
#define OFF_EKLO  39168
#define OFF_BINHI 18432      // bf16 [64][152] 19456
#define OFF_BINLO 37888
#define OFF_EVHI  57344      // bf16 [64][152] 19456
#define OFF_EVLO  76800

__device__ __forceinline__ unsigned pk2(__nv_bfloat16 a, __nv_bfloat16 b) {
    __nv_bfloat162 t = __halves2bfloat162(a, b);
    return *reinterpret_cast<unsigned*>(&t);
}
__device__ __forceinline__ void cv(float x, __nv_bfloat16& h, __nv_bfloat16& l) {
    h = __float2bfloat16(x);
    l = __float2bfloat16(x - __bfloat162float(h));
}
__device__ __forceinline__ unsigned su32(const void* p) {
    return (unsigned)__cvta_generic_to_shared(p);
}
__device__ __forceinline__ void cpasync16(unsigned s, const void* g) {
    asm volatile("cp.async.cg.shared.global [%0], [%1], 16;" :: "r"(s), "l"(g));
}
__device__ __forceinline__ void cp_commit() {
    asm volatile("cp.async.commit_group;" ::: "memory");
}
__device__ __forceinline__ void cp_wait0() {
    asm volatile("cp.async.wait_group 0;" ::: "memory");
}
__device__ __forceinline__ void cp_wait1() {
    asm volatile("cp.async.wait_group 1;" ::: "memory");
}
__device__ __forceinline__ void ldsm4(unsigned& r0, unsigned& r1, unsigned& r2,
                                      unsigned& r3, unsigned addr) {
    asm volatile("ldmatrix.sync.aligned.m8n8.x4.shared.b16 {%0,%1,%2,%3}, [%4];"
                 : "=r"(r0), "=r"(r1), "=r"(r2), "=r"(r3) : "r"(addr));
}
__device__ __forceinline__ void mma16816(float* c, unsigned a0, unsigned a1,
                                         unsigned a2, unsigned a3,
                                         unsigned b0, unsigned b1) {
    asm volatile(
        "mma.sync.aligned.m16n8k16.row.col.f32.bf16.bf16.f32 "
        "{%0,%1,%2,%3}, {%4,%5,%6,%7}, {%8,%9}, {%0,%1,%2,%3};"
        : "+f"(c[0]), "+f"(c[1]), "+f"(c[2]), "+f"(c[3])
        : "r"(a0), "r"(a1), "r"(a2), "r"(a3), "r"(b0), "r"(b1));
}

// =====================================================================
// prep kernels
// =====================================================================
__global__ __launch_bounds__(256) void conv_x(const float* __restrict__ x)
{
    __shared__ float s[32][33];
    const int b = blockIdx.z, c0 = blockIdx.y*32, t0 = blockIdx.x*32;
    const int tx = threadIdx.x & 31, ty = threadIdx.x >> 5;
    #pragma unroll
    for (int r = 0; r < 4; r++) {
        int c = ty + r*8;
        s[c][tx] = x[((size_t)b*C_ + c0 + c)*T_ + t0 + tx];
    }
    __syncthreads();
    #pragma unroll
    for (int r = 0; r < 4; r++) {
        int t = ty + r*8;
        float v = s[tx][t];
        __nv_bfloat16 h, l;
        cv(v, h, l);
        size_t idx = ((size_t)b*T_ + t0 + t)*C_ + c0 + tx;
        g_xthi[idx] = h;
        g_xtlo[idx] = l;
    }
}

__global__ __launch_bounds__(256) void conv_w(
    const float* __restrict__ w0, const float* __restrict__ w1,
    const float* __restrict__ w2, const float* __restrict__ w3)
{
    const int g = blockIdx.y;
    const float* W = g==0 ? w0 : g==1 ? w1 : g==2 ? w2 : w3;
    int idx = blockIdx.x*256 + threadIdx.x;
    float v = W[idx];
    __nv_bfloat16 h, l;
    cv(v, h, l);
    g_whi[(size_t)g*C_*C_ + idx] = h;
    g_wlo[(size_t)g*C_*C_ + idx] = l;
}

// erel_k -> bf16 hi/lo [129][64]; erel_v -> transposed bf16 hi/lo [64][144] zero-padded
__global__ __launch_bounds__(256) void conv_erel(
    const float* __restrict__ erelk, const float* __restrict__ erelv)
{
    int idx = blockIdx.x*256 + threadIdx.x;
    if (idx < REL_*D_) {
        __nv_bfloat16 h, l;
        cv(erelk[idx], h, l);
        g_ekhi[idx] = h; g_eklo[idx] = l;
    }
    if (idx < D_*144) {
        int d = idx / 144, r = idx - d*144;
        float v = (r < REL_) ? erelv[r*D_ + d] : 0.f;
        __nv_bfloat16 h, l;
        cv(v, h, l);
        g_evhi[idx] = h; g_evlo[idx] = l;
    }
}

// =====================================================================
// Fused QKV tensor GEMM (unchanged)
// =====================================================================
__global__ __launch_bounds__(256, 2) void proj_fused(
    const float* __restrict__ bq, const float* __restrict__ bk,
    const float* __restrict__ bv)
{
    __shared__ __align__(16) __nv_bfloat16 sA[2][128*40];
    __shared__ __align__(16) __nv_bfloat16 sB[2][128*40];

    const int tid = threadIdx.x, lane = tid & 31, w = tid >> 5;
    const int wm = w & 3, wn = w >> 2;
    const int lg = lane >> 2, tg = lane & 3;
    const int l7 = lane & 7, lh = (lane >> 3) & 1, lq = lane >> 4;

    const int ny = blockIdx.y;
    const int wsel = ny >> 2;
    const int o0 = (ny & 3) * 128;
    const int m0g = blockIdx.x * 128;
    const int b = m0g >> 10, t0 = m0g & 1023;

    const __nv_bfloat16* Ah = g_xthi;
    const __nv_bfloat16* Al = g_xtlo;
    const __nv_bfloat16* Bh = g_whi + (size_t)wsel*C_*C_;
    const __nv_bfloat16* Bl = g_wlo + (size_t)wsel*C_*C_;

    float acc[2][8][4] = {};

    const unsigned aHB = su32(sA[0]) + (wm*32 + lh*8 + l7)*80 + lq*16;
    const unsigned aLB = su32(sA[1]) + (wm*32 + lh*8 + l7)*80 + lq*16;
    const unsigned bHB = su32(sB[0]) + (wn*64 + lq*8 + l7)*80 + lh*16;
    const unsigned bLB = su32(sB[1]) + (wn*64 + lq*8 + l7)*80 + lh*16;

    for (int k0 = 0; k0 < C_; k0 += 32) {
        __syncthreads();
        #pragma unroll
        for (int r = 0; r < 4; r++) {
            int s = tid + r*256;
            int buf = s >> 9, rc = s & 511;
            int row = rc >> 2, c = rc & 3;
            unsigned off = row*80 + c*16;
            const __nv_bfloat16* asrc = (buf ? Al : Ah) + (size_t)(m0g+row)*C_ + k0 + c*8;
            const __nv_bfloat16* bsrc = (buf ? Bl : Bh) + (size_t)(o0+row)*C_ + k0 + c*8;
            cpasync16(su32(sA[buf]) + off, asrc);
            cpasync16(su32(sB[buf]) + off, bsrc);
        }
        cp_commit(); cp_wait0();
        __syncthreads();

        #pragma unroll
        for (int ks = 0; ks < 2; ks++) {
            const unsigned ko = ks*32;
            unsigned aH[2][4], aL[2][4];
            #pragma unroll
            for (int mi = 0; mi < 2; mi++) {
                ldsm4(aH[mi][0],aH[mi][1],aH[mi][2],aH[mi][3], aHB + mi*16*80 + ko);
                ldsm4(aL[mi][0],aL[mi][1],aL[mi][2],aL[mi][3], aLB + mi*16*80 + ko);
            }
            #pragma unroll
            for (int nb = 0; nb < 4; nb++) {
                unsigned bH[4], bL[4];
                ldsm4(bH[0],bH[1],bH[2],bH[3], bHB + nb*16*80 + ko);
                ldsm4(bL[0],bL[1],bL[2],bL[3], bLB + nb*16*80 + ko);
                #pragma unroll
                for (int mi = 0; mi < 2; mi++) {
                    #pragma unroll
                    for (int t = 0; t < 2; t++) {
                        float* c = acc[mi][nb*2+t];
                        mma16816(c, aH[mi][0],aH[mi][1],aH[mi][2],aH[mi][3], bH[t*2],bH[t*2+1]);
                        mma16816(c, aH[mi][0],aH[mi][1],aH[mi][2],aH[mi][3], bL[t*2],bL[t*2+1]);
                        mma16816(c, aL[mi][0],aL[mi][1],aL[mi][2],aL[mi][3], bH[t*2],bH[t*2+1]);
                    }
                }
            }
        }
    }

    const float* bias = wsel==0 ? bq : (wsel==1 ? bk : bv);
    if (wsel < 2) {
        __nv_bfloat16* oh = wsel==0 ? g_qhi : g_khi;
        __nv_bfloat16* ol = wsel==0 ? g_qlo : g_klo;
        #pragma unroll
        for (int mi = 0; mi < 2; mi++) {
            int tr0 = t0 + wm*32 + mi*16 + lg;
            #pragma unroll
            for (int nj = 0; nj < 8; nj++) {
                int o = o0 + wn*64 + nj*8 + tg*2;
                float bi0 = bias[o], bi1 = bias[o+1];
                int hh = o >> 6, d = o & 63;
                size_t base = ((size_t)(b*H_+hh)*T_ + tr0)*D_ + d;
                __nv_bfloat16 h0,l0,h1,l1;
                cv(acc[mi][nj][0]+bi0, h0,l0); cv(acc[mi][nj][1]+bi1, h1,l1);
                *(unsigned*)&oh[base] = pk2(h0,h1);
                *(unsigned*)&ol[base] = pk2(l0,l1);
                cv(acc[mi][nj][2]+bi0, h0,l0); cv(acc[mi][nj][3]+bi1, h1,l1);
                *(unsigned*)&oh[base + 8*D_] = pk2(h0,h1);
                *(unsigned*)&ol[base + 8*D_] = pk2(l0,l1);
            }
        }
    } else {
        #pragma unroll
        for (int mi = 0; mi < 2; mi++) {
            int tr0 = t0 + wm*32 + mi*16 + lg;
            #pragma unroll
            for (int nj = 0; nj < 8; nj++) {
                int o = o0 + wn*64 + nj*8 + tg*2;
                float bi0 = bias[o], bi1 = bias[o+1];
                int hh = o >> 6, d = o & 63;
                size_t base = ((size_t)(b*H_+hh)*D_ + d)*T_ + tr0;
                __nv_bfloat16 h0,l0;
                cv(acc[mi][nj][0]+bi0, h0,l0); g_vhi[base] = h0;      g_vlo[base] = l0;
                cv(acc[mi][nj][1]+bi1, h0,l0); g_vhi[base+T_] = h0;   g_vlo[base+T_] = l0;
                cv(acc[mi][nj][2]+bi0, h0,l0); g_vhi[base+8] = h0;    g_vlo[base+8] = l0;
                cv(acc[mi][nj][3]+bi1, h0,l0); g_vhi[base+T_+8] = h0; g_vlo[base+T_+8] = l0;
            }
        }
    }
}

// =====================================================================
// Output projection tensor GEMM (unchanged)
// =====================================================================
__global__ __launch_bounds__(256, 2) void outp_gemm(
    const float* __restrict__ bo, const float* __restrict__ mask,
    float* __restrict__ out)
{
    __shared__ __align__(16) __nv_bfloat16 sA[2][128*40];
    __shared__ __align__(16) __nv_bfloat16 sB[2][128*40];

    const int tid = threadIdx.x, lane = tid & 31, w = tid >> 5;
    const int wm = w & 3, wn = w >> 2;
    const int lg = lane >> 2, tg = lane & 3;
    const int l7 = lane & 7, lh = (lane >> 3) & 1, lq = lane >> 4;

    const int o0 = blockIdx.x * 128;
    const int n0g = blockIdx.y * 128;
    const int b = n0g >> 10, t0 = n0g & 1023;

    const __nv_bfloat16* Ah = g_whi + (size_t)3*C_*C_;
    const __nv_bfloat16* Al = g_wlo + (size_t)3*C_*C_;

    float acc[2][8][4] = {};

    const unsigned aHB = su32(sA[0]) + (wm*32 + lh*8 + l7)*80 + lq*16;
    const unsigned aLB = su32(sA[1]) + (wm*32 + lh*8 + l7)*80 + lq*16;
    const unsigned bHB = su32(sB[0]) + (wn*64 + lq*8 + l7)*80 + lh*16;
    const unsigned bLB = su32(sB[1]) + (wn*64 + lq*8 + l7)*80 + lh*16;

    for (int k0 = 0; k0 < C_; k0 += 32) {
        __syncthreads();
        #pragma unroll
        for (int r = 0; r < 4; r++) {
            int s = tid + r*256;
            int buf = s >> 9, rc = s & 511;
            int row = rc >> 2, c = rc & 3;
            unsigned off = row*80 + c*16;
            const __nv_bfloat16* asrc = (buf ? Al : Ah) + (size_t)(o0+row)*C_ + k0 + c*8;
            const __nv_bfloat16* bsrc = (buf ? g_ytlo : g_ythi) + (size_t)(n0g+row)*C_ + k0 + c*8;
            cpasync16(su32(sA[buf]) + off, asrc);
            cpasync16(su32(sB[buf]) + off, bsrc);
        }
        cp_commit(); cp_wait0();
        __syncthreads();

        #pragma unroll
        for (int ks = 0; ks < 2; ks++) {
            const unsigned ko = ks*32;
            unsigned aH[2][4], aL[2][4];
            #pragma unroll
            for (int mi = 0; mi < 2; mi++) {
                ldsm4(aH[mi][0],aH[mi][1],aH[mi][2],aH[mi][3], aHB + mi*16*80 + ko);
                ldsm4(aL[mi][0],aL[mi][1],aL[mi][2],aL[mi][3], aLB + mi*16*80 + ko);
            }
            #pragma unroll
            for (int nb = 0; nb < 4; nb++) {
                unsigned bH[4], bL[4];
                ldsm4(bH[0],bH[1],bH[2],bH[3], bHB + nb*16*80 + ko);
                ldsm4(bL[0],bL[1],bL[2],bL[3], bLB + nb*16*80 + ko);
                #pragma unroll
                for (int mi = 0; mi < 2; mi++) {
                    #pragma unroll
                    for (int t = 0; t < 2; t++) {
                        float* c = acc[mi][nb*2+t];
                        mma16816(c, aH[mi][0],aH[mi][1],aH[mi][2],aH[mi][3], bH[t*2],bH[t*2+1]);
                        mma16816(c, aH[mi][0],aH[mi][1],aH[mi][2],aH[mi][3], bL[t*2],bL[t*2+1]);
                        mma16816(c, aL[mi][0],aL[mi][1],aL[mi][2],aL[mi][3], bH[t*2],bH[t*2+1]);
                    }
                }
            }
        }
    }

    #pragma unroll
    for (int mi = 0; mi < 2; mi++) {
        int o = o0 + wm*32 + mi*16 + lg;
        float bi0 = bo[o], bi1 = bo[o+8];
        #pragma unroll
        for (int nj = 0; nj < 8; nj++) {
            int t = t0 + wn*64 + nj*8 + tg*2;
            float m0v = mask[(size_t)b*T_ + t];
            float m1v = mask[(size_t)b*T_ + t + 1];
            float2 v0 = make_float2((acc[mi][nj][0]+bi0)*m0v, (acc[mi][nj][1]+bi0)*m1v);
            float2 v1 = make_float2((acc[mi][nj][2]+bi1)*m0v, (acc[mi][nj][3]+bi1)*m1v);
            *(float2*)&out[((size_t)b*C_ + o)*T_ + t]     = v0;
            *(float2*)&out[((size_t)b*C_ + o + 8)*T_ + t] = v1;
        }
    }
}

// =====================================================================
// Fused attention: all matmuls (S, PV, qrel, bins@erelv) on tensor cores.
// =====================================================================
__global__ __launch_bounds__(512, 1) void attn_kernel(const float* __restrict__ mask)
{
    extern __shared__ unsigned char smem[];
    __nv_bfloat16* qhi = (__nv_bfloat16*)(smem + OFF_QHI);
    __nv_bfloat16* qlo = (__nv_bfloat16*)(smem + OFF_QLO);
    __nv_bfloat16* khi = (__nv_bfloat16*)(smem + OFF_K);
    __nv_bfloat16* klo = (__nv_bfloat16*)(smem + OFF_K + 18432);
    __nv_bfloat16* vhi = (__nv_bfloat16*)(smem + OFF_V);
    __nv_bfloat16* vlo = (__nv_bfloat16*)(smem + OFF_V + 17408);
    __nv_bfloat16* phi = (__nv_bfloat16*)(smem + OFF_P);
    __nv_bfloat16* plo = (__nv_bfloat16*)(smem + OFF_P + 17408);
    __nv_bfloat16* binhi = (__nv_bfloat16*)(smem + OFF_BINHI);
    __nv_bfloat16* binlo = (__nv_bfloat16*)(smem + OFF_BINLO);
    float* sbin = (float*)(smem + OFF_SBIN);   // [64][132] (e values)
    float* sqr  = (float*)(smem + OFF_SQR);    // [64][136]
    float* smk  = (float*)(smem + OFF_SMK);
    float* sstp = (float*)(smem + OFF_SSTP);
    float* sst  = (float*)(smem + OFF_SST);

    const int tid  = threadIdx.x;
    const int lane = tid & 31;
    const int w    = tid >> 5;
    const int wm   = w & 3;
    const int wg   = w >> 2;
    const int lg   = lane >> 2;
    const int tg   = lane & 3;
    const int r0   = wm*16 + lg;
    const int r1   = r0 + 8;
    const int l7   = lane & 7;
    const int lh   = (lane >> 3) & 1;
    const int lq   = lane >> 4;

    const int i0 = blockIdx.x * 64;
    const int h  = blockIdx.y;
    const int b  = blockIdx.z;
    const size_t headbase = (size_t)(b*H_+h)*T_*D_;

    // ---- Phase A: stage q + erel_k bf16 (cp.async); mask; zero sbin ----
    #pragma unroll
    for (int r = 0; r < 2; r++) {
        int e = tid + r*512;
        int bufi = e >> 9;
        int rc = e & 511;
        int m = rc >> 3, c = rc & 7;
        unsigned dst = su32(bufi ? qlo : qhi) + m*144 + c*16;
        const unsigned char* src =
            (const unsigned char*)(bufi ? g_qlo : g_qhi)
            + (headbase + (size_t)(i0+m)*D_)*2 + c*16;
        cpasync16(dst, src);
    }
    for (int e = tid; e < REL_*8; e += 512) {
        int r = e >> 3, c = e & 7;
        cpasync16(su32(smem + OFF_EKHI) + r*144 + c*16,
                  (const unsigned char*)g_ekhi + (size_t)(r*64 + c*8)*2);
    }
    for (int e = tid; e < REL_*8; e += 512) {
        int r = e >> 3, c = e & 7;
        cpasync16(su32(smem + OFF_EKLO) + r*144 + c*16,
                  (const unsigned char*)g_eklo + (size_t)(r*64 + c*8)*2);
    }
    cp_commit();
    for (int e = tid; e < T_/4; e += 512)
        ((float4*)smk)[e] = ((const float4*)(mask + (size_t)b*T_))[e];
    for (int e = tid; e < 64*132; e += 512)
        sbin[e] = 0.f;
    cp_wait0();
    __syncthreads();

    const unsigned qhiA = su32(qhi) + (unsigned)((wm*16 + lh*8 + l7)*144 + lq*16);
    const unsigned qloA = su32(qlo) + (unsigned)((wm*16 + lh*8 + l7)*144 + lq*16);

    // ---- Phase B: qrel = Q @ erel_k^T via MMA (N=136, cols>128 are pad) ----
    {
        const unsigned ekhiB = su32(smem + OFF_EKHI) + (lq*8 + l7)*144 + lh*16;
        const unsigned ekloB = su32(smem + OFF_EKLO) + (lq*8 + l7)*144 + lh*16;
        float qa[3][2][4] = {};
        const int ng = (wg == 0) ? 3 : 2;
        const int glist[3] = {wg, wg+4, 8};

        #pragma unroll
        for (int ks = 0; ks < 4; ks++) {
            const unsigned ko = ks*32;
            unsigned aH0,aH1,aH2,aH3, aL0,aL1,aL2,aL3;
            ldsm4(aH0,aH1,aH2,aH3, qhiA + ko);
            ldsm4(aL0,aL1,aL2,aL3, qloA + ko);
            for (int gi = 0; gi < ng; gi++) {
                const unsigned ro = glist[gi]*16*144;
                unsigned bH[4], bL[4];
                ldsm4(bH[0],bH[1],bH[2],bH[3], ekhiB + ro + ko);
                ldsm4(bL[0],bL[1],bL[2],bL[3], ekloB + ro + ko);
                #pragma unroll
                for (int t = 0; t < 2; t++) {
                    float* c = qa[gi][t];
                    mma16816(c, aH0,aH1,aH2,aH3, bH[t*2],bH[t*2+1]);
                    mma16816(c, aH0,aH1,aH2,aH3, bL[t*2],bL[t*2+1]);
                    mma16816(c, aL0,aL1,aL2,aL3, bH[t*2],bH[t*2+1]);
                }
            }
        }
        for (int gi = 0; gi < ng; gi++) {
            #pragma unroll
            for (int t = 0; t < 2; t++) {
                int col = glist[gi]*16 + t*8 + tg*2;
                if (col < 136) {
                    *(float2*)&sqr[r0*136 + col] = make_float2(qa[gi][t][0], qa[gi][t][1]);
                    *(float2*)&sqr[r1*136 + col] = make_float2(qa[gi][t][2], qa[gi][t][3]);
                }
            }
        }
    }
    __syncthreads();

    // per-row qrel edge constants (rel clamped to -64 / +64)
    const float qrM0 = sqr[r0*136];       const float qrP0 = sqr[r0*136 + 128];
    const float qrM1 = sqr[r1*136];       const float qrP1 = sqr[r1*136 + 128];

    const float scale = 0.125f;
    float yacc[2][4] = {};
    float ls0=0.f, ls1=0.f, ea0=0.f, ea1=0.f, eb0=0.f, eb1=0.f;

    const unsigned khiB0 = su32(khi) + (unsigned)((wg*32 + lq*8 + l7)*144 + lh*16);
    const unsigned kloB0 = su32(klo) + (unsigned)((wg*32 + lq*8 + l7)*144 + lh*16);
    const unsigned phiA = su32(phi) + (unsigned)((wm*16 + lh*8 + l7)*272 + lq*16);
    const unsigned ploA = su32(plo) + (unsigned)((wm*16 + lh*8 + l7)*272 + lq*16);
    const unsigned vhiB = su32(vhi) + (unsigned)((wg*8 + lq*32 + l7)*272 + lh*16);
    const unsigned vloB = su32(vlo) + (unsigned)((wg*8 + lq*32 + l7)*272 + lh*16);

    // ---- Main loop over 8 key chunks of 128 ----
    for (int kt = 0; kt < 8; kt++) {
        const int j0g = kt * 128;
        const int relbase = j0g - i0;
        const bool fastHi = (relbase >= 127);
        const bool fastLo = (relbase <= -191);
        __syncthreads();
        #pragma unroll
        for (int r = 0; r < 4; r++) {
            int e = tid + r*512;
            int bufi = e >> 10;
            int rc = e & 1023;
            int j = rc >> 3, c = rc & 7;
            unsigned dst = su32(bufi ? klo : khi) + j*144 + c*16;
            const unsigned char* src =
                (const unsigned char*)(bufi ? g_klo : g_khi)
                + (headbase + (size_t)(j0g+j)*D_)*2 + c*16;
            cpasync16(dst, src);
        }
        cp_commit();
        #pragma unroll
        for (int r = 0; r < 4; r++) {
            int e = tid + r*512;
            int bufi = e >> 10;
            int rc = e & 1023;
            int d = rc >> 4, c = rc & 15;
            unsigned dst = su32(bufi ? vlo : vhi) + d*272 + c*16;
            const unsigned char* src =
                (const unsigned char*)(bufi ? g_vlo : g_vhi)
                + (headbase + (size_t)d*T_ + j0g)*2 + c*16;
            cpasync16(dst, src);
        }
        cp_commit();
        cp_wait1();
        __syncthreads();

        // ---- S = Q K^T ----
        float sacc[4][4] = {};
        #pragma unroll
        for (int ks = 0; ks < 4; ks++) {
            const unsigned ko = ks*32;
            unsigned aH0,aH1,aH2,aH3, aL0,aL1,aL2,aL3;
            ldsm4(aH0,aH1,aH2,aH3, qhiA + ko);
            ldsm4(aL0,aL1,aL2,aL3, qloA + ko);
            unsigned bH[8], bL[8];
            ldsm4(bH[0],bH[1],bH[2],bH[3], khiB0 + ko);
            ldsm4(bH[4],bH[5],bH[6],bH[7], khiB0 + 16*144 + ko);
            ldsm4(bL[0],bL[1],bL[2],bL[3], kloB0 + ko);
            ldsm4(bL[4],bL[5],bL[6],bL[7], kloB0 + 16*144 + ko);
            #pragma unroll
            for (int t = 0; t < 4; t++) {
                unsigned b0h = bH[t*2], b1h = bH[t*2+1];
                unsigned b0l = bL[t*2], b1l = bL[t*2+1];
                mma16816(sacc[t], aH0,aH1,aH2,aH3, b0h,b1h);
                mma16816(sacc[t], aH0,aH1,aH2,aH3, b0l,b1l);
                mma16816(sacc[t], aL0,aL1,aL2,aL3, b0h,b1h);
            }
        }

        // ---- epilogue ----
        if (fastHi || fastLo) {
            const float c0 = fastHi ? qrP0 : qrM0;
            const float c1 = fastHi ? qrP1 : qrM1;
            float acc0 = 0.f, acc1 = 0.f;
            #pragma unroll
            for (int t = 0; t < 4; t++) {
                const int cb = wg*32 + t*8 + tg*2;
                #pragma unroll
                for (int ii = 0; ii < 2; ii++) {
                    const int rr = ii ? r1 : r0;
                    const float cc = ii ? c1 : c0;
                    float ev[2];
                    #pragma unroll
                    for (int jj = 0; jj < 2; jj++) {
                        int gj = j0g + cb + jj;
                        float s = sacc[t][ii*2+jj]*scale + cc;
                        if (smk[gj] <= 0.f) s = -1e9f;
                        float e = __expf(s);
                        if (ii == 0) acc0 += e; else acc1 += e;
                        ev[jj] = e;
                    }
                    __nv_bfloat16 eh0,el0,eh1,el1;
                    cv(ev[0],eh0,el0); cv(ev[1],eh1,el1);
                    *(unsigned*)&phi[rr*136 + cb] = pk2(eh0,eh1);
                    *(unsigned*)&plo[rr*136 + cb] = pk2(el0,el1);
                }
            }
            ls0 += acc0; ls1 += acc1;
            if (fastHi) { eb0 += acc0; eb1 += acc1; }
            else        { ea0 += acc0; ea1 += acc1; }
        } else {
            #pragma unroll
            for (int t = 0; t < 4; t++) {
                const int cb = wg*32 + t*8 + tg*2;
                #pragma unroll
                for (int ii = 0; ii < 2; ii++) {
                    const int rr = ii ? r1 : r0;
                    const int gi = i0 + rr;
                    float ev[2];
                    #pragma unroll
                    for (int jj = 0; jj < 2; jj++) {
                        int gj = j0g + cb + jj;
                        int rel = gj - gi;
                        int relc = rel < -64 ? -64 : (rel > 64 ? 64 : rel);
                        float s = sacc[t][ii*2+jj]*scale + sqr[rr*136 + relc + 64];
                        if (smk[gj] <= 0.f) s = -1e9f;
                        float e = __expf(s);
                        if (ii == 0) ls0 += e; else ls1 += e;
                        if (rel <= -64)      { if (ii == 0) ea0 += e; else ea1 += e; }
                        else if (rel >= 64)  { if (ii == 0) eb0 += e; else eb1 += e; }
                        else                 sbin[rr*132 + rel + 64] = e;
                        ev[jj] = e;
                    }
                    __nv_bfloat16 eh0,el0,eh1,el1;
                    cv(ev[0],eh0,el0); cv(ev[1],eh1,el1);
                    *(unsigned*)&phi[rr*136 + cb] = pk2(eh0,eh1);
                    *(unsigned*)&plo[rr*136 + cb] = pk2(el0,el1);
                }
            }
        }
        cp_wait0();
        __syncthreads();

        // ---- PV: y += P @ V ----
        #pragma unroll
        for (int ks = 0; ks < 8; ks++) {
            const unsigned ko = ks*32;
            unsigned aH0,aH1,aH2,aH3, aL0,aL1,aL2,aL3;
            ldsm4(aH0,aH1,aH2,aH3, phiA + ko);
            ldsm4(aL0,aL1,aL2,aL3, ploA + ko);
            unsigned bH[4], bL[4];
            ldsm4(bH[0],bH[1],bH[2],bH[3], vhiB + ko);
            ldsm4(bL[0],bL[1],bL[2],bL[3], vloB + ko);
            #pragma unroll
            for (int ti = 0; ti < 2; ti++) {
                unsigned b0h = bH[ti*2], b1h = bH[ti*2+1];
                unsigned b0l = bL[ti*2], b1l = bL[ti*2+1];
                mma16816(yacc[ti], aH0,aH1,aH2,aH3, b0h,b1h);
                mma16816(yacc[ti], aH0,aH1,aH2,aH3, b0l,b1l);
                mma16816(yacc[ti], aL0,aL1,aL2,aL3, b0h,b1h);
            }
        }
    }
    __syncthreads();   // last PV reads of V/P done

    // ---- stage erel_v^T bf16 (into V/P overlay) ----
    for (int e = tid; e < 64*18; e += 512) {
        int d = e/18, c = e - d*18;
        cpasync16(su32(smem + OFF_EVHI) + d*304 + c*16,
                  (const unsigned char*)g_evhi + (size_t)(d*144 + c*8)*2);
    }
    for (int e = tid; e < 64*18; e += 512) {
        int d = e/18, c = e - d*18;
        cpasync16(su32(smem + OFF_EVLO) + d*304 + c*16,
                  (const unsigned char*)g_evlo + (size_t)(d*144 + c*8)*2);
    }
    cp_commit();

    // ---- stat reduction ----
    {
        float v;
        #define RED_(x) v = x; v += __shfl_xor_sync(~0u, v, 1); v += __shfl_xor_sync(~0u, v, 2); x = v;
        RED_(ls0) RED_(ls1) RED_(ea0) RED_(ea1) RED_(eb0) RED_(eb1)
        #undef RED_
        if (tg == 0) {
            sstp[0*256 + wg*64 + r0] = ls0;  sstp[0*256 + wg*64 + r1] = ls1;
            sstp[1*256 + wg*64 + r0] = ea0;  sstp[1*256 + wg*64 + r1] = ea1;
            sstp[2*256 + wg*64 + r0] = eb0;  sstp[2*256 + wg*64 + r1] = eb1;
        }
    }
    __syncthreads();
    if (tid < 64) {
        float l = 0.f, a = 0.f, c = 0.f;
        #pragma unroll
        for (int g = 0; g < 4; g++) {
            l += sstp[0*256 + g*64 + tid];
            a += sstp[1*256 + g*64 + tid];
            c += sstp[2*256 + g*64 + tid];
        }
        sst[tid] = l;
        sbin[tid*132]       = a;   // edge bin rel<=-64
        sbin[tid*132 + 128] = c;   // edge bin rel>=+64
    }
    __syncthreads();

    // ---- convert bins fp32 -> bf16 hi/lo [64][152] (zero-pad k 129..143) ----
    for (int e = tid; e < 64*144; e += 512) {
        int m = e/144, c = e - m*144;
        float v = (c < REL_) ? sbin[m*132 + c] : 0.f;
        __nv_bfloat16 hh, ll;
        cv(v, hh, ll);
        binhi[m*152 + c] = hh;
        binlo[m*152 + c] = ll;
    }
    cp_wait0();
    __syncthreads();

    // ---- yacc += bins @ erel_v^T  (M=64, N=64, K=144) ----
    {
        const unsigned binA  = su32(smem + OFF_BINHI) + (wm*16 + lh*8 + l7)*304 + lq*16;
        const unsigned binAl = su32(smem + OFF_BINLO) + (wm*16 + lh*8 + l7)*304 + lq*16;
        const unsigned evB   = su32(smem + OFF_EVHI)  + (wg*8 + lq*32 + l7)*304 + lh*16;
        const unsigned evBl  = su32(smem + OFF_EVLO)  + (wg*8 + lq*32 + l7)*304 + lh*16;
        #pragma unroll
        for (int ks = 0; ks < 9; ks++) {
            const unsigned ko = ks*32;
            unsigned aH0,aH1,aH2,aH3, aL0,aL1,aL2,aL3;
            ldsm4(aH0,aH1,aH2,aH3, binA + ko);
            ldsm4(aL0,aL1,aL2,aL3, binAl + ko);
            unsigned bH[4], bL[4];
            ldsm4(bH[0],bH[1],bH[2],bH[3], evB + ko);
            ldsm4(bL[0],bL[1],bL[2],bL[3], evBl + ko);
            #pragma unroll
            for (int ti = 0; ti < 2; ti++) {
                unsigned b0h = bH[ti*2], b1h = bH[ti*2+1];
                unsigned b0l = bL[ti*2], b1l = bL[ti*2+1];
                mma16816(yacc[ti], aH0,aH1,aH2,aH3, b0h,b1h);
                mma16816(yacc[ti], aH0,aH1,aH2,aH3, b0l,b1l);
                mma16816(yacc[ti], aL0,aL1,aL2,aL3, b0h,b1h);
            }
        }
    }

    // ---- final: y = yacc / l ; store yt bf16 hi/lo ----
    {
        const float inv0 = 1.f / sst[r0];
        const float inv1 = 1.f / sst[r1];
        const int dA = wg*8 + tg*2;
        const int dB = dA + 32;
        const int cbase = h*64;
        size_t tb0 = ((size_t)b*T_ + i0 + r0)*C_;
        size_t tb1 = ((size_t)b*T_ + i0 + r1)*C_;
        __nv_bfloat16 h0,l0,h1,l1;
        cv(yacc[0][0]*inv0,h0,l0); cv(yacc[0][1]*inv0,h1,l1);
        *(unsigned*)&g_ythi[tb0 + cbase + dA] = pk2(h0,h1);
        *(unsigned*)&g_ytlo[tb0 + cbase + dA] = pk2(l0,l1);
        cv(yacc[0][2]*inv1,h0,l0); cv(yacc[0][3]*inv1,h1,l1);
        *(unsigned*)&g_ythi[tb1 + cbase + dA] = pk2(h0,h1);
        *(unsigned*)&g_ytlo[tb1 + cbase + dA] = pk2(l0,l1);
        cv(yacc[1][0]*inv0,h0,l0); cv(yacc[1][1]*inv0,h1,l1);
        *(unsigned*)&g_ythi[tb0 + cbase + dB] = pk2(h0,h1);
        *(unsigned*)&g_ytlo[tb0 + cbase + dB] = pk2(l0,l1);
        cv(yacc[1][2]*inv1,h0,l0); cv(yacc[1][3]*inv1,h1,l1);
        *(unsigned*)&g_ythi[tb1 + cbase + dB] = pk2(h0,h1);
        *(unsigned*)&g_ytlo[tb1 + cbase + dB] = pk2(l0,l1);
    }
}

// =====================================================================
extern "C" void kernel_launch(void* const* d_in, const int* in_sizes, int n_in,
                              void* d_out, int out_size)
{
    const float* x     = (const float*)d_in[0];
    const float* xmask = (const float*)d_in[1];
    const float* Wq    = (const float*)d_in[2];
    const float* bq    = (const float*)d_in[3];
    const float* Wk    = (const float*)d_in[4];
    const float* bk    = (const float*)d_in[5];
    const float* Wv    = (const float*)d_in[6];
    const float* bv    = (const float*)d_in[7];
    const float* Wo    = (const float*)d_in[8];
    const float* bo    = (const float*)d_in[9];
    const float* erelk = (const float*)d_in[10];
    const float* erelv = (const float*)d_in[11];
    float* out = (float*)d_out;

    cudaFuncSetAttribute(attn_kernel,
                         cudaFuncAttributeMaxDynamicSharedMemorySize, SMEM_BYTES);

    conv_x<<<dim3(T_/32, C_/32, B_), 256>>>(x);
    conv_w<<<dim3(C_*C_/256, 4), 256>>>(Wq, Wk, Wv, Wo);
    conv_erel<<<36, 256>>>(erelk, erelv);

    proj_fused<<<dim3(64, 12), 256>>>(bq, bk, bv);

    attn_kernel<<<dim3(16, H_, B_), 512, SMEM_BYTES>>>(xmask);

    outp_gemm<<<dim3(4, 64), 256>>>(bo, xmask, out);
}

// round 9
// speedup vs baseline: 4.2696x; 1.0183x over previous
#include <cuda_runtime.h>
#include <cuda_bf16.h>

#define B_ 8
#define C_ 512
#define T_ 1024
#define H_ 8
#define D_ 64
#define REL_ 129

// ---------------- scratch (no cudaMalloc allowed) ----------------
__device__ __nv_bfloat16 g_xthi[B_*T_*C_];    // x^T (B,T,C) hi
__device__ __nv_bfloat16 g_xtlo[B_*T_*C_];
__device__ __nv_bfloat16 g_whi[4*C_*C_];      // Wq,Wk,Wv,Wo hi
__device__ __nv_bfloat16 g_wlo[4*C_*C_];
__device__ __nv_bfloat16 g_qhi[B_*H_*T_*D_];  // (B,H,T,D)
__device__ __nv_bfloat16 g_qlo[B_*H_*T_*D_];
__device__ __nv_bfloat16 g_khi[B_*H_*T_*D_];
__device__ __nv_bfloat16 g_klo[B_*H_*T_*D_];
__device__ __nv_bfloat16 g_vhi[B_*H_*T_*D_];  // (B,H,D,T)
__device__ __nv_bfloat16 g_vlo[B_*H_*T_*D_];
__device__ __nv_bfloat16 g_ythi[B_*T_*C_];    // y^T (B,T,C)
__device__ __nv_bfloat16 g_ytlo[B_*T_*C_];
__device__ __nv_bfloat16 g_ekhi[REL_*D_];     // erel_k [129][64]
__device__ __nv_bfloat16 g_eklo[REL_*D_];
__device__ __nv_bfloat16 g_evhi[D_*144];      // erel_v^T [64][144] (zero-padded)
__device__ __nv_bfloat16 g_evlo[D_*144];

// ---------------- attn shared memory (byte offsets), 64-query CTA ----------------
#define OFF_QHI   0          // bf16 [64][72]  9216
#define OFF_QLO   9216
#define OFF_K     18432      // khi 18432 + klo 18432
#define OFF_V     55296      // vhi 17408 + vlo 17408
#define OFF_P     90112      // phi 17408 + plo 17408
#define OFF_SBIN  124928     // fp32 [64][132] 33792
#define OFF_SQR   158720     // fp32 [64][136] 34816
#define OFF_SMK   193536     // fp32 [1024] 4096
#define OFF_SSTP  197632     // fp32 [3][4][64] 3072
#define OFF_SST   200704     // fp32 [64] (+pad) 768
#define SMEM_BYTES 201472
// overlays
#define OFF_EKHI  18432
#define OFF_EKLO  39168
#define OFF_BINHI 18432
#define OFF_BINLO 37888
#define OFF_EVHI  57344
#define OFF_EVLO  76800

__device__ __forceinline__ unsigned pk2(__nv_bfloat16 a, __nv_bfloat16 b) {
    __nv_bfloat162 t = __halves2bfloat162(a, b);
    return *reinterpret_cast<unsigned*>(&t);
}
__device__ __forceinline__ void cv(float x, __nv_bfloat16& h, __nv_bfloat16& l) {
    h = __float2bfloat16(x);
    l = __float2bfloat16(x - __bfloat162float(h));
}
__device__ __forceinline__ unsigned su32(const void* p) {
    return (unsigned)__cvta_generic_to_shared(p);
}
__device__ __forceinline__ void cpasync16(unsigned s, const void* g) {
    asm volatile("cp.async.cg.shared.global [%0], [%1], 16;" :: "r"(s), "l"(g));
}
__device__ __forceinline__ void cp_commit() {
    asm volatile("cp.async.commit_group;" ::: "memory");
}
__device__ __forceinline__ void cp_wait0() {
    asm volatile("cp.async.wait_group 0;" ::: "memory");
}
__device__ __forceinline__ void cp_wait1() {
    asm volatile("cp.async.wait_group 1;" ::: "memory");
}
__device__ __forceinline__ void ldsm4(unsigned& r0, unsigned& r1, unsigned& r2,
                                      unsigned& r3, unsigned addr) {
    asm volatile("ldmatrix.sync.aligned.m8n8.x4.shared.b16 {%0,%1,%2,%3}, [%4];"
                 : "=r"(r0), "=r"(r1), "=r"(r2), "=r"(r3) : "r"(addr));
}
__device__ __forceinline__ void mma16816(float* c, unsigned a0, unsigned a1,
                                         unsigned a2, unsigned a3,
                                         unsigned b0, unsigned b1) {
    asm volatile(
        "mma.sync.aligned.m16n8k16.row.col.f32.bf16.bf16.f32 "
        "{%0,%1,%2,%3}, {%4,%5,%6,%7}, {%8,%9}, {%0,%1,%2,%3};"
        : "+f"(c[0]), "+f"(c[1]), "+f"(c[2]), "+f"(c[3])
        : "r"(a0), "r"(a1), "r"(a2), "r"(a3), "r"(b0), "r"(b1));
}

// =====================================================================
// prep kernels (unchanged)
// =====================================================================
__global__ __launch_bounds__(256) void conv_x(const float* __restrict__ x)
{
    __shared__ float s[32][33];
    const int b = blockIdx.z, c0 = blockIdx.y*32, t0 = blockIdx.x*32;
    const int tx = threadIdx.x & 31, ty = threadIdx.x >> 5;
    #pragma unroll
    for (int r = 0; r < 4; r++) {
        int c = ty + r*8;
        s[c][tx] = x[((size_t)b*C_ + c0 + c)*T_ + t0 + tx];
    }
    __syncthreads();
    #pragma unroll
    for (int r = 0; r < 4; r++) {
        int t = ty + r*8;
        float v = s[tx][t];
        __nv_bfloat16 h, l;
        cv(v, h, l);
        size_t idx = ((size_t)b*T_ + t0 + t)*C_ + c0 + tx;
        g_xthi[idx] = h;
        g_xtlo[idx] = l;
    }
}

__global__ __launch_bounds__(256) void conv_w(
    const float* __restrict__ w0, const float* __restrict__ w1,
    const float* __restrict__ w2, const float* __restrict__ w3)
{
    const int g = blockIdx.y;
    const float* W = g==0 ? w0 : g==1 ? w1 : g==2 ? w2 : w3;
    int idx = blockIdx.x*256 + threadIdx.x;
    float v = W[idx];
    __nv_bfloat16 h, l;
    cv(v, h, l);
    g_whi[(size_t)g*C_*C_ + idx] = h;
    g_wlo[(size_t)g*C_*C_ + idx] = l;
}

__global__ __launch_bounds__(256) void conv_erel(
    const float* __restrict__ erelk, const float* __restrict__ erelv)
{
    int idx = blockIdx.x*256 + threadIdx.x;
    if (idx < REL_*D_) {
        __nv_bfloat16 h, l;
        cv(erelk[idx], h, l);
        g_ekhi[idx] = h; g_eklo[idx] = l;
    }
    if (idx < D_*144) {
        int d = idx / 144, r = idx - d*144;
        float v = (r < REL_) ? erelv[r*D_ + d] : 0.f;
        __nv_bfloat16 h, l;
        cv(v, h, l);
        g_evhi[idx] = h; g_evlo[idx] = l;
    }
}

// =====================================================================
// Fused QKV tensor GEMM — double-buffered k-loop
// =====================================================================
__global__ __launch_bounds__(256, 2) void proj_fused(
    const float* __restrict__ bq, const float* __restrict__ bk,
    const float* __restrict__ bv)
{
    __shared__ __align__(16) __nv_bfloat16 sA[2][2][128*40];  // [stage][hi/lo]
    __shared__ __align__(16) __nv_bfloat16 sB[2][2][128*40];

    const int tid = threadIdx.x, lane = tid & 31, w = tid >> 5;
    const int wm = w & 3, wn = w >> 2;
    const int lg = lane >> 2, tg = lane & 3;
    const int l7 = lane & 7, lh = (lane >> 3) & 1, lq = lane >> 4;

    const int ny = blockIdx.y;
    const int wsel = ny >> 2;
    const int o0 = (ny & 3) * 128;
    const int m0g = blockIdx.x * 128;
    const int b = m0g >> 10, t0 = m0g & 1023;

    const __nv_bfloat16* Ah = g_xthi;
    const __nv_bfloat16* Al = g_xtlo;
    const __nv_bfloat16* Bh = g_whi + (size_t)wsel*C_*C_;
    const __nv_bfloat16* Bl = g_wlo + (size_t)wsel*C_*C_;

    float acc[2][8][4] = {};

    const unsigned STG = 2*128*40*2;   // stage stride in bytes
    const unsigned aHB = su32(sA[0][0]) + (wm*32 + lh*8 + l7)*80 + lq*16;
    const unsigned aLB = su32(sA[0][1]) + (wm*32 + lh*8 + l7)*80 + lq*16;
    const unsigned bHB = su32(sB[0][0]) + (wn*64 + lq*8 + l7)*80 + lh*16;
    const unsigned bLB = su32(sB[0][1]) + (wn*64 + lq*8 + l7)*80 + lh*16;

    // prefetch helper (macro to keep cp.async source addressing simple)
    #define PROJ_PREFETCH(k0, st) do { \
        _Pragma("unroll") \
        for (int r = 0; r < 4; r++) { \
            int s = tid + r*256; \
            int buf = s >> 9, rc = s & 511; \
            int row = rc >> 2, c = rc & 3; \
            unsigned off = row*80 + c*16; \
            const __nv_bfloat16* asrc = (buf ? Al : Ah) + (size_t)(m0g+row)*C_ + (k0) + c*8; \
            const __nv_bfloat16* bsrc = (buf ? Bl : Bh) + (size_t)(o0+row)*C_ + (k0) + c*8; \
            cpasync16(su32(sA[st][buf]) + off, asrc); \
            cpasync16(su32(sB[st][buf]) + off, bsrc); \
        } \
        cp_commit(); \
    } while (0)

    PROJ_PREFETCH(0, 0);

    #pragma unroll 1
    for (int it = 0; it < 16; it++) {
        const int cur = it & 1;
        if (it + 1 < 16) {
            PROJ_PREFETCH((it+1)*32, cur^1);
            cp_wait1();
        } else {
            cp_wait0();
        }
        __syncthreads();

        const unsigned so = cur * STG;
        #pragma unroll
        for (int ks = 0; ks < 2; ks++) {
            const unsigned ko = ks*32;
            unsigned aH[2][4], aL[2][4];
            #pragma unroll
            for (int mi = 0; mi < 2; mi++) {
                ldsm4(aH[mi][0],aH[mi][1],aH[mi][2],aH[mi][3], aHB + so + mi*16*80 + ko);
                ldsm4(aL[mi][0],aL[mi][1],aL[mi][2],aL[mi][3], aLB + so + mi*16*80 + ko);
            }
            #pragma unroll
            for (int nb = 0; nb < 4; nb++) {
                unsigned bH[4], bL[4];
                ldsm4(bH[0],bH[1],bH[2],bH[3], bHB + so + nb*16*80 + ko);
                ldsm4(bL[0],bL[1],bL[2],bL[3], bLB + so + nb*16*80 + ko);
                #pragma unroll
                for (int mi = 0; mi < 2; mi++) {
                    #pragma unroll
                    for (int t = 0; t < 2; t++) {
                        float* c = acc[mi][nb*2+t];
                        mma16816(c, aH[mi][0],aH[mi][1],aH[mi][2],aH[mi][3], bH[t*2],bH[t*2+1]);
                        mma16816(c, aH[mi][0],aH[mi][1],aH[mi][2],aH[mi][3], bL[t*2],bL[t*2+1]);
                        mma16816(c, aL[mi][0],aL[mi][1],aL[mi][2],aL[mi][3], bH[t*2],bH[t*2+1]);
                    }
                }
            }
        }
        __syncthreads();   // protect cur stage before it is refilled
    }
    #undef PROJ_PREFETCH

    const float* bias = wsel==0 ? bq : (wsel==1 ? bk : bv);
    if (wsel < 2) {
        __nv_bfloat16* oh = wsel==0 ? g_qhi : g_khi;
        __nv_bfloat16* ol = wsel==0 ? g_qlo : g_klo;
        #pragma unroll
        for (int mi = 0; mi < 2; mi++) {
            int tr0 = t0 + wm*32 + mi*16 + lg;
            #pragma unroll
            for (int nj = 0; nj < 8; nj++) {
                int o = o0 + wn*64 + nj*8 + tg*2;
                float bi0 = bias[o], bi1 = bias[o+1];
                int hh = o >> 6, d = o & 63;
                size_t base = ((size_t)(b*H_+hh)*T_ + tr0)*D_ + d;
                __nv_bfloat16 h0,l0,h1,l1;
                cv(acc[mi][nj][0]+bi0, h0,l0); cv(acc[mi][nj][1]+bi1, h1,l1);
                *(unsigned*)&oh[base] = pk2(h0,h1);
                *(unsigned*)&ol[base] = pk2(l0,l1);
                cv(acc[mi][nj][2]+bi0, h0,l0); cv(acc[mi][nj][3]+bi1, h1,l1);
                *(unsigned*)&oh[base + 8*D_] = pk2(h0,h1);
                *(unsigned*)&ol[base + 8*D_] = pk2(l0,l1);
            }
        }
    } else {
        #pragma unroll
        for (int mi = 0; mi < 2; mi++) {
            int tr0 = t0 + wm*32 + mi*16 + lg;
            #pragma unroll
            for (int nj = 0; nj < 8; nj++) {
                int o = o0 + wn*64 + nj*8 + tg*2;
                float bi0 = bias[o], bi1 = bias[o+1];
                int hh = o >> 6, d = o & 63;
                size_t base = ((size_t)(b*H_+hh)*D_ + d)*T_ + tr0;
                __nv_bfloat16 h0,l0;
                cv(acc[mi][nj][0]+bi0, h0,l0); g_vhi[base] = h0;      g_vlo[base] = l0;
                cv(acc[mi][nj][1]+bi1, h0,l0); g_vhi[base+T_] = h0;   g_vlo[base+T_] = l0;
                cv(acc[mi][nj][2]+bi0, h0,l0); g_vhi[base+8] = h0;    g_vlo[base+8] = l0;
                cv(acc[mi][nj][3]+bi1, h0,l0); g_vhi[base+T_+8] = h0; g_vlo[base+T_+8] = l0;
            }
        }
    }
}

// =====================================================================
// Output projection tensor GEMM — double-buffered k-loop
// =====================================================================
__global__ __launch_bounds__(256, 2) void outp_gemm(
    const float* __restrict__ bo, const float* __restrict__ mask,
    float* __restrict__ out)
{
    __shared__ __align__(16) __nv_bfloat16 sA[2][2][128*40];
    __shared__ __align__(16) __nv_bfloat16 sB[2][2][128*40];

    const int tid = threadIdx.x, lane = tid & 31, w = tid >> 5;
    const int wm = w & 3, wn = w >> 2;
    const int lg = lane >> 2, tg = lane & 3;
    const int l7 = lane & 7, lh = (lane >> 3) & 1, lq = lane >> 4;

    const int o0 = blockIdx.x * 128;
    const int n0g = blockIdx.y * 128;
    const int b = n0g >> 10, t0 = n0g & 1023;

    const __nv_bfloat16* Ah = g_whi + (size_t)3*C_*C_;
    const __nv_bfloat16* Al = g_wlo + (size_t)3*C_*C_;

    float acc[2][8][4] = {};

    const unsigned STG = 2*128*40*2;
    const unsigned aHB = su32(sA[0][0]) + (wm*32 + lh*8 + l7)*80 + lq*16;
    const unsigned aLB = su32(sA[0][1]) + (wm*32 + lh*8 + l7)*80 + lq*16;
    const unsigned bHB = su32(sB[0][0]) + (wn*64 + lq*8 + l7)*80 + lh*16;
    const unsigned bLB = su32(sB[0][1]) + (wn*64 + lq*8 + l7)*80 + lh*16;

    #define OUTP_PREFETCH(k0, st) do { \
        _Pragma("unroll") \
        for (int r = 0; r < 4; r++) { \
            int s = tid + r*256; \
            int buf = s >> 9, rc = s & 511; \
            int row = rc >> 2, c = rc & 3; \
            unsigned off = row*80 + c*16; \
            const __nv_bfloat16* asrc = (buf ? Al : Ah) + (size_t)(o0+row)*C_ + (k0) + c*8; \
            const __nv_bfloat16* bsrc = (buf ? g_ytlo : g_ythi) + (size_t)(n0g+row)*C_ + (k0) + c*8; \
            cpasync16(su32(sA[st][buf]) + off, asrc); \
            cpasync16(su32(sB[st][buf]) + off, bsrc); \
        } \
        cp_commit(); \
    } while (0)

    OUTP_PREFETCH(0, 0);

    #pragma unroll 1
    for (int it = 0; it < 16; it++) {
        const int cur = it & 1;
        if (it + 1 < 16) {
            OUTP_PREFETCH((it+1)*32, cur^1);
            cp_wait1();
        } else {
            cp_wait0();
        }
        __syncthreads();

        const unsigned so = cur * STG;
        #pragma unroll
        for (int ks = 0; ks < 2; ks++) {
            const unsigned ko = ks*32;
            unsigned aH[2][4], aL[2][4];
            #pragma unroll
            for (int mi = 0; mi < 2; mi++) {
                ldsm4(aH[mi][0],aH[mi][1],aH[mi][2],aH[mi][3], aHB + so + mi*16*80 + ko);
                ldsm4(aL[mi][0],aL[mi][1],aL[mi][2],aL[mi][3], aLB + so + mi*16*80 + ko);
            }
            #pragma unroll
            for (int nb = 0; nb < 4; nb++) {
                unsigned bH[4], bL[4];
                ldsm4(bH[0],bH[1],bH[2],bH[3], bHB + so + nb*16*80 + ko);
                ldsm4(bL[0],bL[1],bL[2],bL[3], bLB + so + nb*16*80 + ko);
                #pragma unroll
                for (int mi = 0; mi < 2; mi++) {
                    #pragma unroll
                    for (int t = 0; t < 2; t++) {
                        float* c = acc[mi][nb*2+t];
                        mma16816(c, aH[mi][0],aH[mi][1],aH[mi][2],aH[mi][3], bH[t*2],bH[t*2+1]);
                        mma16816(c, aH[mi][0],aH[mi][1],aH[mi][2],aH[mi][3], bL[t*2],bL[t*2+1]);
                        mma16816(c, aL[mi][0],aL[mi][1],aL[mi][2],aL[mi][3], bH[t*2],bH[t*2+1]);
                    }
                }
            }
        }
        __syncthreads();
    }
    #undef OUTP_PREFETCH

    #pragma unroll
    for (int mi = 0; mi < 2; mi++) {
        int o = o0 + wm*32 + mi*16 + lg;
        float bi0 = bo[o], bi1 = bo[o+8];
        #pragma unroll
        for (int nj = 0; nj < 8; nj++) {
            int t = t0 + wn*64 + nj*8 + tg*2;
            float m0v = mask[(size_t)b*T_ + t];
            float m1v = mask[(size_t)b*T_ + t + 1];
            float2 v0 = make_float2((acc[mi][nj][0]+bi0)*m0v, (acc[mi][nj][1]+bi0)*m1v);
            float2 v1 = make_float2((acc[mi][nj][2]+bi1)*m0v, (acc[mi][nj][3]+bi1)*m1v);
            *(float2*)&out[((size_t)b*C_ + o)*T_ + t]     = v0;
            *(float2*)&out[((size_t)b*C_ + o + 8)*T_ + t] = v1;
        }
    }
}

// =====================================================================
// Fused attention (unchanged from round 8)
// =====================================================================
__global__ __launch_bounds__(512, 1) void attn_kernel(const float* __restrict__ mask)
{
    extern __shared__ unsigned char smem[];
    __nv_bfloat16* qhi = (__nv_bfloat16*)(smem + OFF_QHI);
    __nv_bfloat16* qlo = (__nv_bfloat16*)(smem + OFF_QLO);
    __nv_bfloat16* khi = (__nv_bfloat16*)(smem + OFF_K);
    __nv_bfloat16* klo = (__nv_bfloat16*)(smem + OFF_K + 18432);
    __nv_bfloat16* vhi = (__nv_bfloat16*)(smem + OFF_V);
    __nv_bfloat16* vlo = (__nv_bfloat16*)(smem + OFF_V + 17408);
    __nv_bfloat16* phi = (__nv_bfloat16*)(smem + OFF_P);
    __nv_bfloat16* plo = (__nv_bfloat16*)(smem + OFF_P + 17408);
    __nv_bfloat16* binhi = (__nv_bfloat16*)(smem + OFF_BINHI);
    __nv_bfloat16* binlo = (__nv_bfloat16*)(smem + OFF_BINLO);
    float* sbin = (float*)(smem + OFF_SBIN);
    float* sqr  = (float*)(smem + OFF_SQR);
    float* smk  = (float*)(smem + OFF_SMK);
    float* sstp = (float*)(smem + OFF_SSTP);
    float* sst  = (float*)(smem + OFF_SST);

    const int tid  = threadIdx.x;
    const int lane = tid & 31;
    const int w    = tid >> 5;
    const int wm   = w & 3;
    const int wg   = w >> 2;
    const int lg   = lane >> 2;
    const int tg   = lane & 3;
    const int r0   = wm*16 + lg;
    const int r1   = r0 + 8;
    const int l7   = lane & 7;
    const int lh   = (lane >> 3) & 1;
    const int lq   = lane >> 4;

    const int i0 = blockIdx.x * 64;
    const int h  = blockIdx.y;
    const int b  = blockIdx.z;
    const size_t headbase = (size_t)(b*H_+h)*T_*D_;

    #pragma unroll
    for (int r = 0; r < 2; r++) {
        int e = tid + r*512;
        int bufi = e >> 9;
        int rc = e & 511;
        int m = rc >> 3, c = rc & 7;
        unsigned dst = su32(bufi ? qlo : qhi) + m*144 + c*16;
        const unsigned char* src =
            (const unsigned char*)(bufi ? g_qlo : g_qhi)
            + (headbase + (size_t)(i0+m)*D_)*2 + c*16;
        cpasync16(dst, src);
    }
    for (int e = tid; e < REL_*8; e += 512) {
        int r = e >> 3, c = e & 7;
        cpasync16(su32(smem + OFF_EKHI) + r*144 + c*16,
                  (const unsigned char*)g_ekhi + (size_t)(r*64 + c*8)*2);
    }
    for (int e = tid; e < REL_*8; e += 512) {
        int r = e >> 3, c = e & 7;
        cpasync16(su32(smem + OFF_EKLO) + r*144 + c*16,
                  (const unsigned char*)g_eklo + (size_t)(r*64 + c*8)*2);
    }
    cp_commit();
    for (int e = tid; e < T_/4; e += 512)
        ((float4*)smk)[e] = ((const float4*)(mask + (size_t)b*T_))[e];
    for (int e = tid; e < 64*132; e += 512)
        sbin[e] = 0.f;
    cp_wait0();
    __syncthreads();

    const unsigned qhiA = su32(qhi) + (unsigned)((wm*16 + lh*8 + l7)*144 + lq*16);
    const unsigned qloA = su32(qlo) + (unsigned)((wm*16 + lh*8 + l7)*144 + lq*16);

    {
        const unsigned ekhiB = su32(smem + OFF_EKHI) + (lq*8 + l7)*144 + lh*16;
        const unsigned ekloB = su32(smem + OFF_EKLO) + (lq*8 + l7)*144 + lh*16;
        float qa[3][2][4] = {};
        const int ng = (wg == 0) ? 3 : 2;
        const int glist[3] = {wg, wg+4, 8};

        #pragma unroll
        for (int ks = 0; ks < 4; ks++) {
            const unsigned ko = ks*32;
            unsigned aH0,aH1,aH2,aH3, aL0,aL1,aL2,aL3;
            ldsm4(aH0,aH1,aH2,aH3, qhiA + ko);
            ldsm4(aL0,aL1,aL2,aL3, qloA + ko);
            for (int gi = 0; gi < ng; gi++) {
                const unsigned ro = glist[gi]*16*144;
                unsigned bH[4], bL[4];
                ldsm4(bH[0],bH[1],bH[2],bH[3], ekhiB + ro + ko);
                ldsm4(bL[0],bL[1],bL[2],bL[3], ekloB + ro + ko);
                #pragma unroll
                for (int t = 0; t < 2; t++) {
                    float* c = qa[gi][t];
                    mma16816(c, aH0,aH1,aH2,aH3, bH[t*2],bH[t*2+1]);
                    mma16816(c, aH0,aH1,aH2,aH3, bL[t*2],bL[t*2+1]);
                    mma16816(c, aL0,aL1,aL2,aL3, bH[t*2],bH[t*2+1]);
                }
            }
        }
        for (int gi = 0; gi < ng; gi++) {
            #pragma unroll
            for (int t = 0; t < 2; t++) {
                int col = glist[gi]*16 + t*8 + tg*2;
                if (col < 136) {
                    *(float2*)&sqr[r0*136 + col] = make_float2(qa[gi][t][0], qa[gi][t][1]);
                    *(float2*)&sqr[r1*136 + col] = make_float2(qa[gi][t][2], qa[gi][t][3]);
                }
            }
        }
    }
    __syncthreads();

    const float qrM0 = sqr[r0*136];       const float qrP0 = sqr[r0*136 + 128];
    const float qrM1 = sqr[r1*136];       const float qrP1 = sqr[r1*136 + 128];

    const float scale = 0.125f;
    float yacc[2][4] = {};
    float ls0=0.f, ls1=0.f, ea0=0.f, ea1=0.f, eb0=0.f, eb1=0.f;

    const unsigned khiB0 = su32(khi) + (unsigned)((wg*32 + lq*8 + l7)*144 + lh*16);
    const unsigned kloB0 = su32(klo) + (unsigned)((wg*32 + lq*8 + l7)*144 + lh*16);
    const unsigned phiA = su32(phi) + (unsigned)((wm*16 + lh*8 + l7)*272 + lq*16);
    const unsigned ploA = su32(plo) + (unsigned)((wm*16 + lh*8 + l7)*272 + lq*16);
    const unsigned vhiB = su32(vhi) + (unsigned)((wg*8 + lq*32 + l7)*272 + lh*16);
    const unsigned vloB = su32(vlo) + (unsigned)((wg*8 + lq*32 + l7)*272 + lh*16);

    for (int kt = 0; kt < 8; kt++) {
        const int j0g = kt * 128;
        const int relbase = j0g - i0;
        const bool fastHi = (relbase >= 127);
        const bool fastLo = (relbase <= -191);
        __syncthreads();
        #pragma unroll
        for (int r = 0; r < 4; r++) {
            int e = tid + r*512;
            int bufi = e >> 10;
            int rc = e & 1023;
            int j = rc >> 3, c = rc & 7;
            unsigned dst = su32(bufi ? klo : khi) + j*144 + c*16;
            const unsigned char* src =
                (const unsigned char*)(bufi ? g_klo : g_khi)
                + (headbase + (size_t)(j0g+j)*D_)*2 + c*16;
            cpasync16(dst, src);
        }
        cp_commit();
        #pragma unroll
        for (int r = 0; r < 4; r++) {
            int e = tid + r*512;
            int bufi = e >> 10;
            int rc = e & 1023;
            int d = rc >> 4, c = rc & 15;
            unsigned dst = su32(bufi ? vlo : vhi) + d*272 + c*16;
            const unsigned char* src =
                (const unsigned char*)(bufi ? g_vlo : g_vhi)
                + (headbase + (size_t)d*T_ + j0g)*2 + c*16;
            cpasync16(dst, src);
        }
        cp_commit();
        cp_wait1();
        __syncthreads();

        float sacc[4][4] = {};
        #pragma unroll
        for (int ks = 0; ks < 4; ks++) {
            const unsigned ko = ks*32;
            unsigned aH0,aH1,aH2,aH3, aL0,aL1,aL2,aL3;
            ldsm4(aH0,aH1,aH2,aH3, qhiA + ko);
            ldsm4(aL0,aL1,aL2,aL3, qloA + ko);
            unsigned bH[8], bL[8];
            ldsm4(bH[0],bH[1],bH[2],bH[3], khiB0 + ko);
            ldsm4(bH[4],bH[5],bH[6],bH[7], khiB0 + 16*144 + ko);
            ldsm4(bL[0],bL[1],bL[2],bL[3], kloB0 + ko);
            ldsm4(bL[4],bL[5],bL[6],bL[7], kloB0 + 16*144 + ko);
            #pragma unroll
            for (int t = 0; t < 4; t++) {
                unsigned b0h = bH[t*2], b1h = bH[t*2+1];
                unsigned b0l = bL[t*2], b1l = bL[t*2+1];
                mma16816(sacc[t], aH0,aH1,aH2,aH3, b0h,b1h);
                mma16816(sacc[t], aH0,aH1,aH2,aH3, b0l,b1l);
                mma16816(sacc[t], aL0,aL1,aL2,aL3, b0h,b1h);
            }
        }

        if (fastHi || fastLo) {
            const float c0 = fastHi ? qrP0 : qrM0;
            const float c1 = fastHi ? qrP1 : qrM1;
            float acc0 = 0.f, acc1 = 0.f;
            #pragma unroll
            for (int t = 0; t < 4; t++) {
                const int cb = wg*32 + t*8 + tg*2;
                #pragma unroll
                for (int ii = 0; ii < 2; ii++) {
                    const int rr = ii ? r1 : r0;
                    const float cc = ii ? c1 : c0;
                    float ev[2];
                    #pragma unroll
                    for (int jj = 0; jj < 2; jj++) {
                        int gj = j0g + cb + jj;
                        float s = sacc[t][ii*2+jj]*scale + cc;
                        if (smk[gj] <= 0.f) s = -1e9f;
                        float e = __expf(s);
                        if (ii == 0) acc0 += e; else acc1 += e;
                        ev[jj] = e;
                    }
                    __nv_bfloat16 eh0,el0,eh1,el1;
                    cv(ev[0],eh0,el0); cv(ev[1],eh1,el1);
                    *(unsigned*)&phi[rr*136 + cb] = pk2(eh0,eh1);
                    *(unsigned*)&plo[rr*136 + cb] = pk2(el0,el1);
                }
            }
            ls0 += acc0; ls1 += acc1;
            if (fastHi) { eb0 += acc0; eb1 += acc1; }
            else        { ea0 += acc0; ea1 += acc1; }
        } else {
            #pragma unroll
            for (int t = 0; t < 4; t++) {
                const int cb = wg*32 + t*8 + tg*2;
                #pragma unroll
                for (int ii = 0; ii < 2; ii++) {
                    const int rr = ii ? r1 : r0;
                    const int gi = i0 + rr;
                    float ev[2];
                    #pragma unroll
                    for (int jj = 0; jj < 2; jj++) {
                        int gj = j0g + cb + jj;
                        int rel = gj - gi;
                        int relc = rel < -64 ? -64 : (rel > 64 ? 64 : rel);
                        float s = sacc[t][ii*2+jj]*scale + sqr[rr*136 + relc + 64];
                        if (smk[gj] <= 0.f) s = -1e9f;
                        float e = __expf(s);
                        if (ii == 0) ls0 += e; else ls1 += e;
                        if (rel <= -64)      { if (ii == 0) ea0 += e; else ea1 += e; }
                        else if (rel >= 64)  { if (ii == 0) eb0 += e; else eb1 += e; }
                        else                 sbin[rr*132 + rel + 64] = e;
                        ev[jj] = e;
                    }
                    __nv_bfloat16 eh0,el0,eh1,el1;
                    cv(ev[0],eh0,el0); cv(ev[1],eh1,el1);
                    *(unsigned*)&phi[rr*136 + cb] = pk2(eh0,eh1);
                    *(unsigned*)&plo[rr*136 + cb] = pk2(el0,el1);
                }
            }
        }
        cp_wait0();
        __syncthreads();

        #pragma unroll
        for (int ks = 0; ks < 8; ks++) {
            const unsigned ko = ks*32;
            unsigned aH0,aH1,aH2,aH3, aL0,aL1,aL2,aL3;
            ldsm4(aH0,aH1,aH2,aH3, phiA + ko);
            ldsm4(aL0,aL1,aL2,aL3, ploA + ko);
            unsigned bH[4], bL[4];
            ldsm4(bH[0],bH[1],bH[2],bH[3], vhiB + ko);
            ldsm4(bL[0],bL[1],bL[2],bL[3], vloB + ko);
            #pragma unroll
            for (int ti = 0; ti < 2; ti++) {
                unsigned b0h = bH[ti*2], b1h = bH[ti*2+1];
                unsigned b0l = bL[ti*2], b1l = bL[ti*2+1];
                mma16816(yacc[ti], aH0,aH1,aH2,aH3, b0h,b1h);
                mma16816(yacc[ti], aH0,aH1,aH2,aH3, b0l,b1l);
                mma16816(yacc[ti], aL0,aL1,aL2,aL3, b0h,b1h);
            }
        }
    }
    __syncthreads();

    for (int e = tid; e < 64*18; e += 512) {
        int d = e/18, c = e - d*18;
        cpasync16(su32(smem + OFF_EVHI) + d*304 + c*16,
                  (const unsigned char*)g_evhi + (size_t)(d*144 + c*8)*2);
    }
    for (int e = tid; e < 64*18; e += 512) {
        int d = e/18, c = e - d*18;
        cpasync16(su32(smem + OFF_EVLO) + d*304 + c*16,
                  (const unsigned char*)g_evlo + (size_t)(d*144 + c*8)*2);
    }
    cp_commit();

    {
        float v;
        #define RED_(x) v = x; v += __shfl_xor_sync(~0u, v, 1); v += __shfl_xor_sync(~0u, v, 2); x = v;
        RED_(ls0) RED_(ls1) RED_(ea0) RED_(ea1) RED_(eb0) RED_(eb1)
        #undef RED_
        if (tg == 0) {
            sstp[0*256 + wg*64 + r0] = ls0;  sstp[0*256 + wg*64 + r1] = ls1;
            sstp[1*256 + wg*64 + r0] = ea0;  sstp[1*256 + wg*64 + r1] = ea1;
            sstp[2*256 + wg*64 + r0] = eb0;  sstp[2*256 + wg*64 + r1] = eb1;
        }
    }
    __syncthreads();
    if (tid < 64) {
        float l = 0.f, a = 0.f, c = 0.f;
        #pragma unroll
        for (int g = 0; g < 4; g++) {
            l += sstp[0*256 + g*64 + tid];
            a += sstp[1*256 + g*64 + tid];
            c += sstp[2*256 + g*64 + tid];
        }
        sst[tid] = l;
        sbin[tid*132]       = a;
        sbin[tid*132 + 128] = c;
    }
    __syncthreads();

    for (int e = tid; e < 64*144; e += 512) {
        int m = e/144, c = e - m*144;
        float v = (c < REL_) ? sbin[m*132 + c] : 0.f;
        __nv_bfloat16 hh, ll;
        cv(v, hh, ll);
        binhi[m*152 + c] = hh;
        binlo[m*152 + c] = ll;
    }
    cp_wait0();
    __syncthreads();

    {
        const unsigned binA  = su32(smem + OFF_BINHI) + (wm*16 + lh*8 + l7)*304 + lq*16;
        const unsigned binAl = su32(smem + OFF_BINLO) + (wm*16 + lh*8 + l7)*304 + lq*16;
        const unsigned evB   = su32(smem + OFF_EVHI)  + (wg*8 + lq*32 + l7)*304 + lh*16;
        const unsigned evBl  = su32(smem + OFF_EVLO)  + (wg*8 + lq*32 + l7)*304 + lh*16;
        #pragma unroll
        for (int ks = 0; ks < 9; ks++) {
            const unsigned ko = ks*32;
            unsigned aH0,aH1,aH2,aH3, aL0,aL1,aL2,aL3;
            ldsm4(aH0,aH1,aH2,aH3, binA + ko);
            ldsm4(aL0,aL1,aL2,aL3, binAl + ko);
            unsigned bH[4], bL[4];
            ldsm4(bH[0],bH[1],bH[2],bH[3], evB + ko);
            ldsm4(bL[0],bL[1],bL[2],bL[3], evBl + ko);
            #pragma unroll
            for (int ti = 0; ti < 2; ti++) {
                unsigned b0h = bH[ti*2], b1h = bH[ti*2+1];
                unsigned b0l = bL[ti*2], b1l = bL[ti*2+1];
                mma16816(yacc[ti], aH0,aH1,aH2,aH3, b0h,b1h);
                mma16816(yacc[ti], aH0,aH1,aH2,aH3, b0l,b1l);
                mma16816(yacc[ti], aL0,aL1,aL2,aL3, b0h,b1h);
            }
        }
    }

    {
        const float inv0 = 1.f / sst[r0];
        const float inv1 = 1.f / sst[r1];
        const int dA = wg*8 + tg*2;
        const int dB = dA + 32;
        const int cbase = h*64;
        size_t tb0 = ((size_t)b*T_ + i0 + r0)*C_;
        size_t tb1 = ((size_t)b*T_ + i0 + r1)*C_;
        __nv_bfloat16 h0,l0,h1,l1;
        cv(yacc[0][0]*inv0,h0,l0); cv(yacc[0][1]*inv0,h1,l1);
        *(unsigned*)&g_ythi[tb0 + cbase + dA] = pk2(h0,h1);
        *(unsigned*)&g_ytlo[tb0 + cbase + dA] = pk2(l0,l1);
        cv(yacc[0][2]*inv1,h0,l0); cv(yacc[0][3]*inv1,h1,l1);
        *(unsigned*)&g_ythi[tb1 + cbase + dA] = pk2(h0,h1);
        *(unsigned*)&g_ytlo[tb1 + cbase + dA] = pk2(l0,l1);
        cv(yacc[1][0]*inv0,h0,l0); cv(yacc[1][1]*inv0,h1,l1);
        *(unsigned*)&g_ythi[tb0 + cbase + dB] = pk2(h0,h1);
        *(unsigned*)&g_ytlo[tb0 + cbase + dB] = pk2(l0,l1);
        cv(yacc[1][2]*inv1,h0,l0); cv(yacc[1][3]*inv1,h1,l1);
        *(unsigned*)&g_ythi[tb1 + cbase + dB] = pk2(h0,h1);
        *(unsigned*)&g_ytlo[tb1 + cbase + dB] = pk2(l0,l1);
    }
}

// =====================================================================
extern "C" void kernel_launch(void* const* d_in, const int* in_sizes, int n_in,
                              void* d_out, int out_size)
{
    const float* x     = (const float*)d_in[0];
    const float* xmask = (const float*)d_in[1];
    const float* Wq    = (const float*)d_in[2];
    const float* bq    = (const float*)d_in[3];
    const float* Wk    = (const float*)d_in[4];
    const float* bk    = (const float*)d_in[5];
    const float* Wv    = (const float*)d_in[6];
    const float* bv    = (const float*)d_in[7];
    const float* Wo    = (const float*)d_in[8];
    const float* bo    = (const float*)d_in[9];
    const float* erelk = (const float*)d_in[10];
    const float* erelv = (const float*)d_in[11];
    float* out = (float*)d_out;

    cudaFuncSetAttribute(attn_kernel,
                         cudaFuncAttributeMaxDynamicSharedMemorySize, SMEM_BYTES);

    conv_x<<<dim3(T_/32, C_/32, B_), 256>>>(x);
    conv_w<<<dim3(C_*C_/256, 4), 256>>>(Wq, Wk, Wv, Wo);
    conv_erel<<<36, 256>>>(erelk, erelv);

    proj_fused<<<dim3(64, 12), 256>>>(bq, bk, bv);

    attn_kernel<<<dim3(16, H_, B_), 512, SMEM_BYTES>>>(xmask);

    outp_gemm<<<dim3(4, 64), 256>>>(bo, xmask, out);
}

// round 11
// speedup vs baseline: 4.5268x; 1.0602x over previous
#include <cuda_runtime.h>
#include <cuda_bf16.h>
#include <cstdint>

#define B_ 8
#define C_ 512
#define T_ 1024
#define H_ 8
#define D_ 64
#define REL_ 129

// Feature gate: tcgen05 only exists in 'a'-suffixed device passes.
#if defined(__CUDA_ARCH_FEAT_SM103_ALL) || defined(__CUDA_ARCH_FEAT_SM100_ALL) || defined(__CUDA_ARCH_FEAT_SM101_ALL)
#define HAS_TCGEN05 1
#else
#define HAS_TCGEN05 0
#endif

// ---------------- scratch (no cudaMalloc allowed) ----------------
__device__ __nv_bfloat16 g_xthi[B_*T_*C_];    // x^T (B,T,C) hi
__device__ __nv_bfloat16 g_xtlo[B_*T_*C_];
__device__ __nv_bfloat16 g_whi[4*C_*C_];      // Wq,Wk,Wv,Wo hi
__device__ __nv_bfloat16 g_wlo[4*C_*C_];
__device__ __nv_bfloat16 g_qhi[B_*H_*T_*D_];  // (B,H,T,D)
__device__ __nv_bfloat16 g_qlo[B_*H_*T_*D_];
__device__ __nv_bfloat16 g_khi[B_*H_*T_*D_];
__device__ __nv_bfloat16 g_klo[B_*H_*T_*D_];
__device__ __nv_bfloat16 g_vhi[B_*H_*T_*D_];  // (B,H,D,T)
__device__ __nv_bfloat16 g_vlo[B_*H_*T_*D_];
__device__ __nv_bfloat16 g_ythi[B_*T_*C_];    // y^T (B,T,C)
__device__ __nv_bfloat16 g_ytlo[B_*T_*C_];
__device__ __nv_bfloat16 g_ekhi[REL_*D_];     // erel_k [129][64]
__device__ __nv_bfloat16 g_eklo[REL_*D_];
__device__ __nv_bfloat16 g_evhi[D_*144];      // erel_v^T [64][144] (zero-padded)
__device__ __nv_bfloat16 g_evlo[D_*144];

// ---------------- attn shared memory (byte offsets), 64-query CTA ----------------
#define OFF_QHI   0
#define OFF_QLO   9216
#define OFF_K     18432
#define OFF_V     55296
#define OFF_P     90112
#define OFF_SBIN  124928
#define OFF_SQR   158720
#define OFF_SMK   193536
#define OFF_SSTP  197632
#define OFF_SST   200704
#define SMEM_BYTES 201472
#define OFF_EKHI  18432
#define OFF_EKLO  39168
#define OFF_BINHI 18432
#define OFF_BINLO 37888
#define OFF_EVHI  57344
#define OFF_EVLO  76800

// ---------------- proj shared memory ----------------
// fallback layout: sA [stage][buf][128*40] at 0 (40960B), sB at 40960 (40960B)
// tcgen05 layout: tmemptr@0, mbar@8, AH@1024, AL@17408, BH@33792, BL@50176
#define PJ_SMEM 81920
#define PT_TMEM 0
#define PT_MBAR 8
#define PT_AH   1024
#define PT_AL   (PT_AH+16384)
#define PT_BH   (PT_AL+16384)
#define PT_BL   (PT_BH+16384)
#define IDESC_P 0x8100490u   // kind::f16: F32 acc, BF16xBF16, M=128, N=64

// ---------------- helpers ----------------
__device__ __forceinline__ unsigned pk2(__nv_bfloat16 a, __nv_bfloat16 b) {
    __nv_bfloat162 t = __halves2bfloat162(a, b);
    return *reinterpret_cast<unsigned*>(&t);
}
__device__ __forceinline__ void cv(float x, __nv_bfloat16& h, __nv_bfloat16& l) {
    h = __float2bfloat16(x);
    l = __float2bfloat16(x - __bfloat162float(h));
}
__device__ __forceinline__ unsigned su32(const void* p) {
    return (unsigned)__cvta_generic_to_shared(p);
}
__device__ __forceinline__ void cpasync16(unsigned s, const void* g) {
    asm volatile("cp.async.cg.shared.global [%0], [%1], 16;" :: "r"(s), "l"(g));
}
__device__ __forceinline__ void cp_commit() {
    asm volatile("cp.async.commit_group;" ::: "memory");
}
__device__ __forceinline__ void cp_wait0() {
    asm volatile("cp.async.wait_group 0;" ::: "memory");
}
__device__ __forceinline__ void cp_wait1() {
    asm volatile("cp.async.wait_group 1;" ::: "memory");
}
__device__ __forceinline__ void ldsm4(unsigned& r0, unsigned& r1, unsigned& r2,
                                      unsigned& r3, unsigned addr) {
    asm volatile("ldmatrix.sync.aligned.m8n8.x4.shared.b16 {%0,%1,%2,%3}, [%4];"
                 : "=r"(r0), "=r"(r1), "=r"(r2), "=r"(r3) : "r"(addr));
}
__device__ __forceinline__ void mma16816(float* c, unsigned a0, unsigned a1,
                                         unsigned a2, unsigned a3,
                                         unsigned b0, unsigned b1) {
    asm volatile(
        "mma.sync.aligned.m16n8k16.row.col.f32.bf16.bf16.f32 "
        "{%0,%1,%2,%3}, {%4,%5,%6,%7}, {%8,%9}, {%0,%1,%2,%3};"
        : "+f"(c[0]), "+f"(c[1]), "+f"(c[2]), "+f"(c[3])
        : "r"(a0), "r"(a1), "r"(a2), "r"(a3), "r"(b0), "r"(b1));
}

#if HAS_TCGEN05
// ---- tcgen05 machinery (HW-verified example patterns) ----
__device__ __forceinline__ uint32_t elect_one_pred() {
    uint32_t pred;
    asm volatile(
        "{\n\t.reg .pred p;\n\t"
        "elect.sync _|p, 0xFFFFFFFF;\n\t"
        "selp.b32 %0, 1, 0, p;\n\t}"
        : "=r"(pred));
    return pred;
}
static constexpr uint64_t SMEM_DESC_BASE_SW128 =
    (uint64_t(2)  << 61) | (uint64_t(1) << 46) | (uint64_t(64) << 32) | (uint64_t(1) << 16);
#define MAKE_SMEM_DESC(base_addr) \
    (SMEM_DESC_BASE_SW128 | ((uint64_t)((base_addr) >> 4) & 0x3FFF))
#define TCGEN05_ALLOC(smem_result_addr, nCols) \
    asm volatile("tcgen05.alloc.cta_group::1.sync.aligned.shared::cta.b32 [%0], %1;" \
        :: "r"((uint32_t)(smem_result_addr)), "r"((uint32_t)(nCols)) : "memory")
#define TCGEN05_DEALLOC(tmem_addr, nCols) \
    asm volatile("tcgen05.dealloc.cta_group::1.sync.aligned.b32 %0, %1;" \
        :: "r"(tmem_addr), "r"((uint32_t)(nCols)))
#define TCGEN05_COMMIT(mbar_smem_addr) \
    asm volatile("tcgen05.commit.cta_group::1.mbarrier::arrive::one.shared::cluster.b64 [%0];" \
        :: "r"((uint32_t)(mbar_smem_addr)) : "memory")
#define TCGEN05_FENCE_BEFORE() \
    asm volatile("tcgen05.fence::before_thread_sync;" ::: "memory")
#define TCGEN05_FENCE_AFTER() \
    asm volatile("tcgen05.fence::after_thread_sync;" ::: "memory")
#define TCGEN05_WAIT_LD() \
    asm volatile("tcgen05.wait::ld.sync.aligned;" ::: "memory")
#define FENCE_PROXY_ASYNC_SHARED_CTA() \
    asm volatile("fence.proxy.async.shared::cta;" ::: "memory")
#define TCGEN05_LD_32X32B_X32(r, tmem_addr) \
    asm volatile( \
        "tcgen05.ld.sync.aligned.32x32b.x32.b32 " \
        "{%0, %1, %2, %3, %4, %5, %6, %7, " \
        " %8, %9, %10, %11, %12, %13, %14, %15, " \
        " %16, %17, %18, %19, %20, %21, %22, %23, " \
        " %24, %25, %26, %27, %28, %29, %30, %31}, [%32];" \
        : "=r"((r)[0]),  "=r"((r)[1]),  "=r"((r)[2]),  "=r"((r)[3]), \
          "=r"((r)[4]),  "=r"((r)[5]),  "=r"((r)[6]),  "=r"((r)[7]), \
          "=r"((r)[8]),  "=r"((r)[9]),  "=r"((r)[10]), "=r"((r)[11]), \
          "=r"((r)[12]), "=r"((r)[13]), "=r"((r)[14]), "=r"((r)[15]), \
          "=r"((r)[16]), "=r"((r)[17]), "=r"((r)[18]), "=r"((r)[19]), \
          "=r"((r)[20]), "=r"((r)[21]), "=r"((r)[22]), "=r"((r)[23]), \
          "=r"((r)[24]), "=r"((r)[25]), "=r"((r)[26]), "=r"((r)[27]), \
          "=r"((r)[28]), "=r"((r)[29]), "=r"((r)[30]), "=r"((r)[31]) \
        : "r"(tmem_addr))
__device__ __forceinline__ void tcg_f16_ss(uint32_t d_tmem, uint64_t a_desc,
                                           uint64_t b_desc, uint32_t idesc, bool acc)
{
    uint32_t en = acc ? 1u : 0u;
    asm volatile(
        "{\n\t.reg .pred p;\n\t"
        "setp.ne.u32 p, %5, 0;\n\t"
        "tcgen05.mma.cta_group::1.kind::f16 [%0], %1, %2, %3, {%4,%4,%4,%4}, p;\n\t}"
        :: "r"(d_tmem), "l"(a_desc), "l"(b_desc), "r"(idesc), "r"(0u), "r"(en)
        : "memory");
}
#endif // HAS_TCGEN05

// mbarrier wait (base-arch legal, sm_90+)
#define MBARRIER_INIT(mbar_smem_addr, count) \
    asm volatile("mbarrier.init.shared.b64 [%0], %1;" \
        :: "r"((uint32_t)(mbar_smem_addr)), "r"((uint32_t)(count)) : "memory")
#define MBARRIER_WAIT_PARITY(mbar_smem_addr, phase_parity) do { \
    uint32_t _mbar = (uint32_t)(mbar_smem_addr); \
    uint32_t _parity = (uint32_t)(phase_parity); \
    uint32_t _done; \
    asm volatile( \
        "{\n\t.reg .pred p;\n\t" \
        "mbarrier.try_wait.parity.acquire.cta.shared::cta.b64 p, [%1], %2;\n\t" \
        "selp.b32 %0, 1, 0, p;\n\t}" \
        : "=r"(_done) : "r"(_mbar), "r"(_parity) : "memory"); \
    if (!_done) { \
        asm volatile( \
            "{\n\t.reg .pred P1;\n\t" \
            "WAIT_LOOP_%=:\n\t" \
            "mbarrier.try_wait.parity.acquire.cta.shared::cta.b64 P1, [%0], %1, 0x989680;\n\t" \
            "@P1 bra.uni WAIT_DONE_%=;\n\t" \
            "bra.uni WAIT_LOOP_%=;\n\t" \
            "WAIT_DONE_%=:\n\t}" \
            :: "r"(_mbar), "r"(_parity) : "memory"); \
    } \
} while(0)

// =====================================================================
// prep kernels (unchanged)
// =====================================================================
__global__ __launch_bounds__(256) void conv_x(const float* __restrict__ x)
{
    __shared__ float s[32][33];
    const int b = blockIdx.z, c0 = blockIdx.y*32, t0 = blockIdx.x*32;
    const int tx = threadIdx.x & 31, ty = threadIdx.x >> 5;
    #pragma unroll
    for (int r = 0; r < 4; r++) {
        int c = ty + r*8;
        s[c][tx] = x[((size_t)b*C_ + c0 + c)*T_ + t0 + tx];
    }
    __syncthreads();
    #pragma unroll
    for (int r = 0; r < 4; r++) {
        int t = ty + r*8;
        float v = s[tx][t];
        __nv_bfloat16 h, l;
        cv(v, h, l);
        size_t idx = ((size_t)b*T_ + t0 + t)*C_ + c0 + tx;
        g_xthi[idx] = h;
        g_xtlo[idx] = l;
    }
}

__global__ __launch_bounds__(256) void conv_w(
    const float* __restrict__ w0, const float* __restrict__ w1,
    const float* __restrict__ w2, const float* __restrict__ w3)
{
    const int g = blockIdx.y;
    const float* W = g==0 ? w0 : g==1 ? w1 : g==2 ? w2 : w3;
    int idx = blockIdx.x*256 + threadIdx.x;
    float v = W[idx];
    __nv_bfloat16 h, l;
    cv(v, h, l);
    g_whi[(size_t)g*C_*C_ + idx] = h;
    g_wlo[(size_t)g*C_*C_ + idx] = l;
}

__global__ __launch_bounds__(256) void conv_erel(
    const float* __restrict__ erelk, const float* __restrict__ erelv)
{
    int idx = blockIdx.x*256 + threadIdx.x;
    if (idx < REL_*D_) {
        __nv_bfloat16 h, l;
        cv(erelk[idx], h, l);
        g_ekhi[idx] = h; g_eklo[idx] = l;
    }
    if (idx < D_*144) {
        int d = idx / 144, r = idx - d*144;
        float v = (r < REL_) ? erelv[r*D_ + d] : 0.f;
        __nv_bfloat16 h, l;
        cv(v, h, l);
        g_evhi[idx] = h; g_evlo[idx] = l;
    }
}

// =====================================================================
// QKV projection — dual body: tcgen05 SS (if arch-feature pass exists),
// else the proven double-buffered mma.sync path. Same launch config.
// =====================================================================
__global__ __launch_bounds__(256, 2) void proj_any(
    const float* __restrict__ bq, const float* __restrict__ bk,
    const float* __restrict__ bv)
{
    extern __shared__ unsigned char smem[];
    const int tid = threadIdx.x, lane = tid & 31, w = tid >> 5;

    const int ny = blockIdx.y;
    const int wsel = ny >> 2;
    const int o0 = (ny & 3) * 128;
    const int m0g = blockIdx.x * 128;
    const int b = m0g >> 10, t0 = m0g & 1023;

    const __nv_bfloat16* Bh = g_whi + (size_t)wsel*C_*C_;
    const __nv_bfloat16* Bl = g_wlo + (size_t)wsel*C_*C_;
    const float* bias = wsel==0 ? bq : (wsel==1 ? bk : bv);

#if HAS_TCGEN05
    // ----------------- tcgen05 SS path -----------------
    const uint32_t sb = su32(smem);
    if (w == 0) TCGEN05_ALLOC(sb + PT_TMEM, 128);
    if (tid == 0) MBARRIER_INIT(sb + PT_MBAR, 1);
    __syncthreads();
    uint32_t tmem;
    asm volatile("ld.shared.b32 %0, [%1];" : "=r"(tmem) : "r"(sb + PT_TMEM));

    const uint64_t dAh = MAKE_SMEM_DESC(sb + PT_AH);
    const uint64_t dAl = MAKE_SMEM_DESC(sb + PT_AL);
    const uint64_t dBh = MAKE_SMEM_DESC(sb + PT_BH);
    const uint64_t dBl = MAKE_SMEM_DESC(sb + PT_BL);

    for (int kt = 0; kt < 8; kt++) {
        if (kt > 0) MBARRIER_WAIT_PARITY(sb + PT_MBAR, (kt-1) & 1);
        __syncthreads();
        const int kc0 = kt * 64;
        // stage 4 tiles [128 rows][64 bf16] SW128-swizzled
        #pragma unroll
        for (int r = 0; r < 16; r++) {
            int e = tid + r*256;
            int tile = e >> 10;
            int rc = e & 1023;
            int row = rc >> 3, c = rc & 7;
            unsigned dstoff = (unsigned)((row>>3)*1024 + (row&7)*128 + ((c ^ (row&7))*16));
            unsigned dst;
            const __nv_bfloat16* src;
            if (tile == 0)      { dst = sb+PT_AH+dstoff; src = g_xthi + (size_t)(m0g+row)*C_ + kc0 + c*8; }
            else if (tile == 1) { dst = sb+PT_AL+dstoff; src = g_xtlo + (size_t)(m0g+row)*C_ + kc0 + c*8; }
            else if (tile == 2) { dst = sb+PT_BH+dstoff; src = Bh + (size_t)(o0+row)*C_ + kc0 + c*8; }
            else                { dst = sb+PT_BL+dstoff; src = Bl + (size_t)(o0+row)*C_ + kc0 + c*8; }
            cpasync16(dst, src);
        }
        cp_commit();
        cp_wait0();
        __syncthreads();
        FENCE_PROXY_ASYNC_SHARED_CTA();

        if (w == 0) {
            if (elect_one_pred()) {
                #pragma unroll
                for (int n2 = 0; n2 < 2; n2++) {
                    const uint64_t bo_ = (uint64_t)(n2 * 512);  // +64 B-rows = 8 atoms
                    const uint32_t dt = tmem + n2 * 64;
                    #pragma unroll
                    for (int s = 0; s < 4; s++) {
                        const bool first = (kt == 0 && s == 0);
                        tcg_f16_ss(dt, dAh + s*2, dBh + bo_ + s*2, IDESC_P, !first);
                        tcg_f16_ss(dt, dAh + s*2, dBl + bo_ + s*2, IDESC_P, true);
                        tcg_f16_ss(dt, dAl + s*2, dBh + bo_ + s*2, IDESC_P, true);
                    }
                }
                TCGEN05_COMMIT(sb + PT_MBAR);
            }
        }
    }
    MBARRIER_WAIT_PARITY(sb + PT_MBAR, 1);
    TCGEN05_FENCE_AFTER();

    const int mrow = (w & 3)*32 + lane;
    const int cbase = (w >> 2)*64;
    uint32_t dr[64];
    TCGEN05_LD_32X32B_X32(dr, tmem + cbase);
    TCGEN05_LD_32X32B_X32(dr + 32, tmem + cbase + 32);
    TCGEN05_WAIT_LD();
    TCGEN05_FENCE_BEFORE();

    const int t = t0 + mrow;
    if (wsel < 2) {
        __nv_bfloat16* oh = wsel==0 ? g_qhi : g_khi;
        __nv_bfloat16* ol = wsel==0 ? g_qlo : g_klo;
        #pragma unroll
        for (int n = 0; n < 64; n += 2) {
            int o = o0 + cbase + n;
            int hh = o >> 6, d = o & 63;
            float v0 = __uint_as_float(dr[n])   + bias[o];
            float v1 = __uint_as_float(dr[n+1]) + bias[o+1];
            __nv_bfloat16 h0,l0,h1,l1;
            cv(v0,h0,l0); cv(v1,h1,l1);
            size_t idx = ((size_t)(b*H_+hh)*T_ + t)*D_ + d;
            *(unsigned*)&oh[idx] = pk2(h0,h1);
            *(unsigned*)&ol[idx] = pk2(l0,l1);
        }
    } else {
        #pragma unroll
        for (int n = 0; n < 64; n++) {
            int o = o0 + cbase + n;
            int hh = o >> 6, d = o & 63;
            float v = __uint_as_float(dr[n]) + bias[o];
            __nv_bfloat16 h0,l0;
            cv(v,h0,l0);
            size_t idx = ((size_t)(b*H_+hh)*D_ + d)*T_ + t;
            g_vhi[idx] = h0;
            g_vlo[idx] = l0;
        }
    }
    __syncthreads();
    if (w == 0) TCGEN05_DEALLOC(tmem, 128);

#else
    // ----------------- fallback: double-buffered mma.sync (round-9) -----------------
    const int wm = w & 3, wn = w >> 2;
    const int lg = lane >> 2, tg = lane & 3;
    const int l7 = lane & 7, lh = (lane >> 3) & 1, lq = lane >> 4;

    const unsigned SBASE = su32(smem);
    const unsigned STG = 20480;   // stage stride bytes (2 bufs x 10240)

    float acc[2][8][4] = {};

    const unsigned aHB = SBASE + (wm*32 + lh*8 + l7)*80 + lq*16;
    const unsigned aLB = aHB + 10240;
    const unsigned bHB = SBASE + 40960 + (wn*64 + lq*8 + l7)*80 + lh*16;
    const unsigned bLB = bHB + 10240;

    #define PROJ_PREFETCH(k0, st) do { \
        _Pragma("unroll") \
        for (int r = 0; r < 4; r++) { \
            int s = tid + r*256; \
            int buf = s >> 9, rc = s & 511; \
            int row = rc >> 2, c = rc & 3; \
            unsigned off = (st)*STG + buf*10240 + row*80 + c*16; \
            const __nv_bfloat16* asrc = (buf ? g_xtlo : g_xthi) + (size_t)(m0g+row)*C_ + (k0) + c*8; \
            const __nv_bfloat16* bsrc = (buf ? Bl : Bh) + (size_t)(o0+row)*C_ + (k0) + c*8; \
            cpasync16(SBASE + off, asrc); \
            cpasync16(SBASE + 40960 + off, bsrc); \
        } \
        cp_commit(); \
    } while (0)

    PROJ_PREFETCH(0, 0);

    #pragma unroll 1
    for (int it = 0; it < 16; it++) {
        const int cur = it & 1;
        if (it + 1 < 16) {
            PROJ_PREFETCH((it+1)*32, cur^1);
            cp_wait1();
        } else {
            cp_wait0();
        }
        __syncthreads();

        const unsigned so = cur * STG;
        #pragma unroll
        for (int ks = 0; ks < 2; ks++) {
            const unsigned ko = ks*32;
            unsigned aH[2][4], aL[2][4];
            #pragma unroll
            for (int mi = 0; mi < 2; mi++) {
                ldsm4(aH[mi][0],aH[mi][1],aH[mi][2],aH[mi][3], aHB + so + mi*16*80 + ko);
                ldsm4(aL[mi][0],aL[mi][1],aL[mi][2],aL[mi][3], aLB + so + mi*16*80 + ko);
            }
            #pragma unroll
            for (int nb = 0; nb < 4; nb++) {
                unsigned bH[4], bL[4];
                ldsm4(bH[0],bH[1],bH[2],bH[3], bHB + so + nb*16*80 + ko);
                ldsm4(bL[0],bL[1],bL[2],bL[3], bLB + so + nb*16*80 + ko);
                #pragma unroll
                for (int mi = 0; mi < 2; mi++) {
                    #pragma unroll
                    for (int t = 0; t < 2; t++) {
                        float* c = acc[mi][nb*2+t];
                        mma16816(c, aH[mi][0],aH[mi][1],aH[mi][2],aH[mi][3], bH[t*2],bH[t*2+1]);
                        mma16816(c, aH[mi][0],aH[mi][1],aH[mi][2],aH[mi][3], bL[t*2],bL[t*2+1]);
                        mma16816(c, aL[mi][0],aL[mi][1],aL[mi][2],aL[mi][3], bH[t*2],bH[t*2+1]);
                    }
                }
            }
        }
        __syncthreads();
    }
    #undef PROJ_PREFETCH

    if (wsel < 2) {
        __nv_bfloat16* oh = wsel==0 ? g_qhi : g_khi;
        __nv_bfloat16* ol = wsel==0 ? g_qlo : g_klo;
        #pragma unroll
        for (int mi = 0; mi < 2; mi++) {
            int tr0 = t0 + wm*32 + mi*16 + lg;
            #pragma unroll
            for (int nj = 0; nj < 8; nj++) {
                int o = o0 + wn*64 + nj*8 + tg*2;
                float bi0 = bias[o], bi1 = bias[o+1];
                int hh = o >> 6, d = o & 63;
                size_t base = ((size_t)(b*H_+hh)*T_ + tr0)*D_ + d;
                __nv_bfloat16 h0,l0,h1,l1;
                cv(acc[mi][nj][0]+bi0, h0,l0); cv(acc[mi][nj][1]+bi1, h1,l1);
                *(unsigned*)&oh[base] = pk2(h0,h1);
                *(unsigned*)&ol[base] = pk2(l0,l1);
                cv(acc[mi][nj][2]+bi0, h0,l0); cv(acc[mi][nj][3]+bi1, h1,l1);
                *(unsigned*)&oh[base + 8*D_] = pk2(h0,h1);
                *(unsigned*)&ol[base + 8*D_] = pk2(l0,l1);
            }
        }
    } else {
        #pragma unroll
        for (int mi = 0; mi < 2; mi++) {
            int tr0 = t0 + wm*32 + mi*16 + lg;
            #pragma unroll
            for (int nj = 0; nj < 8; nj++) {
                int o = o0 + wn*64 + nj*8 + tg*2;
                float bi0 = bias[o], bi1 = bias[o+1];
                int hh = o >> 6, d = o & 63;
                size_t base = ((size_t)(b*H_+hh)*D_ + d)*T_ + tr0;
                __nv_bfloat16 h0,l0;
                cv(acc[mi][nj][0]+bi0, h0,l0); g_vhi[base] = h0;      g_vlo[base] = l0;
                cv(acc[mi][nj][1]+bi1, h0,l0); g_vhi[base+T_] = h0;   g_vlo[base+T_] = l0;
                cv(acc[mi][nj][2]+bi0, h0,l0); g_vhi[base+8] = h0;    g_vlo[base+8] = l0;
                cv(acc[mi][nj][3]+bi1, h0,l0); g_vhi[base+T_+8] = h0; g_vlo[base+T_+8] = l0;
            }
        }
    }
#endif
}

// =====================================================================
// Output projection tensor GEMM (mma.sync, double-buffered — unchanged)
// =====================================================================
__global__ __launch_bounds__(256, 2) void outp_gemm(
    const float* __restrict__ bo, const float* __restrict__ mask,
    float* __restrict__ out)
{
    __shared__ __align__(16) __nv_bfloat16 sA[2][2][128*40];
    __shared__ __align__(16) __nv_bfloat16 sB[2][2][128*40];

    const int tid = threadIdx.x, lane = tid & 31, w = tid >> 5;
    const int wm = w & 3, wn = w >> 2;
    const int lg = lane >> 2, tg = lane & 3;
    const int l7 = lane & 7, lh = (lane >> 3) & 1, lq = lane >> 4;

    const int o0 = blockIdx.x * 128;
    const int n0g = blockIdx.y * 128;
    const int b = n0g >> 10, t0 = n0g & 1023;

    const __nv_bfloat16* Ah = g_whi + (size_t)3*C_*C_;
    const __nv_bfloat16* Al = g_wlo + (size_t)3*C_*C_;

    float acc[2][8][4] = {};

    const unsigned STG = 2*128*40*2;
    const unsigned aHB = su32(sA[0][0]) + (wm*32 + lh*8 + l7)*80 + lq*16;
    const unsigned aLB = su32(sA[0][1]) + (wm*32 + lh*8 + l7)*80 + lq*16;
    const unsigned bHB = su32(sB[0][0]) + (wn*64 + lq*8 + l7)*80 + lh*16;
    const unsigned bLB = su32(sB[0][1]) + (wn*64 + lq*8 + l7)*80 + lh*16;

    #define OUTP_PREFETCH(k0, st) do { \
        _Pragma("unroll") \
        for (int r = 0; r < 4; r++) { \
            int s = tid + r*256; \
            int buf = s >> 9, rc = s & 511; \
            int row = rc >> 2, c = rc & 3; \
            unsigned off = row*80 + c*16; \
            const __nv_bfloat16* asrc = (buf ? Al : Ah) + (size_t)(o0+row)*C_ + (k0) + c*8; \
            const __nv_bfloat16* bsrc = (buf ? g_ytlo : g_ythi) + (size_t)(n0g+row)*C_ + (k0) + c*8; \
            cpasync16(su32(sA[st][buf]) + off, asrc); \
            cpasync16(su32(sB[st][buf]) + off, bsrc); \
        } \
        cp_commit(); \
    } while (0)

    OUTP_PREFETCH(0, 0);

    #pragma unroll 1
    for (int it = 0; it < 16; it++) {
        const int cur = it & 1;
        if (it + 1 < 16) {
            OUTP_PREFETCH((it+1)*32, cur^1);
            cp_wait1();
        } else {
            cp_wait0();
        }
        __syncthreads();

        const unsigned so = cur * STG;
        #pragma unroll
        for (int ks = 0; ks < 2; ks++) {
            const unsigned ko = ks*32;
            unsigned aH[2][4], aL[2][4];
            #pragma unroll
            for (int mi = 0; mi < 2; mi++) {
                ldsm4(aH[mi][0],aH[mi][1],aH[mi][2],aH[mi][3], aHB + so + mi*16*80 + ko);
                ldsm4(aL[mi][0],aL[mi][1],aL[mi][2],aL[mi][3], aLB + so + mi*16*80 + ko);
            }
            #pragma unroll
            for (int nb = 0; nb < 4; nb++) {
                unsigned bH[4], bL[4];
                ldsm4(bH[0],bH[1],bH[2],bH[3], bHB + so + nb*16*80 + ko);
                ldsm4(bL[0],bL[1],bL[2],bL[3], bLB + so + nb*16*80 + ko);
                #pragma unroll
                for (int mi = 0; mi < 2; mi++) {
                    #pragma unroll
                    for (int t = 0; t < 2; t++) {
                        float* c = acc[mi][nb*2+t];
                        mma16816(c, aH[mi][0],aH[mi][1],aH[mi][2],aH[mi][3], bH[t*2],bH[t*2+1]);
                        mma16816(c, aH[mi][0],aH[mi][1],aH[mi][2],aH[mi][3], bL[t*2],bL[t*2+1]);
                        mma16816(c, aL[mi][0],aL[mi][1],aL[mi][2],aL[mi][3], bH[t*2],bH[t*2+1]);
                    }
                }
            }
        }
        __syncthreads();
    }
    #undef OUTP_PREFETCH

    #pragma unroll
    for (int mi = 0; mi < 2; mi++) {
        int o = o0 + wm*32 + mi*16 + lg;
        float bi0 = bo[o], bi1 = bo[o+8];
        #pragma unroll
        for (int nj = 0; nj < 8; nj++) {
            int t = t0 + wn*64 + nj*8 + tg*2;
            float m0v = mask[(size_t)b*T_ + t];
            float m1v = mask[(size_t)b*T_ + t + 1];
            float2 v0 = make_float2((acc[mi][nj][0]+bi0)*m0v, (acc[mi][nj][1]+bi0)*m1v);
            float2 v1 = make_float2((acc[mi][nj][2]+bi1)*m0v, (acc[mi][nj][3]+bi1)*m1v);
            *(float2*)&out[((size_t)b*C_ + o)*T_ + t]     = v0;
            *(float2*)&out[((size_t)b*C_ + o + 8)*T_ + t] = v1;
        }
    }
}

// =====================================================================
// Fused attention — round-9 core + K(kt+1) prefetch hidden behind PV(kt)
// =====================================================================
__global__ __launch_bounds__(512, 1) void attn_kernel(const float* __restrict__ mask)
{
    extern __shared__ unsigned char smem[];
    __nv_bfloat16* qhi = (__nv_bfloat16*)(smem + OFF_QHI);
    __nv_bfloat16* qlo = (__nv_bfloat16*)(smem + OFF_QLO);
    __nv_bfloat16* khi = (__nv_bfloat16*)(smem + OFF_K);
    __nv_bfloat16* klo = (__nv_bfloat16*)(smem + OFF_K + 18432);
    __nv_bfloat16* vhi = (__nv_bfloat16*)(smem + OFF_V);
    __nv_bfloat16* vlo = (__nv_bfloat16*)(smem + OFF_V + 17408);
    __nv_bfloat16* phi = (__nv_bfloat16*)(smem + OFF_P);
    __nv_bfloat16* plo = (__nv_bfloat16*)(smem + OFF_P + 17408);
    __nv_bfloat16* binhi = (__nv_bfloat16*)(smem + OFF_BINHI);
    __nv_bfloat16* binlo = (__nv_bfloat16*)(smem + OFF_BINLO);
    float* sbin = (float*)(smem + OFF_SBIN);
    float* sqr  = (float*)(smem + OFF_SQR);
    float* smk  = (float*)(smem + OFF_SMK);
    float* sstp = (float*)(smem + OFF_SSTP);
    float* sst  = (float*)(smem + OFF_SST);

    const int tid  = threadIdx.x;
    const int lane = tid & 31;
    const int w    = tid >> 5;
    const int wm   = w & 3;
    const int wg   = w >> 2;
    const int lg   = lane >> 2;
    const int tg   = lane & 3;
    const int r0   = wm*16 + lg;
    const int r1   = r0 + 8;
    const int l7   = lane & 7;
    const int lh   = (lane >> 3) & 1;
    const int lq   = lane >> 4;

    const int i0 = blockIdx.x * 64;
    const int h  = blockIdx.y;
    const int b  = blockIdx.z;
    const size_t headbase = (size_t)(b*H_+h)*T_*D_;

    #define STAGE_K(j0k) do { \
        _Pragma("unroll") \
        for (int r = 0; r < 4; r++) { \
            int e = tid + r*512; \
            int bufi = e >> 10; \
            int rc = e & 1023; \
            int j = rc >> 3, c = rc & 7; \
            unsigned dst = su32(bufi ? klo : khi) + j*144 + c*16; \
            const unsigned char* src = \
                (const unsigned char*)(bufi ? g_klo : g_khi) \
                + (headbase + (size_t)((j0k)+j)*D_)*2 + c*16; \
            cpasync16(dst, src); \
        } \
        cp_commit(); \
    } while (0)

    #define STAGE_V(j0v) do { \
        _Pragma("unroll") \
        for (int r = 0; r < 4; r++) { \
            int e = tid + r*512; \
            int bufi = e >> 10; \
            int rc = e & 1023; \
            int d = rc >> 4, c = rc & 15; \
            unsigned dst = su32(bufi ? vlo : vhi) + d*272 + c*16; \
            const unsigned char* src = \
                (const unsigned char*)(bufi ? g_vlo : g_vhi) \
                + (headbase + (size_t)d*T_ + (j0v))*2 + c*16; \
            cpasync16(dst, src); \
        } \
        cp_commit(); \
    } while (0)

    // ---- Phase A: stage q + erel_k bf16 (cp.async); mask; zero sbin ----
    #pragma unroll
    for (int r = 0; r < 2; r++) {
        int e = tid + r*512;
        int bufi = e >> 9;
        int rc = e & 511;
        int m = rc >> 3, c = rc & 7;
        unsigned dst = su32(bufi ? qlo : qhi) + m*144 + c*16;
        const unsigned char* src =
            (const unsigned char*)(bufi ? g_qlo : g_qhi)
            + (headbase + (size_t)(i0+m)*D_)*2 + c*16;
        cpasync16(dst, src);
    }
    for (int e = tid; e < REL_*8; e += 512) {
        int r = e >> 3, c = e & 7;
        cpasync16(su32(smem + OFF_EKHI) + r*144 + c*16,
                  (const unsigned char*)g_ekhi + (size_t)(r*64 + c*8)*2);
    }
    for (int e = tid; e < REL_*8; e += 512) {
        int r = e >> 3, c = e & 7;
        cpasync16(su32(smem + OFF_EKLO) + r*144 + c*16,
                  (const unsigned char*)g_eklo + (size_t)(r*64 + c*8)*2);
    }
    cp_commit();
    for (int e = tid; e < T_/4; e += 512)
        ((float4*)smk)[e] = ((const float4*)(mask + (size_t)b*T_))[e];
    for (int e = tid; e < 64*132; e += 512)
        sbin[e] = 0.f;
    cp_wait0();
    __syncthreads();

    const unsigned qhiA = su32(qhi) + (unsigned)((wm*16 + lh*8 + l7)*144 + lq*16);
    const unsigned qloA = su32(qlo) + (unsigned)((wm*16 + lh*8 + l7)*144 + lq*16);

    // ---- Phase B: qrel = Q @ erel_k^T via MMA ----
    {
        const unsigned ekhiB = su32(smem + OFF_EKHI) + (lq*8 + l7)*144 + lh*16;
        const unsigned ekloB = su32(smem + OFF_EKLO) + (lq*8 + l7)*144 + lh*16;
        float qa[3][2][4] = {};
        const int ng = (wg == 0) ? 3 : 2;
        const int glist[3] = {wg, wg+4, 8};

        #pragma unroll
        for (int ks = 0; ks < 4; ks++) {
            const unsigned ko = ks*32;
            unsigned aH0,aH1,aH2,aH3, aL0,aL1,aL2,aL3;
            ldsm4(aH0,aH1,aH2,aH3, qhiA + ko);
            ldsm4(aL0,aL1,aL2,aL3, qloA + ko);
            for (int gi = 0; gi < ng; gi++) {
                const unsigned ro = glist[gi]*16*144;
                unsigned bH[4], bL[4];
                ldsm4(bH[0],bH[1],bH[2],bH[3], ekhiB + ro + ko);
                ldsm4(bL[0],bL[1],bL[2],bL[3], ekloB + ro + ko);
                #pragma unroll
                for (int t = 0; t < 2; t++) {
                    float* c = qa[gi][t];
                    mma16816(c, aH0,aH1,aH2,aH3, bH[t*2],bH[t*2+1]);
                    mma16816(c, aH0,aH1,aH2,aH3, bL[t*2],bL[t*2+1]);
                    mma16816(c, aL0,aL1,aL2,aL3, bH[t*2],bH[t*2+1]);
                }
            }
        }
        for (int gi = 0; gi < ng; gi++) {
            #pragma unroll
            for (int t = 0; t < 2; t++) {
                int col = glist[gi]*16 + t*8 + tg*2;
                if (col < 136) {
                    *(float2*)&sqr[r0*136 + col] = make_float2(qa[gi][t][0], qa[gi][t][1]);
                    *(float2*)&sqr[r1*136 + col] = make_float2(qa[gi][t][2], qa[gi][t][3]);
                }
            }
        }
    }
    __syncthreads();   // qrel MMAs done reading K-region overlay

    // prologue: stage K chunk 0 into K region (overlay now free)
    STAGE_K(0);

    const float qrM0 = sqr[r0*136];       const float qrP0 = sqr[r0*136 + 128];
    const float qrM1 = sqr[r1*136];       const float qrP1 = sqr[r1*136 + 128];

    const float scale = 0.125f;
    float yacc[2][4] = {};
    float ls0=0.f, ls1=0.f, ea0=0.f, ea1=0.f, eb0=0.f, eb1=0.f;

    const unsigned khiB0 = su32(khi) + (unsigned)((wg*32 + lq*8 + l7)*144 + lh*16);
    const unsigned kloB0 = su32(klo) + (unsigned)((wg*32 + lq*8 + l7)*144 + lh*16);
    const unsigned phiA = su32(phi) + (unsigned)((wm*16 + lh*8 + l7)*272 + lq*16);
    const unsigned ploA = su32(plo) + (unsigned)((wm*16 + lh*8 + l7)*272 + lq*16);
    const unsigned vhiB = su32(vhi) + (unsigned)((wg*8 + lq*32 + l7)*272 + lh*16);
    const unsigned vloB = su32(vlo) + (unsigned)((wg*8 + lq*32 + l7)*272 + lh*16);

    for (int kt = 0; kt < 8; kt++) {
        const int j0g = kt * 128;
        const int relbase = j0g - i0;
        const bool fastHi = (relbase >= 127);
        const bool fastLo = (relbase <= -191);

        __syncthreads();          // V region free (prev PV reads done)
        STAGE_V(j0g);             // pending: K(kt), V(kt)
        cp_wait1();               // K(kt) arrived (this thread's copies)
        __syncthreads();          // everyone's K copies visible

        // ---- S = Q K^T ----
        float sacc[4][4] = {};
        #pragma unroll
        for (int ks = 0; ks < 4; ks++) {
            const unsigned ko = ks*32;
            unsigned aH0,aH1,aH2,aH3, aL0,aL1,aL2,aL3;
            ldsm4(aH0,aH1,aH2,aH3, qhiA + ko);
            ldsm4(aL0,aL1,aL2,aL3, qloA + ko);
            unsigned bH[8], bL[8];
            ldsm4(bH[0],bH[1],bH[2],bH[3], khiB0 + ko);
            ldsm4(bH[4],bH[5],bH[6],bH[7], khiB0 + 16*144 + ko);
            ldsm4(bL[0],bL[1],bL[2],bL[3], kloB0 + ko);
            ldsm4(bL[4],bL[5],bL[6],bL[7], kloB0 + 16*144 + ko);
            #pragma unroll
            for (int t = 0; t < 4; t++) {
                unsigned b0h = bH[t*2], b1h = bH[t*2+1];
                unsigned b0l = bL[t*2], b1l = bL[t*2+1];
                mma16816(sacc[t], aH0,aH1,aH2,aH3, b0h,b1h);
                mma16816(sacc[t], aH0,aH1,aH2,aH3, b0l,b1l);
                mma16816(sacc[t], aL0,aL1,aL2,aL3, b0h,b1h);
            }
        }

        // ---- epilogue ----
        if (fastHi || fastLo) {
            const float c0 = fastHi ? qrP0 : qrM0;
            const float c1 = fastHi ? qrP1 : qrM1;
            float acc0 = 0.f, acc1 = 0.f;
            #pragma unroll
            for (int t = 0; t < 4; t++) {
                const int cb = wg*32 + t*8 + tg*2;
                #pragma unroll
                for (int ii = 0; ii < 2; ii++) {
                    const int rr = ii ? r1 : r0;
                    const float cc = ii ? c1 : c0;
                    float ev[2];
                    #pragma unroll
                    for (int jj = 0; jj < 2; jj++) {
                        int gj = j0g + cb + jj;
                        float s = sacc[t][ii*2+jj]*scale + cc;
                        if (smk[gj] <= 0.f) s = -1e9f;
                        float e = __expf(s);
                        if (ii == 0) acc0 += e; else acc1 += e;
                        ev[jj] = e;
                    }
                    __nv_bfloat16 eh0,el0,eh1,el1;
                    cv(ev[0],eh0,el0); cv(ev[1],eh1,el1);
                    *(unsigned*)&phi[rr*136 + cb] = pk2(eh0,eh1);
                    *(unsigned*)&plo[rr*136 + cb] = pk2(el0,el1);
                }
            }
            ls0 += acc0; ls1 += acc1;
            if (fastHi) { eb0 += acc0; eb1 += acc1; }
            else        { ea0 += acc0; ea1 += acc1; }
        } else {
            #pragma unroll
            for (int t = 0; t < 4; t++) {
                const int cb = wg*32 + t*8 + tg*2;
                #pragma unroll
                for (int ii = 0; ii < 2; ii++) {
                    const int rr = ii ? r1 : r0;
                    const int gi = i0 + rr;
                    float ev[2];
                    #pragma unroll
                    for (int jj = 0; jj < 2; jj++) {
                        int gj = j0g + cb + jj;
                        int rel = gj - gi;
                        int relc = rel < -64 ? -64 : (rel > 64 ? 64 : rel);
                        float s = sacc[t][ii*2+jj]*scale + sqr[rr*136 + relc + 64];
                        if (smk[gj] <= 0.f) s = -1e9f;
                        float e = __expf(s);
                        if (ii == 0) ls0 += e; else ls1 += e;
                        if (rel <= -64)      { if (ii == 0) ea0 += e; else ea1 += e; }
                        else if (rel >= 64)  { if (ii == 0) eb0 += e; else eb1 += e; }
                        else                 sbin[rr*132 + rel + 64] = e;
                        ev[jj] = e;
                    }
                    __nv_bfloat16 eh0,el0,eh1,el1;
                    cv(ev[0],eh0,el0); cv(ev[1],eh1,el1);
                    *(unsigned*)&phi[rr*136 + cb] = pk2(eh0,eh1);
                    *(unsigned*)&plo[rr*136 + cb] = pk2(el0,el1);
                }
            }
        }
        __syncthreads();          // P visible; all S reads of K done

        // prefetch next K behind PV; then wait V(kt)
        if (kt < 7) {
            STAGE_K(j0g + 128);   // pending: V(kt), K(kt+1)
            cp_wait1();           // V(kt) done (own copies)
        } else {
            cp_wait0();
        }
        __syncthreads();          // everyone's V copies visible

        // ---- PV: y += P @ V ----
        #pragma unroll
        for (int ks = 0; ks < 8; ks++) {
            const unsigned ko = ks*32;
            unsigned aH0,aH1,aH2,aH3, aL0,aL1,aL2,aL3;
            ldsm4(aH0,aH1,aH2,aH3, phiA + ko);
            ldsm4(aL0,aL1,aL2,aL3, ploA + ko);
            unsigned bH[4], bL[4];
            ldsm4(bH[0],bH[1],bH[2],bH[3], vhiB + ko);
            ldsm4(bL[0],bL[1],bL[2],bL[3], vloB + ko);
            #pragma unroll
            for (int ti = 0; ti < 2; ti++) {
                unsigned b0h = bH[ti*2], b1h = bH[ti*2+1];
                unsigned b0l = bL[ti*2], b1l = bL[ti*2+1];
                mma16816(yacc[ti], aH0,aH1,aH2,aH3, b0h,b1h);
                mma16816(yacc[ti], aH0,aH1,aH2,aH3, b0l,b1l);
                mma16816(yacc[ti], aL0,aL1,aL2,aL3, b0h,b1h);
            }
        }
    }
    #undef STAGE_K
    #undef STAGE_V
    __syncthreads();   // last PV reads done

    // ---- stage erel_v^T bf16 (into V/P overlay) ----
    for (int e = tid; e < 64*18; e += 512) {
        int d = e/18, c = e - d*18;
        cpasync16(su32(smem + OFF_EVHI) + d*304 + c*16,
                  (const unsigned char*)g_evhi + (size_t)(d*144 + c*8)*2);
    }
    for (int e = tid; e < 64*18; e += 512) {
        int d = e/18, c = e - d*18;
        cpasync16(su32(smem + OFF_EVLO) + d*304 + c*16,
                  (const unsigned char*)g_evlo + (size_t)(d*144 + c*8)*2);
    }
    cp_commit();

    // ---- stat reduction ----
    {
        float v;
        #define RED_(x) v = x; v += __shfl_xor_sync(~0u, v, 1); v += __shfl_xor_sync(~0u, v, 2); x = v;
        RED_(ls0) RED_(ls1) RED_(ea0) RED_(ea1) RED_(eb0) RED_(eb1)
        #undef RED_
        if (tg == 0) {
            sstp[0*256 + wg*64 + r0] = ls0;  sstp[0*256 + wg*64 + r1] = ls1;
            sstp[1*256 + wg*64 + r0] = ea0;  sstp[1*256 + wg*64 + r1] = ea1;
            sstp[2*256 + wg*64 + r0] = eb0;  sstp[2*256 + wg*64 + r1] = eb1;
        }
    }
    __syncthreads();
    if (tid < 64) {
        float l = 0.f, a = 0.f, c = 0.f;
        #pragma unroll
        for (int g = 0; g < 4; g++) {
            l += sstp[0*256 + g*64 + tid];
            a += sstp[1*256 + g*64 + tid];
            c += sstp[2*256 + g*64 + tid];
        }
        sst[tid] = l;
        sbin[tid*132]       = a;
        sbin[tid*132 + 128] = c;
    }
    __syncthreads();

    // ---- convert bins fp32 -> bf16 hi/lo [64][152] ----
    for (int e = tid; e < 64*144; e += 512) {
        int m = e/144, c = e - m*144;
        float v = (c < REL_) ? sbin[m*132 + c] : 0.f;
        __nv_bfloat16 hh, ll;
        cv(v, hh, ll);
        binhi[m*152 + c] = hh;
        binlo[m*152 + c] = ll;
    }
    cp_wait0();
    __syncthreads();

    // ---- yacc += bins @ erel_v^T ----
    {
        const unsigned binA  = su32(smem + OFF_BINHI) + (wm*16 + lh*8 + l7)*304 + lq*16;
        const unsigned binAl = su32(smem + OFF_BINLO) + (wm*16 + lh*8 + l7)*304 + lq*16;
        const unsigned evB   = su32(smem + OFF_EVHI)  + (wg*8 + lq*32 + l7)*304 + lh*16;
        const unsigned evBl  = su32(smem + OFF_EVLO)  + (wg*8 + lq*32 + l7)*304 + lh*16;
        #pragma unroll
        for (int ks = 0; ks < 9; ks++) {
            const unsigned ko = ks*32;
            unsigned aH0,aH1,aH2,aH3, aL0,aL1,aL2,aL3;
            ldsm4(aH0,aH1,aH2,aH3, binA + ko);
            ldsm4(aL0,aL1,aL2,aL3, binAl + ko);
            unsigned bH[4], bL[4];
            ldsm4(bH[0],bH[1],bH[2],bH[3], evB + ko);
            ldsm4(bL[0],bL[1],bL[2],bL[3], evBl + ko);
            #pragma unroll
            for (int ti = 0; ti < 2; ti++) {
                unsigned b0h = bH[ti*2], b1h = bH[ti*2+1];
                unsigned b0l = bL[ti*2], b1l = bL[ti*2+1];
                mma16816(yacc[ti], aH0,aH1,aH2,aH3, b0h,b1h);
                mma16816(yacc[ti], aH0,aH1,aH2,aH3, b0l,b1l);
                mma16816(yacc[ti], aL0,aL1,aL2,aL3, b0h,b1h);
            }
        }
    }

    // ---- final: y = yacc / l ; store yt bf16 hi/lo ----
    {
        const float inv0 = 1.f / sst[r0];
        const float inv1 = 1.f / sst[r1];
        const int dA = wg*8 + tg*2;
        const int dB = dA + 32;
        const int cbase = h*64;
        size_t tb0 = ((size_t)b*T_ + i0 + r0)*C_;
        size_t tb1 = ((size_t)b*T_ + i0 + r1)*C_;
        __nv_bfloat16 h0,l0,h1,l1;
        cv(yacc[0][0]*inv0,h0,l0); cv(yacc[0][1]*inv0,h1,l1);
        *(unsigned*)&g_ythi[tb0 + cbase + dA] = pk2(h0,h1);
        *(unsigned*)&g_ytlo[tb0 + cbase + dA] = pk2(l0,l1);
        cv(yacc[0][2]*inv1,h0,l0); cv(yacc[0][3]*inv1,h1,l1);
        *(unsigned*)&g_ythi[tb1 + cbase + dA] = pk2(h0,h1);
        *(unsigned*)&g_ytlo[tb1 + cbase + dA] = pk2(l0,l1);
        cv(yacc[1][0]*inv0,h0,l0); cv(yacc[1][1]*inv0,h1,l1);
        *(unsigned*)&g_ythi[tb0 + cbase + dB] = pk2(h0,h1);
        *(unsigned*)&g_ytlo[tb0 + cbase + dB] = pk2(l0,l1);
        cv(yacc[1][2]*inv1,h0,l0); cv(yacc[1][3]*inv1,h1,l1);
        *(unsigned*)&g_ythi[tb1 + cbase + dB] = pk2(h0,h1);
        *(unsigned*)&g_ytlo[tb1 + cbase + dB] = pk2(l0,l1);
    }
}

// =====================================================================
extern "C" void kernel_launch(void* const* d_in, const int* in_sizes, int n_in,
                              void* d_out, int out_size)
{
    const float* x     = (const float*)d_in[0];
    const float* xmask = (const float*)d_in[1];
    const float* Wq    = (const float*)d_in[2];
    const float* bq    = (const float*)d_in[3];
    const float* Wk    = (const float*)d_in[4];
    const float* bk    = (const float*)d_in[5];
    const float* Wv    = (const float*)d_in[6];
    const float* bv    = (const float*)d_in[7];
    const float* Wo    = (const float*)d_in[8];
    const float* bo    = (const float*)d_in[9];
    const float* erelk = (const float*)d_in[10];
    const float* erelv = (const float*)d_in[11];
    float* out = (float*)d_out;

    cudaFuncSetAttribute(attn_kernel,
                         cudaFuncAttributeMaxDynamicSharedMemorySize, SMEM_BYTES);
    cudaFuncSetAttribute(proj_any,
                         cudaFuncAttributeMaxDynamicSharedMemorySize, PJ_SMEM);

    conv_x<<<dim3(T_/32, C_/32, B_), 256>>>(x);
    conv_w<<<dim3(C_*C_/256, 4), 256>>>(Wq, Wk, Wv, Wo);
    conv_erel<<<36, 256>>>(erelk, erelv);

    proj_any<<<dim3(64, 12), 256, PJ_SMEM>>>(bq, bk, bv);

    attn_kernel<<<dim3(16, H_, B_), 512, SMEM_BYTES>>>(xmask);

    outp_gemm<<<dim3(4, 64), 256>>>(bo, xmask, out);
}

// round 12
// speedup vs baseline: 4.5701x; 1.0096x over previous
#include <cuda_runtime.h>
#include <cuda_bf16.h>
#include <cstdint>

#define B_ 8
#define C_ 512
#define T_ 1024
#define H_ 8
#define D_ 64
#define REL_ 129

// Feature gate: tcgen05 only exists in 'a'-suffixed device passes.
#if defined(__CUDA_ARCH_FEAT_SM103_ALL) || defined(__CUDA_ARCH_FEAT_SM100_ALL) || defined(__CUDA_ARCH_FEAT_SM101_ALL)
#define HAS_TCGEN05 1
#else
#define HAS_TCGEN05 0
#endif

// ---------------- scratch (no cudaMalloc allowed) ----------------
__device__ __nv_bfloat16 g_xthi[B_*T_*C_];    // x^T (B,T,C) hi
__device__ __nv_bfloat16 g_xtlo[B_*T_*C_];
__device__ __nv_bfloat16 g_whi[4*C_*C_];      // Wq,Wk,Wv,Wo hi
__device__ __nv_bfloat16 g_wlo[4*C_*C_];
__device__ __nv_bfloat16 g_qhi[B_*H_*T_*D_];  // (B,H,T,D)
__device__ __nv_bfloat16 g_qlo[B_*H_*T_*D_];
__device__ __nv_bfloat16 g_khi[B_*H_*T_*D_];
__device__ __nv_bfloat16 g_klo[B_*H_*T_*D_];
__device__ __nv_bfloat16 g_vhi[B_*H_*T_*D_];  // (B,H,D,T)
__device__ __nv_bfloat16 g_vlo[B_*H_*T_*D_];
__device__ __nv_bfloat16 g_ythi[B_*T_*C_];    // y^T (B,T,C)
__device__ __nv_bfloat16 g_ytlo[B_*T_*C_];
__device__ __nv_bfloat16 g_ekhi[REL_*D_];     // erel_k [129][64]
__device__ __nv_bfloat16 g_eklo[REL_*D_];
__device__ __nv_bfloat16 g_evhi[D_*144];      // erel_v^T [64][144] (zero-padded)
__device__ __nv_bfloat16 g_evlo[D_*144];

// ---------------- attn shared memory (byte offsets), 64-query CTA ----------------
#define OFF_QHI   0
#define OFF_QLO   9216
#define OFF_K     18432
#define OFF_V     55296
#define OFF_P     90112
#define OFF_SBIN  124928
#define OFF_SQR   158720
#define OFF_SMK   193536
#define OFF_SSTP  197632
#define OFF_SST   200704
#define SMEM_BYTES 201472
#define OFF_EKHI  18432
#define OFF_EKLO  39168
#define OFF_BINHI 18432
#define OFF_BINLO 37888
#define OFF_EVHI  57344
#define OFF_EVLO  76800

// ---------------- proj shared memory ----------------
// tcgen05 layout: tmemptr@0, mbar0@8, mbar1@16,
//   stage0 @1024 (AH,AL,BH,BL x16KB), stage1 @66560
// fallback (mma.sync) uses first 81920 bytes with its own layout.
#define PJ_SMEM 132096
#define PT_TMEM 0
#define PT_MB0  8
#define PT_MB1  16
#define PT_STAGE0 1024
#define PT_STAGE1 (1024+65536)
#define IDESC_P 0x8100490u   // kind::f16: F32 acc, BF16xBF16, M=128, N=64

// ---------------- helpers ----------------
__device__ __forceinline__ unsigned pk2(__nv_bfloat16 a, __nv_bfloat16 b) {
    __nv_bfloat162 t = __halves2bfloat162(a, b);
    return *reinterpret_cast<unsigned*>(&t);
}
__device__ __forceinline__ void cv(float x, __nv_bfloat16& h, __nv_bfloat16& l) {
    h = __float2bfloat16(x);
    l = __float2bfloat16(x - __bfloat162float(h));
}
__device__ __forceinline__ unsigned su32(const void* p) {
    return (unsigned)__cvta_generic_to_shared(p);
}
__device__ __forceinline__ void cpasync16(unsigned s, const void* g) {
    asm volatile("cp.async.cg.shared.global [%0], [%1], 16;" :: "r"(s), "l"(g));
}
__device__ __forceinline__ void cp_commit() {
    asm volatile("cp.async.commit_group;" ::: "memory");
}
__device__ __forceinline__ void cp_wait0() {
    asm volatile("cp.async.wait_group 0;" ::: "memory");
}
__device__ __forceinline__ void cp_wait1() {
    asm volatile("cp.async.wait_group 1;" ::: "memory");
}
__device__ __forceinline__ void ldsm4(unsigned& r0, unsigned& r1, unsigned& r2,
                                      unsigned& r3, unsigned addr) {
    asm volatile("ldmatrix.sync.aligned.m8n8.x4.shared.b16 {%0,%1,%2,%3}, [%4];"
                 : "=r"(r0), "=r"(r1), "=r"(r2), "=r"(r3) : "r"(addr));
}
__device__ __forceinline__ void mma16816(float* c, unsigned a0, unsigned a1,
                                         unsigned a2, unsigned a3,
                                         unsigned b0, unsigned b1) {
    asm volatile(
        "mma.sync.aligned.m16n8k16.row.col.f32.bf16.bf16.f32 "
        "{%0,%1,%2,%3}, {%4,%5,%6,%7}, {%8,%9}, {%0,%1,%2,%3};"
        : "+f"(c[0]), "+f"(c[1]), "+f"(c[2]), "+f"(c[3])
        : "r"(a0), "r"(a1), "r"(a2), "r"(a3), "r"(b0), "r"(b1));
}

#if HAS_TCGEN05
// ---- tcgen05 machinery (HW-verified example patterns) ----
__device__ __forceinline__ uint32_t elect_one_pred() {
    uint32_t pred;
    asm volatile(
        "{\n\t.reg .pred p;\n\t"
        "elect.sync _|p, 0xFFFFFFFF;\n\t"
        "selp.b32 %0, 1, 0, p;\n\t}"
        : "=r"(pred));
    return pred;
}
static constexpr uint64_t SMEM_DESC_BASE_SW128 =
    (uint64_t(2)  << 61) | (uint64_t(1) << 46) | (uint64_t(64) << 32) | (uint64_t(1) << 16);
#define MAKE_SMEM_DESC(base_addr) \
    (SMEM_DESC_BASE_SW128 | ((uint64_t)((base_addr) >> 4) & 0x3FFF))
#define TCGEN05_ALLOC(smem_result_addr, nCols) \
    asm volatile("tcgen05.alloc.cta_group::1.sync.aligned.shared::cta.b32 [%0], %1;" \
        :: "r"((uint32_t)(smem_result_addr)), "r"((uint32_t)(nCols)) : "memory")
#define TCGEN05_DEALLOC(tmem_addr, nCols) \
    asm volatile("tcgen05.dealloc.cta_group::1.sync.aligned.b32 %0, %1;" \
        :: "r"(tmem_addr), "r"((uint32_t)(nCols)))
#define TCGEN05_COMMIT(mbar_smem_addr) \
    asm volatile("tcgen05.commit.cta_group::1.mbarrier::arrive::one.shared::cluster.b64 [%0];" \
        :: "r"((uint32_t)(mbar_smem_addr)) : "memory")
#define TCGEN05_FENCE_BEFORE() \
    asm volatile("tcgen05.fence::before_thread_sync;" ::: "memory")
#define TCGEN05_FENCE_AFTER() \
    asm volatile("tcgen05.fence::after_thread_sync;" ::: "memory")
#define TCGEN05_WAIT_LD() \
    asm volatile("tcgen05.wait::ld.sync.aligned;" ::: "memory")
#define FENCE_PROXY_ASYNC_SHARED_CTA() \
    asm volatile("fence.proxy.async.shared::cta;" ::: "memory")
#define TCGEN05_LD_32X32B_X32(r, tmem_addr) \
    asm volatile( \
        "tcgen05.ld.sync.aligned.32x32b.x32.b32 " \
        "{%0, %1, %2, %3, %4, %5, %6, %7, " \
        " %8, %9, %10, %11, %12, %13, %14, %15, " \
        " %16, %17, %18, %19, %20, %21, %22, %23, " \
        " %24, %25, %26, %27, %28, %29, %30, %31}, [%32];" \
        : "=r"((r)[0]),  "=r"((r)[1]),  "=r"((r)[2]),  "=r"((r)[3]), \
          "=r"((r)[4]),  "=r"((r)[5]),  "=r"((r)[6]),  "=r"((r)[7]), \
          "=r"((r)[8]),  "=r"((r)[9]),  "=r"((r)[10]), "=r"((r)[11]), \
          "=r"((r)[12]), "=r"((r)[13]), "=r"((r)[14]), "=r"((r)[15]), \
          "=r"((r)[16]), "=r"((r)[17]), "=r"((r)[18]), "=r"((r)[19]), \
          "=r"((r)[20]), "=r"((r)[21]), "=r"((r)[22]), "=r"((r)[23]), \
          "=r"((r)[24]), "=r"((r)[25]), "=r"((r)[26]), "=r"((r)[27]), \
          "=r"((r)[28]), "=r"((r)[29]), "=r"((r)[30]), "=r"((r)[31]) \
        : "r"(tmem_addr))
__device__ __forceinline__ void tcg_f16_ss(uint32_t d_tmem, uint64_t a_desc,
                                           uint64_t b_desc, uint32_t idesc, bool acc)
{
    uint32_t en = acc ? 1u : 0u;
    asm volatile(
        "{\n\t.reg .pred p;\n\t"
        "setp.ne.u32 p, %5, 0;\n\t"
        "tcgen05.mma.cta_group::1.kind::f16 [%0], %1, %2, %3, {%4,%4,%4,%4}, p;\n\t}"
        :: "r"(d_tmem), "l"(a_desc), "l"(b_desc), "r"(idesc), "r"(0u), "r"(en)
        : "memory");
}
#endif // HAS_TCGEN05

// mbarrier (base-arch legal, sm_90+)
#define MBARRIER_INIT(mbar_smem_addr, count) \
    asm volatile("mbarrier.init.shared.b64 [%0], %1;" \
        :: "r"((uint32_t)(mbar_smem_addr)), "r"((uint32_t)(count)) : "memory")
#define MBARRIER_WAIT_PARITY(mbar_smem_addr, phase_parity) do { \
    uint32_t _mbar = (uint32_t)(mbar_smem_addr); \
    uint32_t _parity = (uint32_t)(phase_parity); \
    uint32_t _done; \
    asm volatile( \
        "{\n\t.reg .pred p;\n\t" \
        "mbarrier.try_wait.parity.acquire.cta.shared::cta.b64 p, [%1], %2;\n\t" \
        "selp.b32 %0, 1, 0, p;\n\t}" \
        : "=r"(_done) : "r"(_mbar), "r"(_parity) : "memory"); \
    if (!_done) { \
        asm volatile( \
            "{\n\t.reg .pred P1;\n\t" \
            "WAIT_LOOP_%=:\n\t" \
            "mbarrier.try_wait.parity.acquire.cta.shared::cta.b64 P1, [%0], %1, 0x989680;\n\t" \
            "@P1 bra.uni WAIT_DONE_%=;\n\t" \
            "bra.uni WAIT_LOOP_%=;\n\t" \
            "WAIT_DONE_%=:\n\t}" \
            :: "r"(_mbar), "r"(_parity) : "memory"); \
    } \
} while(0)

// =====================================================================
// prep kernels (unchanged)
// =====================================================================
__global__ __launch_bounds__(256) void conv_x(const float* __restrict__ x)
{
    __shared__ float s[32][33];
    const int b = blockIdx.z, c0 = blockIdx.y*32, t0 = blockIdx.x*32;
    const int tx = threadIdx.x & 31, ty = threadIdx.x >> 5;
    #pragma unroll
    for (int r = 0; r < 4; r++) {
        int c = ty + r*8;
        s[c][tx] = x[((size_t)b*C_ + c0 + c)*T_ + t0 + tx];
    }
    __syncthreads();
    #pragma unroll
    for (int r = 0; r < 4; r++) {
        int t = ty + r*8;
        float v = s[tx][t];
        __nv_bfloat16 h, l;
        cv(v, h, l);
        size_t idx = ((size_t)b*T_ + t0 + t)*C_ + c0 + tx;
        g_xthi[idx] = h;
        g_xtlo[idx] = l;
    }
}

__global__ __launch_bounds__(256) void conv_w(
    const float* __restrict__ w0, const float* __restrict__ w1,
    const float* __restrict__ w2, const float* __restrict__ w3)
{
    const int g = blockIdx.y;
    const float* W = g==0 ? w0 : g==1 ? w1 : g==2 ? w2 : w3;
    int idx = blockIdx.x*256 + threadIdx.x;
    float v = W[idx];
    __nv_bfloat16 h, l;
    cv(v, h, l);
    g_whi[(size_t)g*C_*C_ + idx] = h;
    g_wlo[(size_t)g*C_*C_ + idx] = l;
}

__global__ __launch_bounds__(256) void conv_erel(
    const float* __restrict__ erelk, const float* __restrict__ erelv)
{
    int idx = blockIdx.x*256 + threadIdx.x;
    if (idx < REL_*D_) {
        __nv_bfloat16 h, l;
        cv(erelk[idx], h, l);
        g_ekhi[idx] = h; g_eklo[idx] = l;
    }
    if (idx < D_*144) {
        int d = idx / 144, r = idx - d*144;
        float v = (r < REL_) ? erelv[r*D_ + d] : 0.f;
        __nv_bfloat16 h, l;
        cv(v, h, l);
        g_evhi[idx] = h; g_evlo[idx] = l;
    }
}

// =====================================================================
// QKV projection — tcgen05 SS double-buffered pipeline (if available),
// else the proven double-buffered mma.sync path.
// =====================================================================
__global__ __launch_bounds__(256) void proj_any(
    const float* __restrict__ bq, const float* __restrict__ bk,
    const float* __restrict__ bv)
{
    extern __shared__ unsigned char smem[];
    const int tid = threadIdx.x, lane = tid & 31, w = tid >> 5;

    const int ny = blockIdx.y;
    const int wsel = ny >> 2;
    const int o0 = (ny & 3) * 128;
    const int m0g = blockIdx.x * 128;
    const int b = m0g >> 10, t0 = m0g & 1023;

    const __nv_bfloat16* Bh = g_whi + (size_t)wsel*C_*C_;
    const __nv_bfloat16* Bl = g_wlo + (size_t)wsel*C_*C_;
    const float* bias = wsel==0 ? bq : (wsel==1 ? bk : bv);

#if HAS_TCGEN05
    // ----------------- tcgen05 SS path, 2-stage pipeline -----------------
    const uint32_t sb = su32(smem);
    if (w == 0) TCGEN05_ALLOC(sb + PT_TMEM, 128);
    if (tid == 0) { MBARRIER_INIT(sb + PT_MB0, 1); MBARRIER_INIT(sb + PT_MB1, 1); }
    __syncthreads();
    uint32_t tmem;
    asm volatile("ld.shared.b32 %0, [%1];" : "=r"(tmem) : "r"(sb + PT_TMEM));

    const uint32_t stg[2] = { sb + PT_STAGE0, sb + PT_STAGE1 };
    const uint32_t mb[2]  = { sb + PT_MB0, sb + PT_MB1 };

    // stage 4 tiles [128 rows][64 bf16] SW128-swizzled into stage base `sbv`
    #define PSTAGE(ktv, sbv) do { \
        const int kc0_ = (ktv) * 64; \
        _Pragma("unroll") \
        for (int r = 0; r < 16; r++) { \
            int e = tid + r*256; \
            int tile = e >> 10; \
            int rc = e & 1023; \
            int row = rc >> 3, c = rc & 7; \
            unsigned dstoff = (unsigned)(tile*16384 + (row>>3)*1024 + (row&7)*128 + ((c ^ (row&7))*16)); \
            const __nv_bfloat16* src; \
            if (tile == 0)      src = g_xthi + (size_t)(m0g+row)*C_ + kc0_ + c*8; \
            else if (tile == 1) src = g_xtlo + (size_t)(m0g+row)*C_ + kc0_ + c*8; \
            else if (tile == 2) src = Bh + (size_t)(o0+row)*C_ + kc0_ + c*8; \
            else                src = Bl + (size_t)(o0+row)*C_ + kc0_ + c*8; \
            cpasync16((sbv) + dstoff, src); \
        } \
        cp_commit(); \
    } while (0)

    // prologue: stage chunk 0 into stage 0
    PSTAGE(0, stg[0]);
    cp_wait0();
    __syncthreads();

    int ph0 = 0, ph1 = 0;
    #pragma unroll 1
    for (int kt = 0; kt < 8; kt++) {
        const int bsel = kt & 1;
        FENCE_PROXY_ASYNC_SHARED_CTA();
        if (w == 0) {
            if (elect_one_pred()) {
                const uint32_t base = stg[bsel];
                const uint64_t dAh = MAKE_SMEM_DESC(base);
                const uint64_t dAl = MAKE_SMEM_DESC(base + 16384);
                const uint64_t dBh = MAKE_SMEM_DESC(base + 32768);
                const uint64_t dBl = MAKE_SMEM_DESC(base + 49152);
                #pragma unroll
                for (int n2 = 0; n2 < 2; n2++) {
                    const uint64_t bo_ = (uint64_t)(n2 * 512);  // +64 B-rows = 8 atoms
                    const uint32_t dt = tmem + n2 * 64;
                    #pragma unroll
                    for (int s = 0; s < 4; s++) {
                        const bool first = (kt == 0 && s == 0);
                        tcg_f16_ss(dt, dAh + s*2, dBh + bo_ + s*2, IDESC_P, !first);
                        tcg_f16_ss(dt, dAh + s*2, dBl + bo_ + s*2, IDESC_P, true);
                        tcg_f16_ss(dt, dAl + s*2, dBh + bo_ + s*2, IDESC_P, true);
                    }
                }
                TCGEN05_COMMIT(mb[bsel]);
            }
        }
        if (kt < 7) {
            const int b2 = (kt + 1) & 1;
            if (kt >= 1) {
                // free stage b2: MMA(kt-1) (which read it) must be done
                if (b2 == 0) { MBARRIER_WAIT_PARITY(mb[0], ph0 & 1); ph0++; }
                else         { MBARRIER_WAIT_PARITY(mb[1], ph1 & 1); ph1++; }
            }
            PSTAGE(kt + 1, stg[b2]);
            cp_wait0();
            __syncthreads();
        }
    }
    #undef PSTAGE
    // final: wait last commit (mbar[1], phase ph1) — covers ALL prior MMAs
    MBARRIER_WAIT_PARITY(mb[1], ph1 & 1);
    TCGEN05_FENCE_AFTER();

    const int mrow = (w & 3)*32 + lane;
    const int cbase = (w >> 2)*64;
    uint32_t dr[64];
    TCGEN05_LD_32X32B_X32(dr, tmem + cbase);
    TCGEN05_LD_32X32B_X32(dr + 32, tmem + cbase + 32);
    TCGEN05_WAIT_LD();
    TCGEN05_FENCE_BEFORE();

    const int t = t0 + mrow;
    if (wsel < 2) {
        __nv_bfloat16* oh = wsel==0 ? g_qhi : g_khi;
        __nv_bfloat16* ol = wsel==0 ? g_qlo : g_klo;
        #pragma unroll
        for (int n = 0; n < 64; n += 2) {
            int o = o0 + cbase + n;
            int hh = o >> 6, d = o & 63;
            float v0 = __uint_as_float(dr[n])   + bias[o];
            float v1 = __uint_as_float(dr[n+1]) + bias[o+1];
            __nv_bfloat16 h0,l0,h1,l1;
            cv(v0,h0,l0); cv(v1,h1,l1);
            size_t idx = ((size_t)(b*H_+hh)*T_ + t)*D_ + d;
            *(unsigned*)&oh[idx] = pk2(h0,h1);
            *(unsigned*)&ol[idx] = pk2(l0,l1);
        }
    } else {
        #pragma unroll
        for (int n = 0; n < 64; n++) {
            int o = o0 + cbase + n;
            int hh = o >> 6, d = o & 63;
            float v = __uint_as_float(dr[n]) + bias[o];
            __nv_bfloat16 h0,l0;
            cv(v,h0,l0);
            size_t idx = ((size_t)(b*H_+hh)*D_ + d)*T_ + t;
            g_vhi[idx] = h0;
            g_vlo[idx] = l0;
        }
    }
    __syncthreads();
    if (w == 0) TCGEN05_DEALLOC(tmem, 128);

#else
    // ----------------- fallback: double-buffered mma.sync (round-9) -----------------
    const int wm = w & 3, wn = w >> 2;
    const int lg = lane >> 2, tg = lane & 3;
    const int l7 = lane & 7, lh = (lane >> 3) & 1, lq = lane >> 4;

    const unsigned SBASE = su32(smem);
    const unsigned STG = 20480;

    float acc[2][8][4] = {};

    const unsigned aHB = SBASE + (wm*32 + lh*8 + l7)*80 + lq*16;
    const unsigned aLB = aHB + 10240;
    const unsigned bHB = SBASE + 40960 + (wn*64 + lq*8 + l7)*80 + lh*16;
    const unsigned bLB = bHB + 10240;

    #define PROJ_PREFETCH(k0, st) do { \
        _Pragma("unroll") \
        for (int r = 0; r < 4; r++) { \
            int s = tid + r*256; \
            int buf = s >> 9, rc = s & 511; \
            int row = rc >> 2, c = rc & 3; \
            unsigned off = (st)*STG + buf*10240 + row*80 + c*16; \
            const __nv_bfloat16* asrc = (buf ? g_xtlo : g_xthi) + (size_t)(m0g+row)*C_ + (k0) + c*8; \
            const __nv_bfloat16* bsrc = (buf ? Bl : Bh) + (size_t)(o0+row)*C_ + (k0) + c*8; \
            cpasync16(SBASE + off, asrc); \
            cpasync16(SBASE + 40960 + off, bsrc); \
        } \
        cp_commit(); \
    } while (0)

    PROJ_PREFETCH(0, 0);

    #pragma unroll 1
    for (int it = 0; it < 16; it++) {
        const int cur = it & 1;
        if (it + 1 < 16) {
            PROJ_PREFETCH((it+1)*32, cur^1);
            cp_wait1();
        } else {
            cp_wait0();
        }
        __syncthreads();

        const unsigned so = cur * STG;
        #pragma unroll
        for (int ks = 0; ks < 2; ks++) {
            const unsigned ko = ks*32;
            unsigned aH[2][4], aL[2][4];
            #pragma unroll
            for (int mi = 0; mi < 2; mi++) {
                ldsm4(aH[mi][0],aH[mi][1],aH[mi][2],aH[mi][3], aHB + so + mi*16*80 + ko);
                ldsm4(aL[mi][0],aL[mi][1],aL[mi][2],aL[mi][3], aLB + so + mi*16*80 + ko);
            }
            #pragma unroll
            for (int nb = 0; nb < 4; nb++) {
                unsigned bH[4], bL[4];
                ldsm4(bH[0],bH[1],bH[2],bH[3], bHB + so + nb*16*80 + ko);
                ldsm4(bL[0],bL[1],bL[2],bL[3], bLB + so + nb*16*80 + ko);
                #pragma unroll
                for (int mi = 0; mi < 2; mi++) {
                    #pragma unroll
                    for (int t = 0; t < 2; t++) {
                        float* c = acc[mi][nb*2+t];
                        mma16816(c, aH[mi][0],aH[mi][1],aH[mi][2],aH[mi][3], bH[t*2],bH[t*2+1]);
                        mma16816(c, aH[mi][0],aH[mi][1],aH[mi][2],aH[mi][3], bL[t*2],bL[t*2+1]);
                        mma16816(c, aL[mi][0],aL[mi][1],aL[mi][2],aL[mi][3], bH[t*2],bH[t*2+1]);
                    }
                }
            }
        }
        __syncthreads();
    }
    #undef PROJ_PREFETCH

    if (wsel < 2) {
        __nv_bfloat16* oh = wsel==0 ? g_qhi : g_khi;
        __nv_bfloat16* ol = wsel==0 ? g_qlo : g_klo;
        #pragma unroll
        for (int mi = 0; mi < 2; mi++) {
            int tr0 = t0 + wm*32 + mi*16 + lg;
            #pragma unroll
            for (int nj = 0; nj < 8; nj++) {
                int o = o0 + wn*64 + nj*8 + tg*2;
                float bi0 = bias[o], bi1 = bias[o+1];
                int hh = o >> 6, d = o & 63;
                size_t base = ((size_t)(b*H_+hh)*T_ + tr0)*D_ + d;
                __nv_bfloat16 h0,l0,h1,l1;
                cv(acc[mi][nj][0]+bi0, h0,l0); cv(acc[mi][nj][1]+bi1, h1,l1);
                *(unsigned*)&oh[base] = pk2(h0,h1);
                *(unsigned*)&ol[base] = pk2(l0,l1);
                cv(acc[mi][nj][2]+bi0, h0,l0); cv(acc[mi][nj][3]+bi1, h1,l1);
                *(unsigned*)&oh[base + 8*D_] = pk2(h0,h1);
                *(unsigned*)&ol[base + 8*D_] = pk2(l0,l1);
            }
        }
    } else {
        #pragma unroll
        for (int mi = 0; mi < 2; mi++) {
            int tr0 = t0 + wm*32 + mi*16 + lg;
            #pragma unroll
            for (int nj = 0; nj < 8; nj++) {
                int o = o0 + wn*64 + nj*8 + tg*2;
                float bi0 = bias[o], bi1 = bias[o+1];
                int hh = o >> 6, d = o & 63;
                size_t base = ((size_t)(b*H_+hh)*D_ + d)*T_ + tr0;
                __nv_bfloat16 h0,l0;
                cv(acc[mi][nj][0]+bi0, h0,l0); g_vhi[base] = h0;      g_vlo[base] = l0;
                cv(acc[mi][nj][1]+bi1, h0,l0); g_vhi[base+T_] = h0;   g_vlo[base+T_] = l0;
                cv(acc[mi][nj][2]+bi0, h0,l0); g_vhi[base+8] = h0;    g_vlo[base+8] = l0;
                cv(acc[mi][nj][3]+bi1, h0,l0); g_vhi[base+T_+8] = h0; g_vlo[base+T_+8] = l0;
            }
        }
    }
#endif
}

// =====================================================================
// Output projection tensor GEMM (mma.sync, double-buffered — unchanged)
// =====================================================================
__global__ __launch_bounds__(256, 2) void outp_gemm(
    const float* __restrict__ bo, const float* __restrict__ mask,
    float* __restrict__ out)
{
    __shared__ __align__(16) __nv_bfloat16 sA[2][2][128*40];
    __shared__ __align__(16) __nv_bfloat16 sB[2][2][128*40];

    const int tid = threadIdx.x, lane = tid & 31, w = tid >> 5;
    const int wm = w & 3, wn = w >> 2;
    const int lg = lane >> 2, tg = lane & 3;
    const int l7 = lane & 7, lh = (lane >> 3) & 1, lq = lane >> 4;

    const int o0 = blockIdx.x * 128;
    const int n0g = blockIdx.y * 128;
    const int b = n0g >> 10, t0 = n0g & 1023;

    const __nv_bfloat16* Ah = g_whi + (size_t)3*C_*C_;
    const __nv_bfloat16* Al = g_wlo + (size_t)3*C_*C_;

    float acc[2][8][4] = {};

    const unsigned STG = 2*128*40*2;
    const unsigned aHB = su32(sA[0][0]) + (wm*32 + lh*8 + l7)*80 + lq*16;
    const unsigned aLB = su32(sA[0][1]) + (wm*32 + lh*8 + l7)*80 + lq*16;
    const unsigned bHB = su32(sB[0][0]) + (wn*64 + lq*8 + l7)*80 + lh*16;
    const unsigned bLB = su32(sB[0][1]) + (wn*64 + lq*8 + l7)*80 + lh*16;

    #define OUTP_PREFETCH(k0, st) do { \
        _Pragma("unroll") \
        for (int r = 0; r < 4; r++) { \
            int s = tid + r*256; \
            int buf = s >> 9, rc = s & 511; \
            int row = rc >> 2, c = rc & 3; \
            unsigned off = row*80 + c*16; \
            const __nv_bfloat16* asrc = (buf ? Al : Ah) + (size_t)(o0+row)*C_ + (k0) + c*8; \
            const __nv_bfloat16* bsrc = (buf ? g_ytlo : g_ythi) + (size_t)(n0g+row)*C_ + (k0) + c*8; \
            cpasync16(su32(sA[st][buf]) + off, asrc); \
            cpasync16(su32(sB[st][buf]) + off, bsrc); \
        } \
        cp_commit(); \
    } while (0)

    OUTP_PREFETCH(0, 0);

    #pragma unroll 1
    for (int it = 0; it < 16; it++) {
        const int cur = it & 1;
        if (it + 1 < 16) {
            OUTP_PREFETCH((it+1)*32, cur^1);
            cp_wait1();
        } else {
            cp_wait0();
        }
        __syncthreads();

        const unsigned so = cur * STG;
        #pragma unroll
        for (int ks = 0; ks < 2; ks++) {
            const unsigned ko = ks*32;
            unsigned aH[2][4], aL[2][4];
            #pragma unroll
            for (int mi = 0; mi < 2; mi++) {
                ldsm4(aH[mi][0],aH[mi][1],aH[mi][2],aH[mi][3], aHB + so + mi*16*80 + ko);
                ldsm4(aL[mi][0],aL[mi][1],aL[mi][2],aL[mi][3], aLB + so + mi*16*80 + ko);
            }
            #pragma unroll
            for (int nb = 0; nb < 4; nb++) {
                unsigned bH[4], bL[4];
                ldsm4(bH[0],bH[1],bH[2],bH[3], bHB + so + nb*16*80 + ko);
                ldsm4(bL[0],bL[1],bL[2],bL[3], bLB + so + nb*16*80 + ko);
                #pragma unroll
                for (int mi = 0; mi < 2; mi++) {
                    #pragma unroll
                    for (int t = 0; t < 2; t++) {
                        float* c = acc[mi][nb*2+t];
                        mma16816(c, aH[mi][0],aH[mi][1],aH[mi][2],aH[mi][3], bH[t*2],bH[t*2+1]);
                        mma16816(c, aH[mi][0],aH[mi][1],aH[mi][2],aH[mi][3], bL[t*2],bL[t*2+1]);
                        mma16816(c, aL[mi][0],aL[mi][1],aL[mi][2],aL[mi][3], bH[t*2],bH[t*2+1]);
                    }
                }
            }
        }
        __syncthreads();
    }
    #undef OUTP_PREFETCH

    #pragma unroll
    for (int mi = 0; mi < 2; mi++) {
        int o = o0 + wm*32 + mi*16 + lg;
        float bi0 = bo[o], bi1 = bo[o+8];
        #pragma unroll
        for (int nj = 0; nj < 8; nj++) {
            int t = t0 + wn*64 + nj*8 + tg*2;
            float m0v = mask[(size_t)b*T_ + t];
            float m1v = mask[(size_t)b*T_ + t + 1];
            float2 v0 = make_float2((acc[mi][nj][0]+bi0)*m0v, (acc[mi][nj][1]+bi0)*m1v);
            float2 v1 = make_float2((acc[mi][nj][2]+bi1)*m0v, (acc[mi][nj][3]+bi1)*m1v);
            *(float2*)&out[((size_t)b*C_ + o)*T_ + t]     = v0;
            *(float2*)&out[((size_t)b*C_ + o + 8)*T_ + t] = v1;
        }
    }
}

// =====================================================================
// Fused attention — round-11 (K prefetch behind PV) unchanged
// =====================================================================
__global__ __launch_bounds__(512, 1) void attn_kernel(const float* __restrict__ mask)
{
    extern __shared__ unsigned char smem[];
    __nv_bfloat16* qhi = (__nv_bfloat16*)(smem + OFF_QHI);
    __nv_bfloat16* qlo = (__nv_bfloat16*)(smem + OFF_QLO);
    __nv_bfloat16* khi = (__nv_bfloat16*)(smem + OFF_K);
    __nv_bfloat16* klo = (__nv_bfloat16*)(smem + OFF_K + 18432);
    __nv_bfloat16* vhi = (__nv_bfloat16*)(smem + OFF_V);
    __nv_bfloat16* vlo = (__nv_bfloat16*)(smem + OFF_V + 17408);
    __nv_bfloat16* phi = (__nv_bfloat16*)(smem + OFF_P);
    __nv_bfloat16* plo = (__nv_bfloat16*)(smem + OFF_P + 17408);
    __nv_bfloat16* binhi = (__nv_bfloat16*)(smem + OFF_BINHI);
    __nv_bfloat16* binlo = (__nv_bfloat16*)(smem + OFF_BINLO);
    float* sbin = (float*)(smem + OFF_SBIN);
    float* sqr  = (float*)(smem + OFF_SQR);
    float* smk  = (float*)(smem + OFF_SMK);
    float* sstp = (float*)(smem + OFF_SSTP);
    float* sst  = (float*)(smem + OFF_SST);

    const int tid  = threadIdx.x;
    const int lane = tid & 31;
    const int w    = tid >> 5;
    const int wm   = w & 3;
    const int wg   = w >> 2;
    const int lg   = lane >> 2;
    const int tg   = lane & 3;
    const int r0   = wm*16 + lg;
    const int r1   = r0 + 8;
    const int l7   = lane & 7;
    const int lh   = (lane >> 3) & 1;
    const int lq   = lane >> 4;

    const int i0 = blockIdx.x * 64;
    const int h  = blockIdx.y;
    const int b  = blockIdx.z;
    const size_t headbase = (size_t)(b*H_+h)*T_*D_;

    #define STAGE_K(j0k) do { \
        _Pragma("unroll") \
        for (int r = 0; r < 4; r++) { \
            int e = tid + r*512; \
            int bufi = e >> 10; \
            int rc = e & 1023; \
            int j = rc >> 3, c = rc & 7; \
            unsigned dst = su32(bufi ? klo : khi) + j*144 + c*16; \
            const unsigned char* src = \
                (const unsigned char*)(bufi ? g_klo : g_khi) \
                + (headbase + (size_t)((j0k)+j)*D_)*2 + c*16; \
            cpasync16(dst, src); \
        } \
        cp_commit(); \
    } while (0)

    #define STAGE_V(j0v) do { \
        _Pragma("unroll") \
        for (int r = 0; r < 4; r++) { \
            int e = tid + r*512; \
            int bufi = e >> 10; \
            int rc = e & 1023; \
            int d = rc >> 4, c = rc & 15; \
            unsigned dst = su32(bufi ? vlo : vhi) + d*272 + c*16; \
            const unsigned char* src = \
                (const unsigned char*)(bufi ? g_vlo : g_vhi) \
                + (headbase + (size_t)d*T_ + (j0v))*2 + c*16; \
            cpasync16(dst, src); \
        } \
        cp_commit(); \
    } while (0)

    // ---- Phase A ----
    #pragma unroll
    for (int r = 0; r < 2; r++) {
        int e = tid + r*512;
        int bufi = e >> 9;
        int rc = e & 511;
        int m = rc >> 3, c = rc & 7;
        unsigned dst = su32(bufi ? qlo : qhi) + m*144 + c*16;
        const unsigned char* src =
            (const unsigned char*)(bufi ? g_qlo : g_qhi)
            + (headbase + (size_t)(i0+m)*D_)*2 + c*16;
        cpasync16(dst, src);
    }
    for (int e = tid; e < REL_*8; e += 512) {
        int r = e >> 3, c = e & 7;
        cpasync16(su32(smem + OFF_EKHI) + r*144 + c*16,
                  (const unsigned char*)g_ekhi + (size_t)(r*64 + c*8)*2);
    }
    for (int e = tid; e < REL_*8; e += 512) {
        int r = e >> 3, c = e & 7;
        cpasync16(su32(smem + OFF_EKLO) + r*144 + c*16,
                  (const unsigned char*)g_eklo + (size_t)(r*64 + c*8)*2);
    }
    cp_commit();
    for (int e = tid; e < T_/4; e += 512)
        ((float4*)smk)[e] = ((const float4*)(mask + (size_t)b*T_))[e];
    for (int e = tid; e < 64*132; e += 512)
        sbin[e] = 0.f;
    cp_wait0();
    __syncthreads();

    const unsigned qhiA = su32(qhi) + (unsigned)((wm*16 + lh*8 + l7)*144 + lq*16);
    const unsigned qloA = su32(qlo) + (unsigned)((wm*16 + lh*8 + l7)*144 + lq*16);

    // ---- Phase B: qrel via MMA ----
    {
        const unsigned ekhiB = su32(smem + OFF_EKHI) + (lq*8 + l7)*144 + lh*16;
        const unsigned ekloB = su32(smem + OFF_EKLO) + (lq*8 + l7)*144 + lh*16;
        float qa[3][2][4] = {};
        const int ng = (wg == 0) ? 3 : 2;
        const int glist[3] = {wg, wg+4, 8};

        #pragma unroll
        for (int ks = 0; ks < 4; ks++) {
            const unsigned ko = ks*32;
            unsigned aH0,aH1,aH2,aH3, aL0,aL1,aL2,aL3;
            ldsm4(aH0,aH1,aH2,aH3, qhiA + ko);
            ldsm4(aL0,aL1,aL2,aL3, qloA + ko);
            for (int gi = 0; gi < ng; gi++) {
                const unsigned ro = glist[gi]*16*144;
                unsigned bH[4], bL[4];
                ldsm4(bH[0],bH[1],bH[2],bH[3], ekhiB + ro + ko);
                ldsm4(bL[0],bL[1],bL[2],bL[3], ekloB + ro + ko);
                #pragma unroll
                for (int t = 0; t < 2; t++) {
                    float* c = qa[gi][t];
                    mma16816(c, aH0,aH1,aH2,aH3, bH[t*2],bH[t*2+1]);
                    mma16816(c, aH0,aH1,aH2,aH3, bL[t*2],bL[t*2+1]);
                    mma16816(c, aL0,aL1,aL2,aL3, bH[t*2],bH[t*2+1]);
                }
            }
        }
        for (int gi = 0; gi < ng; gi++) {
            #pragma unroll
            for (int t = 0; t < 2; t++) {
                int col = glist[gi]*16 + t*8 + tg*2;
                if (col < 136) {
                    *(float2*)&sqr[r0*136 + col] = make_float2(qa[gi][t][0], qa[gi][t][1]);
                    *(float2*)&sqr[r1*136 + col] = make_float2(qa[gi][t][2], qa[gi][t][3]);
                }
            }
        }
    }
    __syncthreads();

    STAGE_K(0);

    const float qrM0 = sqr[r0*136];       const float qrP0 = sqr[r0*136 + 128];
    const float qrM1 = sqr[r1*136];       const float qrP1 = sqr[r1*136 + 128];

    const float scale = 0.125f;
    float yacc[2][4] = {};
    float ls0=0.f, ls1=0.f, ea0=0.f, ea1=0.f, eb0=0.f, eb1=0.f;

    const unsigned khiB0 = su32(khi) + (unsigned)((wg*32 + lq*8 + l7)*144 + lh*16);
    const unsigned kloB0 = su32(klo) + (unsigned)((wg*32 + lq*8 + l7)*144 + lh*16);
    const unsigned phiA = su32(phi) + (unsigned)((wm*16 + lh*8 + l7)*272 + lq*16);
    const unsigned ploA = su32(plo) + (unsigned)((wm*16 + lh*8 + l7)*272 + lq*16);
    const unsigned vhiB = su32(vhi) + (unsigned)((wg*8 + lq*32 + l7)*272 + lh*16);
    const unsigned vloB = su32(vlo) + (unsigned)((wg*8 + lq*32 + l7)*272 + lh*16);

    for (int kt = 0; kt < 8; kt++) {
        const int j0g = kt * 128;
        const int relbase = j0g - i0;
        const bool fastHi = (relbase >= 127);
        const bool fastLo = (relbase <= -191);

        __syncthreads();
        STAGE_V(j0g);
        cp_wait1();
        __syncthreads();

        float sacc[4][4] = {};
        #pragma unroll
        for (int ks = 0; ks < 4; ks++) {
            const unsigned ko = ks*32;
            unsigned aH0,aH1,aH2,aH3, aL0,aL1,aL2,aL3;
            ldsm4(aH0,aH1,aH2,aH3, qhiA + ko);
            ldsm4(aL0,aL1,aL2,aL3, qloA + ko);
            unsigned bH[8], bL[8];
            ldsm4(bH[0],bH[1],bH[2],bH[3], khiB0 + ko);
            ldsm4(bH[4],bH[5],bH[6],bH[7], khiB0 + 16*144 + ko);
            ldsm4(bL[0],bL[1],bL[2],bL[3], kloB0 + ko);
            ldsm4(bL[4],bL[5],bL[6],bL[7], kloB0 + 16*144 + ko);
            #pragma unroll
            for (int t = 0; t < 4; t++) {
                unsigned b0h = bH[t*2], b1h = bH[t*2+1];
                unsigned b0l = bL[t*2], b1l = bL[t*2+1];
                mma16816(sacc[t], aH0,aH1,aH2,aH3, b0h,b1h);
                mma16816(sacc[t], aH0,aH1,aH2,aH3, b0l,b1l);
                mma16816(sacc[t], aL0,aL1,aL2,aL3, b0h,b1h);
            }
        }

        if (fastHi || fastLo) {
            const float c0 = fastHi ? qrP0 : qrM0;
            const float c1 = fastHi ? qrP1 : qrM1;
            float acc0 = 0.f, acc1 = 0.f;
            #pragma unroll
            for (int t = 0; t < 4; t++) {
                const int cb = wg*32 + t*8 + tg*2;
                #pragma unroll
                for (int ii = 0; ii < 2; ii++) {
                    const int rr = ii ? r1 : r0;
                    const float cc = ii ? c1 : c0;
                    float ev[2];
                    #pragma unroll
                    for (int jj = 0; jj < 2; jj++) {
                        int gj = j0g + cb + jj;
                        float s = sacc[t][ii*2+jj]*scale + cc;
                        if (smk[gj] <= 0.f) s = -1e9f;
                        float e = __expf(s);
                        if (ii == 0) acc0 += e; else acc1 += e;
                        ev[jj] = e;
                    }
                    __nv_bfloat16 eh0,el0,eh1,el1;
                    cv(ev[0],eh0,el0); cv(ev[1],eh1,el1);
                    *(unsigned*)&phi[rr*136 + cb] = pk2(eh0,eh1);
                    *(unsigned*)&plo[rr*136 + cb] = pk2(el0,el1);
                }
            }
            ls0 += acc0; ls1 += acc1;
            if (fastHi) { eb0 += acc0; eb1 += acc1; }
            else        { ea0 += acc0; ea1 += acc1; }
        } else {
            #pragma unroll
            for (int t = 0; t < 4; t++) {
                const int cb = wg*32 + t*8 + tg*2;
                #pragma unroll
                for (int ii = 0; ii < 2; ii++) {
                    const int rr = ii ? r1 : r0;
                    const int gi = i0 + rr;
                    float ev[2];
                    #pragma unroll
                    for (int jj = 0; jj < 2; jj++) {
                        int gj = j0g + cb + jj;
                        int rel = gj - gi;
                        int relc = rel < -64 ? -64 : (rel > 64 ? 64 : rel);
                        float s = sacc[t][ii*2+jj]*scale + sqr[rr*136 + relc + 64];
                        if (smk[gj] <= 0.f) s = -1e9f;
                        float e = __expf(s);
                        if (ii == 0) ls0 += e; else ls1 += e;
                        if (rel <= -64)      { if (ii == 0) ea0 += e; else ea1 += e; }
                        else if (rel >= 64)  { if (ii == 0) eb0 += e; else eb1 += e; }
                        else                 sbin[rr*132 + rel + 64] = e;
                        ev[jj] = e;
                    }
                    __nv_bfloat16 eh0,el0,eh1,el1;
                    cv(ev[0],eh0,el0); cv(ev[1],eh1,el1);
                    *(unsigned*)&phi[rr*136 + cb] = pk2(eh0,eh1);
                    *(unsigned*)&plo[rr*136 + cb] = pk2(el0,el1);
                }
            }
        }
        __syncthreads();

        if (kt < 7) {
            STAGE_K(j0g + 128);
            cp_wait1();
        } else {
            cp_wait0();
        }
        __syncthreads();

        #pragma unroll
        for (int ks = 0; ks < 8; ks++) {
            const unsigned ko = ks*32;
            unsigned aH0,aH1,aH2,aH3, aL0,aL1,aL2,aL3;
            ldsm4(aH0,aH1,aH2,aH3, phiA + ko);
            ldsm4(aL0,aL1,aL2,aL3, ploA + ko);
            unsigned bH[4], bL[4];
            ldsm4(bH[0],bH[1],bH[2],bH[3], vhiB + ko);
            ldsm4(bL[0],bL[1],bL[2],bL[3], vloB + ko);
            #pragma unroll
            for (int ti = 0; ti < 2; ti++) {
                unsigned b0h = bH[ti*2], b1h = bH[ti*2+1];
                unsigned b0l = bL[ti*2], b1l = bL[ti*2+1];
                mma16816(yacc[ti], aH0,aH1,aH2,aH3, b0h,b1h);
                mma16816(yacc[ti], aH0,aH1,aH2,aH3, b0l,b1l);
                mma16816(yacc[ti], aL0,aL1,aL2,aL3, b0h,b1h);
            }
        }
    }
    #undef STAGE_K
    #undef STAGE_V
    __syncthreads();

    for (int e = tid; e < 64*18; e += 512) {
        int d = e/18, c = e - d*18;
        cpasync16(su32(smem + OFF_EVHI) + d*304 + c*16,
                  (const unsigned char*)g_evhi + (size_t)(d*144 + c*8)*2);
    }
    for (int e = tid; e < 64*18; e += 512) {
        int d = e/18, c = e - d*18;
        cpasync16(su32(smem + OFF_EVLO) + d*304 + c*16,
                  (const unsigned char*)g_evlo + (size_t)(d*144 + c*8)*2);
    }
    cp_commit();

    {
        float v;
        #define RED_(x) v = x; v += __shfl_xor_sync(~0u, v, 1); v += __shfl_xor_sync(~0u, v, 2); x = v;
        RED_(ls0) RED_(ls1) RED_(ea0) RED_(ea1) RED_(eb0) RED_(eb1)
        #undef RED_
        if (tg == 0) {
            sstp[0*256 + wg*64 + r0] = ls0;  sstp[0*256 + wg*64 + r1] = ls1;
            sstp[1*256 + wg*64 + r0] = ea0;  sstp[1*256 + wg*64 + r1] = ea1;
            sstp[2*256 + wg*64 + r0] = eb0;  sstp[2*256 + wg*64 + r1] = eb1;
        }
    }
    __syncthreads();
    if (tid < 64) {
        float l = 0.f, a = 0.f, c = 0.f;
        #pragma unroll
        for (int g = 0; g < 4; g++) {
            l += sstp[0*256 + g*64 + tid];
            a += sstp[1*256 + g*64 + tid];
            c += sstp[2*256 + g*64 + tid];
        }
        sst[tid] = l;
        sbin[tid*132]       = a;
        sbin[tid*132 + 128] = c;
    }
    __syncthreads();

    for (int e = tid; e < 64*144; e += 512) {
        int m = e/144, c = e - m*144;
        float v = (c < REL_) ? sbin[m*132 + c] : 0.f;
        __nv_bfloat16 hh, ll;
        cv(v, hh, ll);
        binhi[m*152 + c] = hh;
        binlo[m*152 + c] = ll;
    }
    cp_wait0();
    __syncthreads();

    {
        const unsigned binA  = su32(smem + OFF_BINHI) + (wm*16 + lh*8 + l7)*304 + lq*16;
        const unsigned binAl = su32(smem + OFF_BINLO) + (wm*16 + lh*8 + l7)*304 + lq*16;
        const unsigned evB   = su32(smem + OFF_EVHI)  + (wg*8 + lq*32 + l7)*304 + lh*16;
        const unsigned evBl  = su32(smem + OFF_EVLO)  + (wg*8 + lq*32 + l7)*304 + lh*16;
        #pragma unroll
        for (int ks = 0; ks < 9; ks++) {
            const unsigned ko = ks*32;
            unsigned aH0,aH1,aH2,aH3, aL0,aL1,aL2,aL3;
            ldsm4(aH0,aH1,aH2,aH3, binA + ko);
            ldsm4(aL0,aL1,aL2,aL3, binAl + ko);
            unsigned bH[4], bL[4];
            ldsm4(bH[0],bH[1],bH[2],bH[3], evB + ko);
            ldsm4(bL[0],bL[1],bL[2],bL[3], evBl + ko);
            #pragma unroll
            for (int ti = 0; ti < 2; ti++) {
                unsigned b0h = bH[ti*2], b1h = bH[ti*2+1];
                unsigned b0l = bL[ti*2], b1l = bL[ti*2+1];
                mma16816(yacc[ti], aH0,aH1,aH2,aH3, b0h,b1h);
                mma16816(yacc[ti], aH0,aH1,aH2,aH3, b0l,b1l);
                mma16816(yacc[ti], aL0,aL1,aL2,aL3, b0h,b1h);
            }
        }
    }

    {
        const float inv0 = 1.f / sst[r0];
        const float inv1 = 1.f / sst[r1];
        const int dA = wg*8 + tg*2;
        const int dB = dA + 32;
        const int cbase = h*64;
        size_t tb0 = ((size_t)b*T_ + i0 + r0)*C_;
        size_t tb1 = ((size_t)b*T_ + i0 + r1)*C_;
        __nv_bfloat16 h0,l0,h1,l1;
        cv(yacc[0][0]*inv0,h0,l0); cv(yacc[0][1]*inv0,h1,l1);
        *(unsigned*)&g_ythi[tb0 + cbase + dA] = pk2(h0,h1);
        *(unsigned*)&g_ytlo[tb0 + cbase + dA] = pk2(l0,l1);
        cv(yacc[0][2]*inv1,h0,l0); cv(yacc[0][3]*inv1,h1,l1);
        *(unsigned*)&g_ythi[tb1 + cbase + dA] = pk2(h0,h1);
        *(unsigned*)&g_ytlo[tb1 + cbase + dA] = pk2(l0,l1);
        cv(yacc[1][0]*inv0,h0,l0); cv(yacc[1][1]*inv0,h1,l1);
        *(unsigned*)&g_ythi[tb0 + cbase + dB] = pk2(h0,h1);
        *(unsigned*)&g_ytlo[tb0 + cbase + dB] = pk2(l0,l1);
        cv(yacc[1][2]*inv1,h0,l0); cv(yacc[1][3]*inv1,h1,l1);
        *(unsigned*)&g_ythi[tb1 + cbase + dB] = pk2(h0,h1);
        *(unsigned*)&g_ytlo[tb1 + cbase + dB] = pk2(l0,l1);
    }
}

// =====================================================================
extern "C" void kernel_launch(void* const* d_in, const int* in_sizes, int n_in,
                              void* d_out, int out_size)
{
    const float* x     = (const float*)d_in[0];
    const float* xmask = (const float*)d_in[1];
    const float* Wq    = (const float*)d_in[2];
    const float* bq    = (const float*)d_in[3];
    const float* Wk    = (const float*)d_in[4];
    const float* bk    = (const float*)d_in[5];
    const float* Wv    = (const float*)d_in[6];
    const float* bv    = (const float*)d_in[7];
    const float* Wo    = (const float*)d_in[8];
    const float* bo    = (const float*)d_in[9];
    const float* erelk = (const float*)d_in[10];
    const float* erelv = (const float*)d_in[11];
    float* out = (float*)d_out;

    cudaFuncSetAttribute(attn_kernel,
                         cudaFuncAttributeMaxDynamicSharedMemorySize, SMEM_BYTES);
    cudaFuncSetAttribute(proj_any,
                         cudaFuncAttributeMaxDynamicSharedMemorySize, PJ_SMEM);

    conv_x<<<dim3(T_/32, C_/32, B_), 256>>>(x);
    conv_w<<<dim3(C_*C_/256, 4), 256>>>(Wq, Wk, Wv, Wo);
    conv_erel<<<36, 256>>>(erelk, erelv);

    proj_any<<<dim3(64, 12), 256, PJ_SMEM>>>(bq, bk, bv);

    attn_kernel<<<dim3(16, H_, B_), 512, SMEM_BYTES>>>(xmask);

    outp_gemm<<<dim3(4, 64), 256>>>(bo, xmask, out);
}